// round 8
// baseline (speedup 1.0000x reference)
#include <cuda_runtime.h>
#include <cuda_bf16.h>
#include <cstdint>

#define B_ 4
#define T_ 2048
#define C_ 1024
#define H_ 16
#define D_ 64
#define C3_ (3 * C_)
#define M_ (B_ * T_)   // 8192
#define NQB (T_ / 128) // 16 q-blocks per (b,h)

// ---------------- scratch (device globals; no runtime alloc) ----------------
__device__ __nv_bfloat16 g_xhi[(size_t)M_ * C_],  g_xlo[(size_t)M_ * C_];
__device__ __nv_bfloat16 g_wqhi[(size_t)C3_ * C_], g_wqlo[(size_t)C3_ * C_];
__device__ __nv_bfloat16 g_wohi[(size_t)C_ * C_],  g_wolo[(size_t)C_ * C_];
// Q,K,V in [B,H,T,D] hi/lo bf16 (written by GEMM1 epilogue)
__device__ __nv_bfloat16 g_qh[(size_t)M_ * C_], g_ql[(size_t)M_ * C_];
__device__ __nv_bfloat16 g_kh[(size_t)M_ * C_], g_kl[(size_t)M_ * C_];
__device__ __nv_bfloat16 g_vh[(size_t)M_ * C_], g_vl[(size_t)M_ * C_];
// attention output hi/lo [M, C] (row = token, col = h*64+d)
__device__ __nv_bfloat16 g_oh[(size_t)M_ * C_], g_ol[(size_t)M_ * C_];

// ---------------------------- helpers ---------------------------------------
__device__ __forceinline__ uint32_t smem_u32(const void* p) {
    uint32_t a;
    asm("{ .reg .u64 t; cvta.to.shared.u64 t, %1; cvt.u32.u64 %0, t; }"
        : "=r"(a) : "l"(p));
    return a;
}
__device__ __forceinline__ void cp16(uint32_t dst, const void* src) {
    asm volatile("cp.async.cg.shared.global [%0], [%1], 16;" :: "r"(dst), "l"(src));
}
__device__ __forceinline__ void cp_commit() {
    asm volatile("cp.async.commit_group;" ::: "memory");
}
__device__ __forceinline__ void cp_wait0() {
    asm volatile("cp.async.wait_group 0;" ::: "memory");
}
__device__ __forceinline__ void cp_wait1() {
    asm volatile("cp.async.wait_group 1;" ::: "memory");
}
__device__ __forceinline__ void ldsm4(uint32_t* r, uint32_t addr) {
    asm volatile("ldmatrix.sync.aligned.m8n8.x4.shared.b16 {%0,%1,%2,%3}, [%4];"
                 : "=r"(r[0]), "=r"(r[1]), "=r"(r[2]), "=r"(r[3]) : "r"(addr));
}
__device__ __forceinline__ void ldsm4t(uint32_t* r, uint32_t addr) {
    asm volatile("ldmatrix.sync.aligned.m8n8.x4.trans.shared.b16 {%0,%1,%2,%3}, [%4];"
                 : "=r"(r[0]), "=r"(r[1]), "=r"(r[2]), "=r"(r[3]) : "r"(addr));
}
__device__ __forceinline__ void mma_bf16(float* c, const uint32_t* a, const uint32_t* b) {
    asm volatile(
        "mma.sync.aligned.m16n8k16.row.col.f32.bf16.bf16.f32 "
        "{%0,%1,%2,%3}, {%4,%5,%6,%7}, {%8,%9}, {%0,%1,%2,%3};"
        : "+f"(c[0]), "+f"(c[1]), "+f"(c[2]), "+f"(c[3])
        : "r"(a[0]), "r"(a[1]), "r"(a[2]), "r"(a[3]), "r"(b[0]), "r"(b[1]));
}
__device__ __forceinline__ void split2(float a, float b, uint32_t& hi, uint32_t& lo) {
    __nv_bfloat162 h = __floats2bfloat162_rn(a, b);
    float2 f = __bfloat1622float2(h);
    __nv_bfloat162 l = __floats2bfloat162_rn(a - f.x, b - f.y);
    hi = *reinterpret_cast<uint32_t*>(&h);
    lo = *reinterpret_cast<uint32_t*>(&l);
}

// ---------------------------------------------------------------------------
// fp32 -> (hi, lo) bf16 split, vectorized x4
// ---------------------------------------------------------------------------
__global__ void cvt_hilo(const float4* __restrict__ x, uint2* __restrict__ hi,
                         uint2* __restrict__ lo, int n4) {
    int i = blockIdx.x * blockDim.x + threadIdx.x;
    if (i >= n4) return;
    float4 v = x[i];
    uint32_t h0, l0, h1, l1;
    split2(v.x, v.y, h0, l0);
    split2(v.z, v.w, h1, l1);
    hi[i] = make_uint2(h0, h1);
    lo[i] = make_uint2(l0, l1);
}

// ---------------------------------------------------------------------------
// bf16 hi/lo tensor-core GEMM via mma.sync.
// 128x128 CTA tile, 4 warps (64x64 warp tile), 2 CTAs/SM, BK=32.
// MODE 0: out = fp32 + bias. MODE 1: QKV -> hi/lo bf16 [B,H,T,D].
// ---------------------------------------------------------------------------
#define GSTRIDE 40
#define MAT_BYTES (128 * GSTRIDE * 2)
#define STAGE_BYTES (4 * MAT_BYTES)
#define GK_SMEM (2 * STAGE_BYTES)

template <int MODE>
__global__ __launch_bounds__(128, 2) void gemm_mma(
    const __nv_bfloat16* __restrict__ Ahi, const __nv_bfloat16* __restrict__ Alo,
    const __nv_bfloat16* __restrict__ Bhi, const __nv_bfloat16* __restrict__ Blo,
    const float* __restrict__ bias, float* __restrict__ out,
    int M, int N, int K)
{
    extern __shared__ __align__(128) char dsm[];
    const uint32_t smb = smem_u32(dsm);

    const int tid  = threadIdx.x;
    const int wid  = tid >> 5;
    const int lane = tid & 31;
    const int wm = wid >> 1;      // 0..1 -> m offset wm*64
    const int wn = wid & 1;       // 0..1 -> n offset wn*64

    const size_t m0 = (size_t)blockIdx.y * 128;
    const size_t n0 = (size_t)blockIdx.x * 128;

    const __nv_bfloat16* srcs[4] = {Ahi + m0 * K, Alo + m0 * K,
                                    Bhi + n0 * K, Blo + n0 * K};

    float acc[4][8][4];
#pragma unroll
    for (int i = 0; i < 4; i++)
#pragma unroll
        for (int j = 0; j < 8; j++)
#pragma unroll
            for (int k = 0; k < 4; k++) acc[i][j][k] = 0.f;

    // 4 matrices x 512 16B chunks / 128 threads = 16 cp.async per thread
    auto load_stage = [&](int kt, int s) {
        const int k0 = kt * 32;
        const uint32_t sb = smb + s * STAGE_BYTES;
#pragma unroll
        for (int m = 0; m < 4; m++) {
            const __nv_bfloat16* src = srcs[m];
#pragma unroll
            for (int i = 0; i < 4; i++) {
                int idx = tid + i * 128;          // 0..511
                int row = idx >> 2;               // 0..127
                int q   = idx & 3;                // 16B chunk in 64B row
                cp16(sb + m * MAT_BYTES + (row * GSTRIDE + q * 8) * 2,
                     src + (size_t)row * K + k0 + q * 8);
            }
        }
        cp_commit();
    };

    const uint32_t a_row = (uint32_t)(wm * 64 + (lane & 15));
    const uint32_t a_kof = (uint32_t)(((lane >> 4) & 1) * 8);
    const uint32_t b_row = (uint32_t)(wn * 64 + (lane & 7) + ((lane >> 4) & 1) * 8);
    const uint32_t b_kof = (uint32_t)(((lane >> 3) & 1) * 8);

    const int NT = K >> 5;
    load_stage(0, 0);

    for (int kt = 0; kt < NT; kt++) {
        cp_wait0();
        __syncthreads();
        if (kt + 1 < NT) load_stage(kt + 1, (kt + 1) & 1);

        const uint32_t sb = smb + (kt & 1) * STAGE_BYTES;
        const uint32_t sAhi = sb;
        const uint32_t sAlo = sb + MAT_BYTES;
        const uint32_t sBhi = sb + 2 * MAT_BYTES;
        const uint32_t sBlo = sb + 3 * MAT_BYTES;

#pragma unroll
        for (int ks = 0; ks < 2; ks++) {
            // B fragments for this k16-step: 4 nf2 blocks of n16 (32 regs)
            uint32_t bh[4][4], bl[4][4];
#pragma unroll
            for (int nf2 = 0; nf2 < 4; nf2++) {
                uint32_t off = ((b_row + nf2 * 16) * GSTRIDE + ks * 16 + b_kof) * 2;
                ldsm4(bh[nf2], sBhi + off);
                ldsm4(bl[nf2], sBlo + off);
            }
            // A fragments: double-buffered, prefetch mf+1 during mf's MMAs
            uint32_t ah[2][4], al[2][4];
            {
                uint32_t off0 = (a_row * GSTRIDE + ks * 16 + a_kof) * 2;
                ldsm4(ah[0], sAhi + off0);
                ldsm4(al[0], sAlo + off0);
            }
#pragma unroll
            for (int mf = 0; mf < 4; mf++) {
                const int cur = mf & 1, nxt = cur ^ 1;
                if (mf < 3) {
                    uint32_t offn = ((a_row + (mf + 1) * 16) * GSTRIDE + ks * 16 + a_kof) * 2;
                    ldsm4(ah[nxt], sAhi + offn);
                    ldsm4(al[nxt], sAlo + offn);
                }
#pragma unroll
                for (int nf = 0; nf < 8; nf++) {
                    const uint32_t* Bh = &bh[nf >> 1][(nf & 1) * 2];
                    const uint32_t* Bl = &bl[nf >> 1][(nf & 1) * 2];
                    mma_bf16(acc[mf][nf], ah[cur], Bh);
                    mma_bf16(acc[mf][nf], ah[cur], Bl);
                    mma_bf16(acc[mf][nf], al[cur], Bh);
                }
            }
        }
    }

    const int r_in = lane >> 2;
    const int c_in = (lane & 3) * 2;

    if (MODE == 0) {
#pragma unroll
        for (int mf = 0; mf < 4; mf++) {
#pragma unroll
            for (int nf = 0; nf < 8; nf++) {
                size_t row = m0 + wm * 64 + mf * 16 + r_in;
                size_t col = n0 + wn * 64 + nf * 8 + c_in;
                float bx = bias[col], by = bias[col + 1];
                float2 o0 = make_float2(acc[mf][nf][0] + bx, acc[mf][nf][1] + by);
                float2 o1 = make_float2(acc[mf][nf][2] + bx, acc[mf][nf][3] + by);
                *(float2*)(out + row * N + col) = o0;
                *(float2*)(out + (row + 8) * N + col) = o1;
            }
        }
    } else {
        __nv_bfloat16* dh[3] = {g_qh, g_kh, g_vh};
        __nv_bfloat16* dl[3] = {g_ql, g_kl, g_vl};
#pragma unroll
        for (int mf = 0; mf < 4; mf++) {
#pragma unroll
            for (int nf = 0; nf < 8; nf++) {
                size_t col = n0 + wn * 64 + nf * 8 + c_in;
                int sec = (int)(col >> 10);
                int h   = (int)((col >> 6) & 15);
                int d   = (int)(col & 63);
                float bx = bias[col], by = bias[col + 1];
#pragma unroll
                for (int half = 0; half < 2; half++) {
                    size_t row = m0 + wm * 64 + mf * 16 + r_in + half * 8;
                    int b = (int)(row >> 11);
                    int t = (int)(row & 2047);
                    size_t idx = (((size_t)(b * H_ + h) * T_ + t) * D_ + d);
                    float v0 = acc[mf][nf][half * 2 + 0] + bx;
                    float v1 = acc[mf][nf][half * 2 + 1] + by;
                    uint32_t hi, lo;
                    split2(v0, v1, hi, lo);
                    *(uint32_t*)(dh[sec] + idx) = hi;
                    *(uint32_t*)(dl[sec] + idx) = lo;
                }
            }
        }
    }
}

// ---------------------------------------------------------------------------
// Tensor-core causal flash attention (FA2-style), hi/lo bf16 mma.sync.
// Work-balanced q-block pairs (p, NQB-1-p): 17 k-tiles per CTA.
// ---------------------------------------------------------------------------
#define AST 72                         // smem row stride (bf16 elems)
#define QSZ (128 * AST)                // one Q matrix (elems)
#define KVSZ (128 * AST)               // one KV matrix (elems)
#define KVSTAGE (4 * KVSZ)             // Khi,Klo,Vhi,Vlo
#define A_SMEM ((2 * QSZ + 2 * KVSTAGE) * 2)   // bytes = 184320

__global__ __launch_bounds__(256) void attn_tc() {
    extern __shared__ __align__(128) __nv_bfloat16 sm[];
    const uint32_t smb = smem_u32(sm);
    const uint32_t sQhi = smb;
    const uint32_t sQlo = smb + QSZ * 2;
    const uint32_t sKV0 = smb + 2 * QSZ * 2;

    const int pair = blockIdx.x;       // 0..NQB/2-1
    const int h  = blockIdx.y;
    const int b  = blockIdx.z;
    const int tid  = threadIdx.x;
    const int wid  = tid >> 5;
    const int lane = tid & 31;
    const int bh = b * H_ + h;

    const __nv_bfloat16* gkh = g_kh + (size_t)bh * T_ * D_;
    const __nv_bfloat16* gkl = g_kl + (size_t)bh * T_ * D_;
    const __nv_bfloat16* gvh = g_vh + (size_t)bh * T_ * D_;
    const __nv_bfloat16* gvl = g_vl + (size_t)bh * T_ * D_;

    auto load_kv = [&](int kt, int s) {
        const uint32_t sb = sKV0 + s * KVSTAGE * 2;
        const __nv_bfloat16* bases[4] = {
            gkh + (size_t)kt * 128 * D_, gkl + (size_t)kt * 128 * D_,
            gvh + (size_t)kt * 128 * D_, gvl + (size_t)kt * 128 * D_};
#pragma unroll
        for (int i = 0; i < 16; i++) {
            int idx = tid + i * 256;       // 0..4095
            int arr = idx >> 10;           // kh,kl,vh,vl
            int rem = idx & 1023;
            int row = rem >> 3;
            int ch  = rem & 7;
            cp16(sb + (arr * KVSZ + row * AST + ch * 8) * 2,
                 bases[arr] + (size_t)row * D_ + ch * 8);
        }
        cp_commit();
    };

    const uint32_t k_row = (uint32_t)((lane & 7) + ((lane >> 4) & 1) * 8);
    const uint32_t k_kof = ((lane >> 3) & 1) * 8;
    const uint32_t v_rof = (uint32_t)(lane & 15);
    const uint32_t v_cof = ((lane >> 4) & 1) * 8;

    auto process_qblock = [&](int qb) {
        const __nv_bfloat16* gqh = g_qh + ((size_t)bh * T_ + qb * 128) * D_;
        const __nv_bfloat16* gql = g_ql + ((size_t)bh * T_ + qb * 128) * D_;
#pragma unroll
        for (int i = 0; i < 8; i++) {
            int idx = tid + i * 256;
            int arr = idx >> 10;
            int rem = idx & 1023;
            int row = rem >> 3;
            int ch  = rem & 7;
            const __nv_bfloat16* src = (arr ? gql : gqh) + (size_t)row * D_ + ch * 8;
            cp16((arr ? sQlo : sQhi) + (row * AST + ch * 8) * 2, src);
        }
        cp_commit();
        load_kv(0, 0);
        cp_wait0();
        __syncthreads();

        uint32_t qhF[4][4], qlF[4][4];
        {
            uint32_t rbase = (uint32_t)(wid * 16 + (lane & 15));
            uint32_t kof = ((lane >> 4) & 1) * 8;
#pragma unroll
            for (int ks = 0; ks < 4; ks++) {
                uint32_t off = (rbase * AST + ks * 16 + kof) * 2;
                ldsm4(qhF[ks], sQhi + off);
                ldsm4(qlF[ks], sQlo + off);
            }
        }

        float O[8][4];
#pragma unroll
        for (int i = 0; i < 8; i++)
#pragma unroll
            for (int j = 0; j < 4; j++) O[i][j] = 0.f;
        float mrow[2] = {-1e30f, -1e30f};
        float lrow[2] = {0.f, 0.f};

        for (int kt = 0; kt <= qb; kt++) {
            const bool more = (kt + 1 <= qb);
            if (more) load_kv(kt + 1, (kt + 1) & 1);
            if (more) cp_wait1(); else cp_wait0();
            __syncthreads();

            const uint32_t sb = sKV0 + (kt & 1) * KVSTAGE * 2;
            const uint32_t sKh = sb;
            const uint32_t sKl = sb + KVSZ * 2;
            const uint32_t sVh = sb + 2 * KVSZ * 2;
            const uint32_t sVl = sb + 3 * KVSZ * 2;

            float S[16][4];
#pragma unroll
            for (int i = 0; i < 16; i++)
#pragma unroll
                for (int j = 0; j < 4; j++) S[i][j] = 0.f;

#pragma unroll
            for (int ks = 0; ks < 4; ks++) {
#pragma unroll
                for (int i = 0; i < 8; i++) {
                    uint32_t off = ((i * 16 + k_row) * AST + ks * 16 + k_kof) * 2;
                    uint32_t kh4[4], kl4[4];
                    ldsm4(kh4, sKh + off);
                    ldsm4(kl4, sKl + off);
#pragma unroll
                    for (int half = 0; half < 2; half++) {
                        int nf = i * 2 + half;
                        mma_bf16(S[nf], qhF[ks], &kh4[half * 2]);
                        mma_bf16(S[nf], qhF[ks], &kl4[half * 2]);
                        mma_bf16(S[nf], qlF[ks], &kh4[half * 2]);
                    }
                }
            }

#pragma unroll
            for (int i = 0; i < 16; i++)
#pragma unroll
                for (int j = 0; j < 4; j++) S[i][j] *= 0.125f;

            if (kt == qb) {
                const int r0 = wid * 16 + (lane >> 2);
#pragma unroll
                for (int nf = 0; nf < 16; nf++) {
                    int col = nf * 8 + (lane & 3) * 2;
                    if (col > r0)      S[nf][0] = -1e30f;
                    if (col + 1 > r0)  S[nf][1] = -1e30f;
                    if (col > r0 + 8)     S[nf][2] = -1e30f;
                    if (col + 1 > r0 + 8) S[nf][3] = -1e30f;
                }
            }

            float rm0 = -1e30f, rm1 = -1e30f;
#pragma unroll
            for (int nf = 0; nf < 16; nf++) {
                rm0 = fmaxf(rm0, fmaxf(S[nf][0], S[nf][1]));
                rm1 = fmaxf(rm1, fmaxf(S[nf][2], S[nf][3]));
            }
            rm0 = fmaxf(rm0, __shfl_xor_sync(0xffffffffu, rm0, 1));
            rm0 = fmaxf(rm0, __shfl_xor_sync(0xffffffffu, rm0, 2));
            rm1 = fmaxf(rm1, __shfl_xor_sync(0xffffffffu, rm1, 1));
            rm1 = fmaxf(rm1, __shfl_xor_sync(0xffffffffu, rm1, 2));

            float mn0 = fmaxf(mrow[0], rm0);
            float mn1 = fmaxf(mrow[1], rm1);
            float a0 = __expf(mrow[0] - mn0);
            float a1 = __expf(mrow[1] - mn1);
            mrow[0] = mn0; mrow[1] = mn1;

            float rs0 = 0.f, rs1 = 0.f;
#pragma unroll
            for (int nf = 0; nf < 16; nf++) {
                S[nf][0] = __expf(S[nf][0] - mn0);
                S[nf][1] = __expf(S[nf][1] - mn0);
                S[nf][2] = __expf(S[nf][2] - mn1);
                S[nf][3] = __expf(S[nf][3] - mn1);
                rs0 += S[nf][0] + S[nf][1];
                rs1 += S[nf][2] + S[nf][3];
            }
            rs0 += __shfl_xor_sync(0xffffffffu, rs0, 1);
            rs0 += __shfl_xor_sync(0xffffffffu, rs0, 2);
            rs1 += __shfl_xor_sync(0xffffffffu, rs1, 1);
            rs1 += __shfl_xor_sync(0xffffffffu, rs1, 2);
            lrow[0] = lrow[0] * a0 + rs0;
            lrow[1] = lrow[1] * a1 + rs1;

#pragma unroll
            for (int nf = 0; nf < 8; nf++) {
                O[nf][0] *= a0; O[nf][1] *= a0;
                O[nf][2] *= a1; O[nf][3] *= a1;
            }

#pragma unroll
            for (int ks2 = 0; ks2 < 8; ks2++) {
                uint32_t ah[4], al[4];
                split2(S[2 * ks2][0],     S[2 * ks2][1],     ah[0], al[0]);
                split2(S[2 * ks2][2],     S[2 * ks2][3],     ah[1], al[1]);
                split2(S[2 * ks2 + 1][0], S[2 * ks2 + 1][1], ah[2], al[2]);
                split2(S[2 * ks2 + 1][2], S[2 * ks2 + 1][3], ah[3], al[3]);
#pragma unroll
                for (int i = 0; i < 4; i++) {
                    uint32_t off = ((ks2 * 16 + v_rof) * AST + i * 16 + v_cof) * 2;
                    uint32_t vh4[4], vl4[4];
                    ldsm4t(vh4, sVh + off);
                    ldsm4t(vl4, sVl + off);
#pragma unroll
                    for (int half = 0; half < 2; half++) {
                        int nf = i * 2 + half;
                        mma_bf16(O[nf], ah, &vh4[half * 2]);
                        mma_bf16(O[nf], ah, &vl4[half * 2]);
                        mma_bf16(O[nf], al, &vh4[half * 2]);
                    }
                }
            }
            __syncthreads();
        }

        const float inv0 = 1.f / lrow[0];
        const float inv1 = 1.f / lrow[1];
        const size_t row0 = (size_t)b * T_ + qb * 128 + wid * 16 + (lane >> 2);
#pragma unroll
        for (int nf = 0; nf < 8; nf++) {
            int col = h * 64 + nf * 8 + (lane & 3) * 2;
            uint32_t hi, lo;
            split2(O[nf][0] * inv0, O[nf][1] * inv0, hi, lo);
            *(uint32_t*)(g_oh + row0 * C_ + col) = hi;
            *(uint32_t*)(g_ol + row0 * C_ + col) = lo;
            split2(O[nf][2] * inv1, O[nf][3] * inv1, hi, lo);
            *(uint32_t*)(g_oh + (row0 + 8) * C_ + col) = hi;
            *(uint32_t*)(g_ol + (row0 + 8) * C_ + col) = lo;
        }
    };

    process_qblock(pair);
    __syncthreads();
    process_qblock(NQB - 1 - pair);
}

// ---------------------------------------------------------------------------
extern "C" void kernel_launch(void* const* d_in, const int* in_sizes, int n_in,
                              void* d_out, int out_size) {
    const float* hidden = (const float*)d_in[0];
    const float* W_qkv  = (const float*)d_in[2];
    const float* b_qkv  = (const float*)d_in[3];
    const float* W_o    = (const float*)d_in[4];
    const float* b_o    = (const float*)d_in[5];
    float* out = (float*)d_out;

    __nv_bfloat16 *xhi, *xlo, *wqhi, *wqlo, *wohi, *wolo, *oh, *ol;
    cudaGetSymbolAddress((void**)&xhi, g_xhi);
    cudaGetSymbolAddress((void**)&xlo, g_xlo);
    cudaGetSymbolAddress((void**)&wqhi, g_wqhi);
    cudaGetSymbolAddress((void**)&wqlo, g_wqlo);
    cudaGetSymbolAddress((void**)&wohi, g_wohi);
    cudaGetSymbolAddress((void**)&wolo, g_wolo);
    cudaGetSymbolAddress((void**)&oh, g_oh);
    cudaGetSymbolAddress((void**)&ol, g_ol);

    cudaFuncSetAttribute(gemm_mma<0>, cudaFuncAttributeMaxDynamicSharedMemorySize, GK_SMEM);
    cudaFuncSetAttribute(gemm_mma<1>, cudaFuncAttributeMaxDynamicSharedMemorySize, GK_SMEM);
    cudaFuncSetAttribute(attn_tc, cudaFuncAttributeMaxDynamicSharedMemorySize, A_SMEM);

    // hi/lo conversions
    {
        int n4 = (M_ * C_) / 4;
        cvt_hilo<<<(n4 + 255) / 256, 256>>>((const float4*)hidden, (uint2*)xhi, (uint2*)xlo, n4);
        n4 = (C3_ * C_) / 4;
        cvt_hilo<<<(n4 + 255) / 256, 256>>>((const float4*)W_qkv, (uint2*)wqhi, (uint2*)wqlo, n4);
        n4 = (C_ * C_) / 4;
        cvt_hilo<<<(n4 + 255) / 256, 256>>>((const float4*)W_o, (uint2*)wohi, (uint2*)wolo, n4);
    }

    // 1) QKV projection -> Q,K,V hi/lo [B,H,T,D]
    {
        dim3 grid(C3_ / 128, M_ / 128);
        gemm_mma<1><<<grid, 128, GK_SMEM>>>(xhi, xlo, wqhi, wqlo, b_qkv, nullptr, M_, C3_, C_);
    }
    // 2) tensor-core flash attention (balanced q-block pairs) -> g_oh/g_ol
    {
        dim3 grid(NQB / 2, H_, B_);
        attn_tc<<<grid, 256, A_SMEM>>>();
    }
    // 3) out = O @ W_o^T + b_o
    {
        dim3 grid(C_ / 128, M_ / 128);
        gemm_mma<0><<<grid, 128, GK_SMEM>>>(oh, ol, wohi, wolo, b_o, out, M_, C_, C_);
    }
}

// round 10
// speedup vs baseline: 1.0174x; 1.0174x over previous
#include <cuda_runtime.h>
#include <cuda_bf16.h>
#include <cstdint>

#define B_ 4
#define T_ 2048
#define C_ 1024
#define H_ 16
#define D_ 64
#define C3_ (3 * C_)
#define M_ (B_ * T_)   // 8192
#define NQB (T_ / 128) // 16 q-blocks per (b,h)

// ---------------- scratch (device globals; no runtime alloc) ----------------
__device__ __nv_bfloat16 g_xhi[(size_t)M_ * C_],  g_xlo[(size_t)M_ * C_];
__device__ __nv_bfloat16 g_wqhi[(size_t)C3_ * C_], g_wqlo[(size_t)C3_ * C_];
__device__ __nv_bfloat16 g_wohi[(size_t)C_ * C_],  g_wolo[(size_t)C_ * C_];
__device__ __nv_bfloat16 g_qh[(size_t)M_ * C_], g_ql[(size_t)M_ * C_];
__device__ __nv_bfloat16 g_kh[(size_t)M_ * C_], g_kl[(size_t)M_ * C_];
__device__ __nv_bfloat16 g_vh[(size_t)M_ * C_], g_vl[(size_t)M_ * C_];
__device__ __nv_bfloat16 g_oh[(size_t)M_ * C_], g_ol[(size_t)M_ * C_];

// ---------------------------- helpers ---------------------------------------
__device__ __forceinline__ uint32_t smem_u32(const void* p) {
    uint32_t a;
    asm("{ .reg .u64 t; cvta.to.shared.u64 t, %1; cvt.u32.u64 %0, t; }"
        : "=r"(a) : "l"(p));
    return a;
}
__device__ __forceinline__ void cp16(uint32_t dst, const void* src) {
    asm volatile("cp.async.cg.shared.global [%0], [%1], 16;" :: "r"(dst), "l"(src));
}
__device__ __forceinline__ void cp_commit() {
    asm volatile("cp.async.commit_group;" ::: "memory");
}
__device__ __forceinline__ void cp_wait0() {
    asm volatile("cp.async.wait_group 0;" ::: "memory");
}
__device__ __forceinline__ void cp_wait1() {
    asm volatile("cp.async.wait_group 1;" ::: "memory");
}
__device__ __forceinline__ void ldsm4(uint32_t* r, uint32_t addr) {
    asm volatile("ldmatrix.sync.aligned.m8n8.x4.shared.b16 {%0,%1,%2,%3}, [%4];"
                 : "=r"(r[0]), "=r"(r[1]), "=r"(r[2]), "=r"(r[3]) : "r"(addr));
}
__device__ __forceinline__ void ldsm4t(uint32_t* r, uint32_t addr) {
    asm volatile("ldmatrix.sync.aligned.m8n8.x4.trans.shared.b16 {%0,%1,%2,%3}, [%4];"
                 : "=r"(r[0]), "=r"(r[1]), "=r"(r[2]), "=r"(r[3]) : "r"(addr));
}
__device__ __forceinline__ void mma_bf16(float* c, const uint32_t* a, const uint32_t* b) {
    asm volatile(
        "mma.sync.aligned.m16n8k16.row.col.f32.bf16.bf16.f32 "
        "{%0,%1,%2,%3}, {%4,%5,%6,%7}, {%8,%9}, {%0,%1,%2,%3};"
        : "+f"(c[0]), "+f"(c[1]), "+f"(c[2]), "+f"(c[3])
        : "r"(a[0]), "r"(a[1]), "r"(a[2]), "r"(a[3]), "r"(b[0]), "r"(b[1]));
}
__device__ __forceinline__ void split2(float a, float b, uint32_t& hi, uint32_t& lo) {
    __nv_bfloat162 h = __floats2bfloat162_rn(a, b);
    float2 f = __bfloat1622float2(h);
    __nv_bfloat162 l = __floats2bfloat162_rn(a - f.x, b - f.y);
    hi = *reinterpret_cast<uint32_t*>(&h);
    lo = *reinterpret_cast<uint32_t*>(&l);
}

// ---------------------------------------------------------------------------
__global__ void cvt_hilo(const float4* __restrict__ x, uint2* __restrict__ hi,
                         uint2* __restrict__ lo, int n4) {
    int i = blockIdx.x * blockDim.x + threadIdx.x;
    if (i >= n4) return;
    float4 v = x[i];
    uint32_t h0, l0, h1, l1;
    split2(v.x, v.y, h0, l0);
    split2(v.z, v.w, h1, l1);
    hi[i] = make_uint2(h0, h1);
    lo[i] = make_uint2(l0, l1);
}

// ---------------------------------------------------------------------------
// bf16 hi/lo tensor-core GEMM via mma.sync (8 warps, 64x32 warp tile,
// 2 CTAs/SM). R7-proven pipeline order: wait -> sync -> prefetch next stage
// (prefetching earlier races with other warps' reads of the same buffer).
// MMAs product-outermost: same-acc distance 4.
// ---------------------------------------------------------------------------
#define GSTRIDE 40
#define MAT_BYTES (128 * GSTRIDE * 2)
#define STAGE_BYTES (4 * MAT_BYTES)
#define GK_SMEM (2 * STAGE_BYTES)

template <int MODE>
__global__ __launch_bounds__(256, 2) void gemm_mma(
    const __nv_bfloat16* __restrict__ Ahi, const __nv_bfloat16* __restrict__ Alo,
    const __nv_bfloat16* __restrict__ Bhi, const __nv_bfloat16* __restrict__ Blo,
    const float* __restrict__ bias, float* __restrict__ out,
    int M, int N, int K)
{
    extern __shared__ __align__(128) char dsm[];
    const uint32_t smb = smem_u32(dsm);

    const int tid  = threadIdx.x;
    const int wid  = tid >> 5;
    const int lane = tid & 31;
    const int wm = wid >> 2;
    const int wn = wid & 3;

    const size_t m0 = (size_t)blockIdx.y * 128;
    const size_t n0 = (size_t)blockIdx.x * 128;

    const __nv_bfloat16* srcs[4] = {Ahi + m0 * K, Alo + m0 * K,
                                    Bhi + n0 * K, Blo + n0 * K};

    float acc[4][4][4];
#pragma unroll
    for (int i = 0; i < 4; i++)
#pragma unroll
        for (int j = 0; j < 4; j++)
#pragma unroll
            for (int k = 0; k < 4; k++) acc[i][j][k] = 0.f;

    auto load_stage = [&](int kt, int s) {
        const int k0 = kt * 32;
        const uint32_t sb = smb + s * STAGE_BYTES;
#pragma unroll
        for (int m = 0; m < 4; m++) {
            const __nv_bfloat16* src = srcs[m];
#pragma unroll
            for (int i = 0; i < 2; i++) {
                int idx = tid + i * 256;
                int row = idx >> 2;
                int q   = idx & 3;
                cp16(sb + m * MAT_BYTES + (row * GSTRIDE + q * 8) * 2,
                     src + (size_t)row * K + k0 + q * 8);
            }
        }
        cp_commit();
    };

    const uint32_t a_row = (uint32_t)(wm * 64 + (lane & 15));
    const uint32_t a_kof = (uint32_t)(((lane >> 4) & 1) * 8);
    const uint32_t b_row = (uint32_t)(wn * 32 + (lane & 7) + ((lane >> 4) & 1) * 8);
    const uint32_t b_kof = (uint32_t)(((lane >> 3) & 1) * 8);

    const int NT = K >> 5;
    load_stage(0, 0);

    for (int kt = 0; kt < NT; kt++) {
        cp_wait0();
        __syncthreads();           // everyone done reading buffer (kt+1)&1
        if (kt + 1 < NT) load_stage(kt + 1, (kt + 1) & 1);

        const uint32_t sb = smb + (kt & 1) * STAGE_BYTES;
        const uint32_t sAhi = sb;
        const uint32_t sAlo = sb + MAT_BYTES;
        const uint32_t sBhi = sb + 2 * MAT_BYTES;
        const uint32_t sBlo = sb + 3 * MAT_BYTES;

#pragma unroll
        for (int ks = 0; ks < 2; ks++) {
            uint32_t bh[2][4], bl[2][4];
#pragma unroll
            for (int nf2 = 0; nf2 < 2; nf2++) {
                uint32_t off = ((b_row + nf2 * 16) * GSTRIDE + ks * 16 + b_kof) * 2;
                ldsm4(bh[nf2], sBhi + off);
                ldsm4(bl[nf2], sBlo + off);
            }
            uint32_t ah[2][4], al[2][4];
            {
                uint32_t off0 = (a_row * GSTRIDE + ks * 16 + a_kof) * 2;
                ldsm4(ah[0], sAhi + off0);
                ldsm4(al[0], sAlo + off0);
            }
#pragma unroll
            for (int mf = 0; mf < 4; mf++) {
                const int cur = mf & 1, nxt = cur ^ 1;
                if (mf < 3) {
                    uint32_t offn = ((a_row + (mf + 1) * 16) * GSTRIDE + ks * 16 + a_kof) * 2;
                    ldsm4(ah[nxt], sAhi + offn);
                    ldsm4(al[nxt], sAlo + offn);
                }
                // product-outermost: same-acc distance = 4
#pragma unroll
                for (int nf = 0; nf < 4; nf++)
                    mma_bf16(acc[mf][nf], ah[cur], &bh[nf >> 1][(nf & 1) * 2]);
#pragma unroll
                for (int nf = 0; nf < 4; nf++)
                    mma_bf16(acc[mf][nf], ah[cur], &bl[nf >> 1][(nf & 1) * 2]);
#pragma unroll
                for (int nf = 0; nf < 4; nf++)
                    mma_bf16(acc[mf][nf], al[cur], &bh[nf >> 1][(nf & 1) * 2]);
            }
        }
    }

    const int r_in = lane >> 2;
    const int c_in = (lane & 3) * 2;

    if (MODE == 0) {
#pragma unroll
        for (int mf = 0; mf < 4; mf++) {
#pragma unroll
            for (int nf = 0; nf < 4; nf++) {
                size_t row = m0 + wm * 64 + mf * 16 + r_in;
                size_t col = n0 + wn * 32 + nf * 8 + c_in;
                float bx = bias[col], by = bias[col + 1];
                float2 o0 = make_float2(acc[mf][nf][0] + bx, acc[mf][nf][1] + by);
                float2 o1 = make_float2(acc[mf][nf][2] + bx, acc[mf][nf][3] + by);
                *(float2*)(out + row * N + col) = o0;
                *(float2*)(out + (row + 8) * N + col) = o1;
            }
        }
    } else {
        __nv_bfloat16* dh[3] = {g_qh, g_kh, g_vh};
        __nv_bfloat16* dl[3] = {g_ql, g_kl, g_vl};
#pragma unroll
        for (int mf = 0; mf < 4; mf++) {
#pragma unroll
            for (int nf = 0; nf < 4; nf++) {
                size_t col = n0 + wn * 32 + nf * 8 + c_in;
                int sec = (int)(col >> 10);
                int h   = (int)((col >> 6) & 15);
                int d   = (int)(col & 63);
                float bx = bias[col], by = bias[col + 1];
#pragma unroll
                for (int half = 0; half < 2; half++) {
                    size_t row = m0 + wm * 64 + mf * 16 + r_in + half * 8;
                    int b = (int)(row >> 11);
                    int t = (int)(row & 2047);
                    size_t idx = (((size_t)(b * H_ + h) * T_ + t) * D_ + d);
                    float v0 = acc[mf][nf][half * 2 + 0] + bx;
                    float v1 = acc[mf][nf][half * 2 + 1] + by;
                    uint32_t hi, lo;
                    split2(v0, v1, hi, lo);
                    *(uint32_t*)(dh[sec] + idx) = hi;
                    *(uint32_t*)(dl[sec] + idx) = lo;
                }
            }
        }
    }
}

// ---------------------------------------------------------------------------
// Tensor-core causal flash attention, hi/lo bf16 mma.sync.
// S-phase K-rows unrolled x2, product-outer (same-acc distance 4);
// PV preloads all 4 d-block V frags (distance 8). Base-2 softmax.
// load_kv(kt+1) early-issue is safe here: every iteration ends with
// __syncthreads() before the buffer is rewritten.
// ---------------------------------------------------------------------------
#define AST 72
#define QSZ (128 * AST)
#define KVSZ (128 * AST)
#define KVSTAGE (4 * KVSZ)
#define A_SMEM ((2 * QSZ + 2 * KVSTAGE) * 2)

__global__ __launch_bounds__(256) void attn_tc() {
    extern __shared__ __align__(128) __nv_bfloat16 sm[];
    const uint32_t smb = smem_u32(sm);
    const uint32_t sQhi = smb;
    const uint32_t sQlo = smb + QSZ * 2;
    const uint32_t sKV0 = smb + 2 * QSZ * 2;

    const int pair = blockIdx.x;
    const int h  = blockIdx.y;
    const int b  = blockIdx.z;
    const int tid  = threadIdx.x;
    const int wid  = tid >> 5;
    const int lane = tid & 31;
    const int bh = b * H_ + h;

    const __nv_bfloat16* gkh = g_kh + (size_t)bh * T_ * D_;
    const __nv_bfloat16* gkl = g_kl + (size_t)bh * T_ * D_;
    const __nv_bfloat16* gvh = g_vh + (size_t)bh * T_ * D_;
    const __nv_bfloat16* gvl = g_vl + (size_t)bh * T_ * D_;

    auto load_kv = [&](int kt, int s) {
        const uint32_t sb = sKV0 + s * KVSTAGE * 2;
        const __nv_bfloat16* bases[4] = {
            gkh + (size_t)kt * 128 * D_, gkl + (size_t)kt * 128 * D_,
            gvh + (size_t)kt * 128 * D_, gvl + (size_t)kt * 128 * D_};
#pragma unroll
        for (int i = 0; i < 16; i++) {
            int idx = tid + i * 256;
            int arr = idx >> 10;
            int rem = idx & 1023;
            int row = rem >> 3;
            int ch  = rem & 7;
            cp16(sb + (arr * KVSZ + row * AST + ch * 8) * 2,
                 bases[arr] + (size_t)row * D_ + ch * 8);
        }
        cp_commit();
    };

    const uint32_t k_row = (uint32_t)((lane & 7) + ((lane >> 4) & 1) * 8);
    const uint32_t k_kof = ((lane >> 3) & 1) * 8;
    const uint32_t v_rof = (uint32_t)(lane & 15);
    const uint32_t v_cof = ((lane >> 4) & 1) * 8;

    // base-2 softmax scale: D^-0.5 * log2(e)
    const float SC2 = 0.125f * 1.44269504f;

    auto process_qblock = [&](int qb) {
        const __nv_bfloat16* gqh = g_qh + ((size_t)bh * T_ + qb * 128) * D_;
        const __nv_bfloat16* gql = g_ql + ((size_t)bh * T_ + qb * 128) * D_;
#pragma unroll
        for (int i = 0; i < 8; i++) {
            int idx = tid + i * 256;
            int arr = idx >> 10;
            int rem = idx & 1023;
            int row = rem >> 3;
            int ch  = rem & 7;
            const __nv_bfloat16* src = (arr ? gql : gqh) + (size_t)row * D_ + ch * 8;
            cp16((arr ? sQlo : sQhi) + (row * AST + ch * 8) * 2, src);
        }
        cp_commit();
        load_kv(0, 0);
        cp_wait0();
        __syncthreads();

        uint32_t qhF[4][4], qlF[4][4];
        {
            uint32_t rbase = (uint32_t)(wid * 16 + (lane & 15));
            uint32_t kof = ((lane >> 4) & 1) * 8;
#pragma unroll
            for (int ks = 0; ks < 4; ks++) {
                uint32_t off = (rbase * AST + ks * 16 + kof) * 2;
                ldsm4(qhF[ks], sQhi + off);
                ldsm4(qlF[ks], sQlo + off);
            }
        }

        float O[8][4];
#pragma unroll
        for (int i = 0; i < 8; i++)
#pragma unroll
            for (int j = 0; j < 4; j++) O[i][j] = 0.f;
        float mrow[2] = {-1e30f, -1e30f};
        float lrow[2] = {0.f, 0.f};

        for (int kt = 0; kt <= qb; kt++) {
            const bool more = (kt + 1 <= qb);
            if (more) load_kv(kt + 1, (kt + 1) & 1);
            if (more) cp_wait1(); else cp_wait0();
            __syncthreads();

            const uint32_t sb = sKV0 + (kt & 1) * KVSTAGE * 2;
            const uint32_t sKh = sb;
            const uint32_t sKl = sb + KVSZ * 2;
            const uint32_t sVh = sb + 2 * KVSZ * 2;
            const uint32_t sVl = sb + 3 * KVSZ * 2;

            // ---- S = Q K^T (K-rows unrolled x2; product-outer MMAs) --------
            float S[16][4];
#pragma unroll
            for (int i = 0; i < 16; i++)
#pragma unroll
                for (int j = 0; j < 4; j++) S[i][j] = 0.f;

#pragma unroll
            for (int ks = 0; ks < 4; ks++) {
#pragma unroll
                for (int i2 = 0; i2 < 4; i2++) {
                    uint32_t kh4[2][4], kl4[2][4];
#pragma unroll
                    for (int ii = 0; ii < 2; ii++) {
                        uint32_t off = (((i2 * 2 + ii) * 16 + k_row) * AST
                                        + ks * 16 + k_kof) * 2;
                        ldsm4(kh4[ii], sKh + off);
                        ldsm4(kl4[ii], sKl + off);
                    }
#pragma unroll
                    for (int ii = 0; ii < 2; ii++)
#pragma unroll
                        for (int half = 0; half < 2; half++)
                            mma_bf16(S[(i2 * 2 + ii) * 2 + half], qhF[ks],
                                     &kh4[ii][half * 2]);
#pragma unroll
                    for (int ii = 0; ii < 2; ii++)
#pragma unroll
                        for (int half = 0; half < 2; half++)
                            mma_bf16(S[(i2 * 2 + ii) * 2 + half], qhF[ks],
                                     &kl4[ii][half * 2]);
#pragma unroll
                    for (int ii = 0; ii < 2; ii++)
#pragma unroll
                        for (int half = 0; half < 2; half++)
                            mma_bf16(S[(i2 * 2 + ii) * 2 + half], qlF[ks],
                                     &kh4[ii][half * 2]);
                }
            }

            // ---- scale (base-2) + causal mask ------------------------------
#pragma unroll
            for (int i = 0; i < 16; i++)
#pragma unroll
                for (int j = 0; j < 4; j++) S[i][j] *= SC2;

            if (kt == qb) {
                const int r0 = wid * 16 + (lane >> 2);
#pragma unroll
                for (int nf = 0; nf < 16; nf++) {
                    int col = nf * 8 + (lane & 3) * 2;
                    if (col > r0)      S[nf][0] = -1e30f;
                    if (col + 1 > r0)  S[nf][1] = -1e30f;
                    if (col > r0 + 8)     S[nf][2] = -1e30f;
                    if (col + 1 > r0 + 8) S[nf][3] = -1e30f;
                }
            }

            // ---- online softmax (base-2, in-warp) --------------------------
            float rm0 = -1e30f, rm1 = -1e30f;
#pragma unroll
            for (int nf = 0; nf < 16; nf++) {
                rm0 = fmaxf(rm0, fmaxf(S[nf][0], S[nf][1]));
                rm1 = fmaxf(rm1, fmaxf(S[nf][2], S[nf][3]));
            }
            rm0 = fmaxf(rm0, __shfl_xor_sync(0xffffffffu, rm0, 1));
            rm0 = fmaxf(rm0, __shfl_xor_sync(0xffffffffu, rm0, 2));
            rm1 = fmaxf(rm1, __shfl_xor_sync(0xffffffffu, rm1, 1));
            rm1 = fmaxf(rm1, __shfl_xor_sync(0xffffffffu, rm1, 2));

            float mn0 = fmaxf(mrow[0], rm0);
            float mn1 = fmaxf(mrow[1], rm1);
            float a0 = exp2f(mrow[0] - mn0);
            float a1 = exp2f(mrow[1] - mn1);
            mrow[0] = mn0; mrow[1] = mn1;

            float rs0 = 0.f, rs1 = 0.f;
#pragma unroll
            for (int nf = 0; nf < 16; nf++) {
                S[nf][0] = exp2f(S[nf][0] - mn0);
                S[nf][1] = exp2f(S[nf][1] - mn0);
                S[nf][2] = exp2f(S[nf][2] - mn1);
                S[nf][3] = exp2f(S[nf][3] - mn1);
                rs0 += S[nf][0] + S[nf][1];
                rs1 += S[nf][2] + S[nf][3];
            }
            rs0 += __shfl_xor_sync(0xffffffffu, rs0, 1);
            rs0 += __shfl_xor_sync(0xffffffffu, rs0, 2);
            rs1 += __shfl_xor_sync(0xffffffffu, rs1, 1);
            rs1 += __shfl_xor_sync(0xffffffffu, rs1, 2);
            lrow[0] = lrow[0] * a0 + rs0;
            lrow[1] = lrow[1] * a1 + rs1;

#pragma unroll
            for (int nf = 0; nf < 8; nf++) {
                O[nf][0] *= a0; O[nf][1] *= a0;
                O[nf][2] *= a1; O[nf][3] *= a1;
            }

            // ---- O += P V: preload all 4 d-block V frags; product-outer ----
#pragma unroll
            for (int ks2 = 0; ks2 < 8; ks2++) {
                uint32_t ah[4], al[4];
                split2(S[2 * ks2][0],     S[2 * ks2][1],     ah[0], al[0]);
                split2(S[2 * ks2][2],     S[2 * ks2][3],     ah[1], al[1]);
                split2(S[2 * ks2 + 1][0], S[2 * ks2 + 1][1], ah[2], al[2]);
                split2(S[2 * ks2 + 1][2], S[2 * ks2 + 1][3], ah[3], al[3]);

                uint32_t vh4[4][4], vl4[4][4];
#pragma unroll
                for (int i = 0; i < 4; i++) {
                    uint32_t off = ((ks2 * 16 + v_rof) * AST + i * 16 + v_cof) * 2;
                    ldsm4t(vh4[i], sVh + off);
                    ldsm4t(vl4[i], sVl + off);
                }
#pragma unroll
                for (int i = 0; i < 4; i++)
#pragma unroll
                    for (int half = 0; half < 2; half++)
                        mma_bf16(O[i * 2 + half], ah, &vh4[i][half * 2]);
#pragma unroll
                for (int i = 0; i < 4; i++)
#pragma unroll
                    for (int half = 0; half < 2; half++)
                        mma_bf16(O[i * 2 + half], ah, &vl4[i][half * 2]);
#pragma unroll
                for (int i = 0; i < 4; i++)
#pragma unroll
                    for (int half = 0; half < 2; half++)
                        mma_bf16(O[i * 2 + half], al, &vh4[i][half * 2]);
            }
            __syncthreads();
        }

        const float inv0 = 1.f / lrow[0];
        const float inv1 = 1.f / lrow[1];
        const size_t row0 = (size_t)b * T_ + qb * 128 + wid * 16 + (lane >> 2);
#pragma unroll
        for (int nf = 0; nf < 8; nf++) {
            int col = h * 64 + nf * 8 + (lane & 3) * 2;
            uint32_t hi, lo;
            split2(O[nf][0] * inv0, O[nf][1] * inv0, hi, lo);
            *(uint32_t*)(g_oh + row0 * C_ + col) = hi;
            *(uint32_t*)(g_ol + row0 * C_ + col) = lo;
            split2(O[nf][2] * inv1, O[nf][3] * inv1, hi, lo);
            *(uint32_t*)(g_oh + (row0 + 8) * C_ + col) = hi;
            *(uint32_t*)(g_ol + (row0 + 8) * C_ + col) = lo;
        }
    };

    process_qblock(pair);
    __syncthreads();
    process_qblock(NQB - 1 - pair);
}

// ---------------------------------------------------------------------------
extern "C" void kernel_launch(void* const* d_in, const int* in_sizes, int n_in,
                              void* d_out, int out_size) {
    const float* hidden = (const float*)d_in[0];
    const float* W_qkv  = (const float*)d_in[2];
    const float* b_qkv  = (const float*)d_in[3];
    const float* W_o    = (const float*)d_in[4];
    const float* b_o    = (const float*)d_in[5];
    float* out = (float*)d_out;

    __nv_bfloat16 *xhi, *xlo, *wqhi, *wqlo, *wohi, *wolo, *oh, *ol;
    cudaGetSymbolAddress((void**)&xhi, g_xhi);
    cudaGetSymbolAddress((void**)&xlo, g_xlo);
    cudaGetSymbolAddress((void**)&wqhi, g_wqhi);
    cudaGetSymbolAddress((void**)&wqlo, g_wqlo);
    cudaGetSymbolAddress((void**)&wohi, g_wohi);
    cudaGetSymbolAddress((void**)&wolo, g_wolo);
    cudaGetSymbolAddress((void**)&oh, g_oh);
    cudaGetSymbolAddress((void**)&ol, g_ol);

    cudaFuncSetAttribute(gemm_mma<0>, cudaFuncAttributeMaxDynamicSharedMemorySize, GK_SMEM);
    cudaFuncSetAttribute(gemm_mma<1>, cudaFuncAttributeMaxDynamicSharedMemorySize, GK_SMEM);
    cudaFuncSetAttribute(attn_tc, cudaFuncAttributeMaxDynamicSharedMemorySize, A_SMEM);

    {
        int n4 = (M_ * C_) / 4;
        cvt_hilo<<<(n4 + 255) / 256, 256>>>((const float4*)hidden, (uint2*)xhi, (uint2*)xlo, n4);
        n4 = (C3_ * C_) / 4;
        cvt_hilo<<<(n4 + 255) / 256, 256>>>((const float4*)W_qkv, (uint2*)wqhi, (uint2*)wqlo, n4);
        n4 = (C_ * C_) / 4;
        cvt_hilo<<<(n4 + 255) / 256, 256>>>((const float4*)W_o, (uint2*)wohi, (uint2*)wolo, n4);
    }

    {
        dim3 grid(C3_ / 128, M_ / 128);
        gemm_mma<1><<<grid, 256, GK_SMEM>>>(xhi, xlo, wqhi, wqlo, b_qkv, nullptr, M_, C3_, C_);
    }
    {
        dim3 grid(NQB / 2, H_, B_);
        attn_tc<<<grid, 256, A_SMEM>>>();
    }
    {
        dim3 grid(C_ / 128, M_ / 128);
        gemm_mma<0><<<grid, 256, GK_SMEM>>>(oh, ol, wohi, wolo, b_o, out, M_, C_, C_);
    }
}

// round 11
// speedup vs baseline: 1.4411x; 1.4164x over previous
#include <cuda_runtime.h>
#include <cuda_fp16.h>
#include <cstdint>

#define B_ 4
#define T_ 2048
#define C_ 1024
#define H_ 16
#define D_ 64
#define C3_ (3 * C_)
#define M_ (B_ * T_)   // 8192
#define NQB (T_ / 128) // 16 q-blocks per (b,h)

// ---------------- scratch (device globals; no runtime alloc) ----------------
// A-side: fp16 hi/lo. B-side: single fp16.
__device__ __half g_xhi[(size_t)M_ * C_],  g_xlo[(size_t)M_ * C_];
__device__ __half g_wq[(size_t)C3_ * C_];            // W_qkv fp16
__device__ __half g_wo[(size_t)C_ * C_];             // W_o   fp16
__device__ __half g_qh[(size_t)M_ * C_], g_ql[(size_t)M_ * C_];  // Q hi/lo [B,H,T,D]
__device__ __half g_k[(size_t)M_ * C_];              // K fp16 [B,H,T,D]
__device__ __half g_v[(size_t)M_ * C_];              // V fp16 [B,H,T,D]
__device__ __half g_oh[(size_t)M_ * C_], g_ol[(size_t)M_ * C_];  // attn out hi/lo

// ---------------------------- helpers ---------------------------------------
__device__ __forceinline__ uint32_t smem_u32(const void* p) {
    uint32_t a;
    asm("{ .reg .u64 t; cvta.to.shared.u64 t, %1; cvt.u32.u64 %0, t; }"
        : "=r"(a) : "l"(p));
    return a;
}
__device__ __forceinline__ void cp16(uint32_t dst, const void* src) {
    asm volatile("cp.async.cg.shared.global [%0], [%1], 16;" :: "r"(dst), "l"(src));
}
__device__ __forceinline__ void cp_commit() {
    asm volatile("cp.async.commit_group;" ::: "memory");
}
__device__ __forceinline__ void cp_wait0() {
    asm volatile("cp.async.wait_group 0;" ::: "memory");
}
__device__ __forceinline__ void cp_wait1() {
    asm volatile("cp.async.wait_group 1;" ::: "memory");
}
__device__ __forceinline__ void ldsm4(uint32_t* r, uint32_t addr) {
    asm volatile("ldmatrix.sync.aligned.m8n8.x4.shared.b16 {%0,%1,%2,%3}, [%4];"
                 : "=r"(r[0]), "=r"(r[1]), "=r"(r[2]), "=r"(r[3]) : "r"(addr));
}
__device__ __forceinline__ void ldsm4t(uint32_t* r, uint32_t addr) {
    asm volatile("ldmatrix.sync.aligned.m8n8.x4.trans.shared.b16 {%0,%1,%2,%3}, [%4];"
                 : "=r"(r[0]), "=r"(r[1]), "=r"(r[2]), "=r"(r[3]) : "r"(addr));
}
__device__ __forceinline__ void mma_f16(float* c, const uint32_t* a, const uint32_t* b) {
    asm volatile(
        "mma.sync.aligned.m16n8k16.row.col.f32.f16.f16.f32 "
        "{%0,%1,%2,%3}, {%4,%5,%6,%7}, {%8,%9}, {%0,%1,%2,%3};"
        : "+f"(c[0]), "+f"(c[1]), "+f"(c[2]), "+f"(c[3])
        : "r"(a[0]), "r"(a[1]), "r"(a[2]), "r"(a[3]), "r"(b[0]), "r"(b[1]));
}
__device__ __forceinline__ void split2h(float a, float b, uint32_t& hi, uint32_t& lo) {
    __half2 h = __floats2half2_rn(a, b);
    float2 f = __half22float2(h);
    __half2 l = __floats2half2_rn(a - f.x, b - f.y);
    hi = *reinterpret_cast<uint32_t*>(&h);
    lo = *reinterpret_cast<uint32_t*>(&l);
}
__device__ __forceinline__ uint32_t pack2h(float a, float b) {
    __half2 h = __floats2half2_rn(a, b);
    return *reinterpret_cast<uint32_t*>(&h);
}

// ---------------------------------------------------------------------------
// fp32 -> fp16 hi/lo split (A-side), and fp32 -> fp16 single (B-side)
// ---------------------------------------------------------------------------
__global__ void cvt_hilo_h(const float4* __restrict__ x, uint2* __restrict__ hi,
                           uint2* __restrict__ lo, int n4) {
    int i = blockIdx.x * blockDim.x + threadIdx.x;
    if (i >= n4) return;
    float4 v = x[i];
    uint32_t h0, l0, h1, l1;
    split2h(v.x, v.y, h0, l0);
    split2h(v.z, v.w, h1, l1);
    hi[i] = make_uint2(h0, h1);
    lo[i] = make_uint2(l0, l1);
}
__global__ void cvt_h(const float4* __restrict__ x, uint2* __restrict__ o, int n4) {
    int i = blockIdx.x * blockDim.x + threadIdx.x;
    if (i >= n4) return;
    float4 v = x[i];
    o[i] = make_uint2(pack2h(v.x, v.y), pack2h(v.z, v.w));
}

// ---------------------------------------------------------------------------
// fp16 GEMM via mma.sync: out[M,N] = (Ahi+Alo)[M,K] @ B[N,K]^T + bias
// A split hi/lo (2 products), B single fp16. 8 warps, 64x32 warp tile,
// 2 CTAs/SM, BK=32, double-buffered cp.async (wait -> sync -> prefetch).
// MODE 0: fp32 out + bias. MODE 1: QKV -> Q hi/lo + K,V single [B,H,T,D].
// ---------------------------------------------------------------------------
#define GSTRIDE 40
#define MAT_BYTES (128 * GSTRIDE * 2)
#define STAGE_BYTES (3 * MAT_BYTES)     // Ahi, Alo, B
#define GK_SMEM (2 * STAGE_BYTES)       // 61440 B

template <int MODE>
__global__ __launch_bounds__(256, 2) void gemm_mma(
    const __half* __restrict__ Ahi, const __half* __restrict__ Alo,
    const __half* __restrict__ Bf,
    const float* __restrict__ bias, float* __restrict__ out,
    int M, int N, int K)
{
    extern __shared__ __align__(128) char dsm[];
    const uint32_t smb = smem_u32(dsm);

    const int tid  = threadIdx.x;
    const int wid  = tid >> 5;
    const int lane = tid & 31;
    const int wm = wid >> 2;
    const int wn = wid & 3;

    const size_t m0 = (size_t)blockIdx.y * 128;
    const size_t n0 = (size_t)blockIdx.x * 128;

    const __half* srcs[3] = {Ahi + m0 * K, Alo + m0 * K, Bf + n0 * K};

    float acc[4][4][4];
#pragma unroll
    for (int i = 0; i < 4; i++)
#pragma unroll
        for (int j = 0; j < 4; j++)
#pragma unroll
            for (int k = 0; k < 4; k++) acc[i][j][k] = 0.f;

    auto load_stage = [&](int kt, int s) {
        const int k0 = kt * 32;
        const uint32_t sb = smb + s * STAGE_BYTES;
#pragma unroll
        for (int m = 0; m < 3; m++) {
            const __half* src = srcs[m];
#pragma unroll
            for (int i = 0; i < 2; i++) {
                int idx = tid + i * 256;
                int row = idx >> 2;
                int q   = idx & 3;
                cp16(sb + m * MAT_BYTES + (row * GSTRIDE + q * 8) * 2,
                     src + (size_t)row * K + k0 + q * 8);
            }
        }
        cp_commit();
    };

    const uint32_t a_row = (uint32_t)(wm * 64 + (lane & 15));
    const uint32_t a_kof = (uint32_t)(((lane >> 4) & 1) * 8);
    const uint32_t b_row = (uint32_t)(wn * 32 + (lane & 7) + ((lane >> 4) & 1) * 8);
    const uint32_t b_kof = (uint32_t)(((lane >> 3) & 1) * 8);

    const int NT = K >> 5;
    load_stage(0, 0);

    for (int kt = 0; kt < NT; kt++) {
        cp_wait0();
        __syncthreads();           // all warps done reading buffer (kt+1)&1
        if (kt + 1 < NT) load_stage(kt + 1, (kt + 1) & 1);

        const uint32_t sb = smb + (kt & 1) * STAGE_BYTES;
        const uint32_t sAhi = sb;
        const uint32_t sAlo = sb + MAT_BYTES;
        const uint32_t sB   = sb + 2 * MAT_BYTES;

#pragma unroll
        for (int ks = 0; ks < 2; ks++) {
            uint32_t bf[2][4];
#pragma unroll
            for (int nf2 = 0; nf2 < 2; nf2++) {
                uint32_t off = ((b_row + nf2 * 16) * GSTRIDE + ks * 16 + b_kof) * 2;
                ldsm4(bf[nf2], sB + off);
            }
            uint32_t ah[2][4], al[2][4];
            {
                uint32_t off0 = (a_row * GSTRIDE + ks * 16 + a_kof) * 2;
                ldsm4(ah[0], sAhi + off0);
                ldsm4(al[0], sAlo + off0);
            }
#pragma unroll
            for (int mf = 0; mf < 4; mf++) {
                const int cur = mf & 1, nxt = cur ^ 1;
                if (mf < 3) {
                    uint32_t offn = ((a_row + (mf + 1) * 16) * GSTRIDE + ks * 16 + a_kof) * 2;
                    ldsm4(ah[nxt], sAhi + offn);
                    ldsm4(al[nxt], sAlo + offn);
                }
                // product-outermost: same-acc distance = 4
#pragma unroll
                for (int nf = 0; nf < 4; nf++)
                    mma_f16(acc[mf][nf], ah[cur], &bf[nf >> 1][(nf & 1) * 2]);
#pragma unroll
                for (int nf = 0; nf < 4; nf++)
                    mma_f16(acc[mf][nf], al[cur], &bf[nf >> 1][(nf & 1) * 2]);
            }
        }
    }

    const int r_in = lane >> 2;
    const int c_in = (lane & 3) * 2;

    if (MODE == 0) {
#pragma unroll
        for (int mf = 0; mf < 4; mf++) {
#pragma unroll
            for (int nf = 0; nf < 4; nf++) {
                size_t row = m0 + wm * 64 + mf * 16 + r_in;
                size_t col = n0 + wn * 32 + nf * 8 + c_in;
                float bx = bias[col], by = bias[col + 1];
                float2 o0 = make_float2(acc[mf][nf][0] + bx, acc[mf][nf][1] + by);
                float2 o1 = make_float2(acc[mf][nf][2] + bx, acc[mf][nf][3] + by);
                *(float2*)(out + row * N + col) = o0;
                *(float2*)(out + (row + 8) * N + col) = o1;
            }
        }
    } else {
#pragma unroll
        for (int mf = 0; mf < 4; mf++) {
#pragma unroll
            for (int nf = 0; nf < 4; nf++) {
                size_t col = n0 + wn * 32 + nf * 8 + c_in;
                int sec = (int)(col >> 10);      // 0=Q, 1=K, 2=V
                int h   = (int)((col >> 6) & 15);
                int d   = (int)(col & 63);
                float bx = bias[col], by = bias[col + 1];
#pragma unroll
                for (int half = 0; half < 2; half++) {
                    size_t row = m0 + wm * 64 + mf * 16 + r_in + half * 8;
                    int b = (int)(row >> 11);
                    int t = (int)(row & 2047);
                    size_t idx = (((size_t)(b * H_ + h) * T_ + t) * D_ + d);
                    float v0 = acc[mf][nf][half * 2 + 0] + bx;
                    float v1 = acc[mf][nf][half * 2 + 1] + by;
                    if (sec == 0) {
                        uint32_t hi, lo;
                        split2h(v0, v1, hi, lo);
                        *(uint32_t*)(g_qh + idx) = hi;
                        *(uint32_t*)(g_ql + idx) = lo;
                    } else if (sec == 1) {
                        *(uint32_t*)(g_k + idx) = pack2h(v0, v1);
                    } else {
                        *(uint32_t*)(g_v + idx) = pack2h(v0, v1);
                    }
                }
            }
        }
    }
}

// ---------------------------------------------------------------------------
// fp16 causal flash attention. Q split hi/lo (2-product S), K single;
// P split hi/lo (2-product PV), V single. Base-2 softmax, balanced q-pairs.
// ---------------------------------------------------------------------------
#define AST 72
#define QSZ (128 * AST)
#define KVSZ (128 * AST)
#define KVSTAGE (2 * KVSZ)             // K, V (single fp16 each)
#define A_SMEM ((2 * QSZ + 2 * KVSTAGE) * 2)   // 110592 B

__global__ __launch_bounds__(256) void attn_tc() {
    extern __shared__ __align__(128) __half sm[];
    const uint32_t smb = smem_u32(sm);
    const uint32_t sQhi = smb;
    const uint32_t sQlo = smb + QSZ * 2;
    const uint32_t sKV0 = smb + 2 * QSZ * 2;

    const int pair = blockIdx.x;
    const int h  = blockIdx.y;
    const int b  = blockIdx.z;
    const int tid  = threadIdx.x;
    const int wid  = tid >> 5;
    const int lane = tid & 31;
    const int bh = b * H_ + h;

    const __half* gk = g_k + (size_t)bh * T_ * D_;
    const __half* gv = g_v + (size_t)bh * T_ * D_;

    auto load_kv = [&](int kt, int s) {
        const uint32_t sb = sKV0 + s * KVSTAGE * 2;
        const __half* bases[2] = {gk + (size_t)kt * 128 * D_,
                                  gv + (size_t)kt * 128 * D_};
#pragma unroll
        for (int i = 0; i < 8; i++) {
            int idx = tid + i * 256;       // 0..2047
            int arr = idx >> 10;           // 0=K, 1=V
            int rem = idx & 1023;
            int row = rem >> 3;
            int ch  = rem & 7;
            cp16(sb + (arr * KVSZ + row * AST + ch * 8) * 2,
                 bases[arr] + (size_t)row * D_ + ch * 8);
        }
        cp_commit();
    };

    const uint32_t k_row = (uint32_t)((lane & 7) + ((lane >> 4) & 1) * 8);
    const uint32_t k_kof = ((lane >> 3) & 1) * 8;
    const uint32_t v_rof = (uint32_t)(lane & 15);
    const uint32_t v_cof = ((lane >> 4) & 1) * 8;

    // base-2 softmax scale: D^-0.5 * log2(e)
    const float SC2 = 0.125f * 1.44269504f;

    auto process_qblock = [&](int qb) {
        const __half* gqh = g_qh + ((size_t)bh * T_ + qb * 128) * D_;
        const __half* gql = g_ql + ((size_t)bh * T_ + qb * 128) * D_;
#pragma unroll
        for (int i = 0; i < 8; i++) {
            int idx = tid + i * 256;
            int arr = idx >> 10;
            int rem = idx & 1023;
            int row = rem >> 3;
            int ch  = rem & 7;
            const __half* src = (arr ? gql : gqh) + (size_t)row * D_ + ch * 8;
            cp16((arr ? sQlo : sQhi) + (row * AST + ch * 8) * 2, src);
        }
        cp_commit();
        load_kv(0, 0);
        cp_wait0();
        __syncthreads();

        uint32_t qhF[4][4], qlF[4][4];
        {
            uint32_t rbase = (uint32_t)(wid * 16 + (lane & 15));
            uint32_t kof = ((lane >> 4) & 1) * 8;
#pragma unroll
            for (int ks = 0; ks < 4; ks++) {
                uint32_t off = (rbase * AST + ks * 16 + kof) * 2;
                ldsm4(qhF[ks], sQhi + off);
                ldsm4(qlF[ks], sQlo + off);
            }
        }

        float O[8][4];
#pragma unroll
        for (int i = 0; i < 8; i++)
#pragma unroll
            for (int j = 0; j < 4; j++) O[i][j] = 0.f;
        float mrow[2] = {-1e30f, -1e30f};
        float lrow[2] = {0.f, 0.f};

        for (int kt = 0; kt <= qb; kt++) {
            const bool more = (kt + 1 <= qb);
            if (more) load_kv(kt + 1, (kt + 1) & 1);
            if (more) cp_wait1(); else cp_wait0();
            __syncthreads();

            const uint32_t sb = sKV0 + (kt & 1) * KVSTAGE * 2;
            const uint32_t sK = sb;
            const uint32_t sV = sb + KVSZ * 2;

            // ---- S = Q K^T (Q hi/lo, 2 products; K-rows unrolled x2) -------
            float S[16][4];
#pragma unroll
            for (int i = 0; i < 16; i++)
#pragma unroll
                for (int j = 0; j < 4; j++) S[i][j] = 0.f;

#pragma unroll
            for (int ks = 0; ks < 4; ks++) {
#pragma unroll
                for (int i2 = 0; i2 < 4; i2++) {
                    uint32_t kh4[2][4];
#pragma unroll
                    for (int ii = 0; ii < 2; ii++) {
                        uint32_t off = (((i2 * 2 + ii) * 16 + k_row) * AST
                                        + ks * 16 + k_kof) * 2;
                        ldsm4(kh4[ii], sK + off);
                    }
#pragma unroll
                    for (int ii = 0; ii < 2; ii++)
#pragma unroll
                        for (int half = 0; half < 2; half++)
                            mma_f16(S[(i2 * 2 + ii) * 2 + half], qhF[ks],
                                    &kh4[ii][half * 2]);
#pragma unroll
                    for (int ii = 0; ii < 2; ii++)
#pragma unroll
                        for (int half = 0; half < 2; half++)
                            mma_f16(S[(i2 * 2 + ii) * 2 + half], qlF[ks],
                                    &kh4[ii][half * 2]);
                }
            }

            // ---- scale (base-2) + causal mask ------------------------------
#pragma unroll
            for (int i = 0; i < 16; i++)
#pragma unroll
                for (int j = 0; j < 4; j++) S[i][j] *= SC2;

            if (kt == qb) {
                const int r0 = wid * 16 + (lane >> 2);
#pragma unroll
                for (int nf = 0; nf < 16; nf++) {
                    int col = nf * 8 + (lane & 3) * 2;
                    if (col > r0)      S[nf][0] = -1e30f;
                    if (col + 1 > r0)  S[nf][1] = -1e30f;
                    if (col > r0 + 8)     S[nf][2] = -1e30f;
                    if (col + 1 > r0 + 8) S[nf][3] = -1e30f;
                }
            }

            // ---- online softmax (base-2, in-warp) --------------------------
            float rm0 = -1e30f, rm1 = -1e30f;
#pragma unroll
            for (int nf = 0; nf < 16; nf++) {
                rm0 = fmaxf(rm0, fmaxf(S[nf][0], S[nf][1]));
                rm1 = fmaxf(rm1, fmaxf(S[nf][2], S[nf][3]));
            }
            rm0 = fmaxf(rm0, __shfl_xor_sync(0xffffffffu, rm0, 1));
            rm0 = fmaxf(rm0, __shfl_xor_sync(0xffffffffu, rm0, 2));
            rm1 = fmaxf(rm1, __shfl_xor_sync(0xffffffffu, rm1, 1));
            rm1 = fmaxf(rm1, __shfl_xor_sync(0xffffffffu, rm1, 2));

            float mn0 = fmaxf(mrow[0], rm0);
            float mn1 = fmaxf(mrow[1], rm1);
            float a0 = exp2f(mrow[0] - mn0);
            float a1 = exp2f(mrow[1] - mn1);
            mrow[0] = mn0; mrow[1] = mn1;

            float rs0 = 0.f, rs1 = 0.f;
#pragma unroll
            for (int nf = 0; nf < 16; nf++) {
                S[nf][0] = exp2f(S[nf][0] - mn0);
                S[nf][1] = exp2f(S[nf][1] - mn0);
                S[nf][2] = exp2f(S[nf][2] - mn1);
                S[nf][3] = exp2f(S[nf][3] - mn1);
                rs0 += S[nf][0] + S[nf][1];
                rs1 += S[nf][2] + S[nf][3];
            }
            rs0 += __shfl_xor_sync(0xffffffffu, rs0, 1);
            rs0 += __shfl_xor_sync(0xffffffffu, rs0, 2);
            rs1 += __shfl_xor_sync(0xffffffffu, rs1, 1);
            rs1 += __shfl_xor_sync(0xffffffffu, rs1, 2);
            lrow[0] = lrow[0] * a0 + rs0;
            lrow[1] = lrow[1] * a1 + rs1;

#pragma unroll
            for (int nf = 0; nf < 8; nf++) {
                O[nf][0] *= a0; O[nf][1] *= a0;
                O[nf][2] *= a1; O[nf][3] *= a1;
            }

            // ---- O += P V (P hi/lo, 2 products; V single; preload frags) ---
#pragma unroll
            for (int ks2 = 0; ks2 < 8; ks2++) {
                uint32_t ph[4], pl[4];
                split2h(S[2 * ks2][0],     S[2 * ks2][1],     ph[0], pl[0]);
                split2h(S[2 * ks2][2],     S[2 * ks2][3],     ph[1], pl[1]);
                split2h(S[2 * ks2 + 1][0], S[2 * ks2 + 1][1], ph[2], pl[2]);
                split2h(S[2 * ks2 + 1][2], S[2 * ks2 + 1][3], ph[3], pl[3]);

                uint32_t vf[4][4];
#pragma unroll
                for (int i = 0; i < 4; i++) {
                    uint32_t off = ((ks2 * 16 + v_rof) * AST + i * 16 + v_cof) * 2;
                    ldsm4t(vf[i], sV + off);
                }
#pragma unroll
                for (int i = 0; i < 4; i++)
#pragma unroll
                    for (int half = 0; half < 2; half++)
                        mma_f16(O[i * 2 + half], ph, &vf[i][half * 2]);
#pragma unroll
                for (int i = 0; i < 4; i++)
#pragma unroll
                    for (int half = 0; half < 2; half++)
                        mma_f16(O[i * 2 + half], pl, &vf[i][half * 2]);
            }
            __syncthreads();
        }

        const float inv0 = 1.f / lrow[0];
        const float inv1 = 1.f / lrow[1];
        const size_t row0 = (size_t)b * T_ + qb * 128 + wid * 16 + (lane >> 2);
#pragma unroll
        for (int nf = 0; nf < 8; nf++) {
            int col = h * 64 + nf * 8 + (lane & 3) * 2;
            uint32_t hi, lo;
            split2h(O[nf][0] * inv0, O[nf][1] * inv0, hi, lo);
            *(uint32_t*)(g_oh + row0 * C_ + col) = hi;
            *(uint32_t*)(g_ol + row0 * C_ + col) = lo;
            split2h(O[nf][2] * inv1, O[nf][3] * inv1, hi, lo);
            *(uint32_t*)(g_oh + (row0 + 8) * C_ + col) = hi;
            *(uint32_t*)(g_ol + (row0 + 8) * C_ + col) = lo;
        }
    };

    process_qblock(pair);
    __syncthreads();
    process_qblock(NQB - 1 - pair);
}

// ---------------------------------------------------------------------------
extern "C" void kernel_launch(void* const* d_in, const int* in_sizes, int n_in,
                              void* d_out, int out_size) {
    const float* hidden = (const float*)d_in[0];
    const float* W_qkv  = (const float*)d_in[2];
    const float* b_qkv  = (const float*)d_in[3];
    const float* W_o    = (const float*)d_in[4];
    const float* b_o    = (const float*)d_in[5];
    float* out = (float*)d_out;

    __half *xhi, *xlo, *wq, *wo, *oh, *ol;
    cudaGetSymbolAddress((void**)&xhi, g_xhi);
    cudaGetSymbolAddress((void**)&xlo, g_xlo);
    cudaGetSymbolAddress((void**)&wq, g_wq);
    cudaGetSymbolAddress((void**)&wo, g_wo);
    cudaGetSymbolAddress((void**)&oh, g_oh);
    cudaGetSymbolAddress((void**)&ol, g_ol);

    cudaFuncSetAttribute(gemm_mma<0>, cudaFuncAttributeMaxDynamicSharedMemorySize, GK_SMEM);
    cudaFuncSetAttribute(gemm_mma<1>, cudaFuncAttributeMaxDynamicSharedMemorySize, GK_SMEM);
    cudaFuncSetAttribute(attn_tc, cudaFuncAttributeMaxDynamicSharedMemorySize, A_SMEM);

    // conversions: hidden -> fp16 hi/lo; weights -> fp16 single
    {
        int n4 = (M_ * C_) / 4;
        cvt_hilo_h<<<(n4 + 255) / 256, 256>>>((const float4*)hidden,
                                              (uint2*)xhi, (uint2*)xlo, n4);
        n4 = (C3_ * C_) / 4;
        cvt_h<<<(n4 + 255) / 256, 256>>>((const float4*)W_qkv, (uint2*)wq, n4);
        n4 = (C_ * C_) / 4;
        cvt_h<<<(n4 + 255) / 256, 256>>>((const float4*)W_o, (uint2*)wo, n4);
    }

    // 1) QKV projection -> Q hi/lo + K,V single fp16 [B,H,T,D]
    {
        dim3 grid(C3_ / 128, M_ / 128);
        gemm_mma<1><<<grid, 256, GK_SMEM>>>(xhi, xlo, wq, b_qkv, nullptr, M_, C3_, C_);
    }
    // 2) flash attention -> g_oh/g_ol
    {
        dim3 grid(NQB / 2, H_, B_);
        attn_tc<<<grid, 256, A_SMEM>>>();
    }
    // 3) out = O @ W_o^T + b_o
    {
        dim3 grid(C_ / 128, M_ / 128);
        gemm_mma<0><<<grid, 256, GK_SMEM>>>(oh, ol, wo, b_o, out, M_, C_, C_);
    }
}

// round 12
// speedup vs baseline: 1.5108x; 1.0484x over previous
#include <cuda_runtime.h>
#include <cuda_fp16.h>
#include <cstdint>

#define B_ 4
#define T_ 2048
#define C_ 1024
#define H_ 16
#define D_ 64
#define C3_ (3 * C_)
#define M_ (B_ * T_)   // 8192
#define NQB (T_ / 128) // 16 q-blocks per (b,h)

// ---------------- scratch (device globals; no runtime alloc) ----------------
__device__ __half g_xhi[(size_t)M_ * C_],  g_xlo[(size_t)M_ * C_];
__device__ __half g_wq[(size_t)C3_ * C_];            // W_qkv fp16
__device__ __half g_wo[(size_t)C_ * C_];             // W_o   fp16
__device__ __half g_qh[(size_t)M_ * C_], g_ql[(size_t)M_ * C_];  // Q hi/lo [B,H,T,D]
__device__ __half g_k[(size_t)M_ * C_];              // K fp16 [B,H,T,D]
__device__ __half g_v[(size_t)M_ * C_];              // V fp16 [B,H,T,D]
__device__ __half g_oh[(size_t)M_ * C_], g_ol[(size_t)M_ * C_];  // attn out hi/lo

// ---------------------------- helpers ---------------------------------------
__device__ __forceinline__ uint32_t smem_u32(const void* p) {
    uint32_t a;
    asm("{ .reg .u64 t; cvta.to.shared.u64 t, %1; cvt.u32.u64 %0, t; }"
        : "=r"(a) : "l"(p));
    return a;
}
__device__ __forceinline__ void cp16(uint32_t dst, const void* src) {
    asm volatile("cp.async.cg.shared.global [%0], [%1], 16;" :: "r"(dst), "l"(src));
}
__device__ __forceinline__ void cp_commit() {
    asm volatile("cp.async.commit_group;" ::: "memory");
}
__device__ __forceinline__ void cp_wait0() {
    asm volatile("cp.async.wait_group 0;" ::: "memory");
}
__device__ __forceinline__ void cp_wait1() {
    asm volatile("cp.async.wait_group 1;" ::: "memory");
}
__device__ __forceinline__ void ldsm4(uint32_t* r, uint32_t addr) {
    asm volatile("ldmatrix.sync.aligned.m8n8.x4.shared.b16 {%0,%1,%2,%3}, [%4];"
                 : "=r"(r[0]), "=r"(r[1]), "=r"(r[2]), "=r"(r[3]) : "r"(addr));
}
__device__ __forceinline__ void ldsm4t(uint32_t* r, uint32_t addr) {
    asm volatile("ldmatrix.sync.aligned.m8n8.x4.trans.shared.b16 {%0,%1,%2,%3}, [%4];"
                 : "=r"(r[0]), "=r"(r[1]), "=r"(r[2]), "=r"(r[3]) : "r"(addr));
}
__device__ __forceinline__ void mma_f16(float* c, const uint32_t* a, const uint32_t* b) {
    asm volatile(
        "mma.sync.aligned.m16n8k16.row.col.f32.f16.f16.f32 "
        "{%0,%1,%2,%3}, {%4,%5,%6,%7}, {%8,%9}, {%0,%1,%2,%3};"
        : "+f"(c[0]), "+f"(c[1]), "+f"(c[2]), "+f"(c[3])
        : "r"(a[0]), "r"(a[1]), "r"(a[2]), "r"(a[3]), "r"(b[0]), "r"(b[1]));
}
__device__ __forceinline__ void split2h(float a, float b, uint32_t& hi, uint32_t& lo) {
    __half2 h = __floats2half2_rn(a, b);
    float2 f = __half22float2(h);
    __half2 l = __floats2half2_rn(a - f.x, b - f.y);
    hi = *reinterpret_cast<uint32_t*>(&h);
    lo = *reinterpret_cast<uint32_t*>(&l);
}
__device__ __forceinline__ uint32_t pack2h(float a, float b) {
    __half2 h = __floats2half2_rn(a, b);
    return *reinterpret_cast<uint32_t*>(&h);
}

// ---------------------------------------------------------------------------
__global__ void cvt_hilo_h(const float4* __restrict__ x, uint2* __restrict__ hi,
                           uint2* __restrict__ lo, int n4) {
    int i = blockIdx.x * blockDim.x + threadIdx.x;
    if (i >= n4) return;
    float4 v = x[i];
    uint32_t h0, l0, h1, l1;
    split2h(v.x, v.y, h0, l0);
    split2h(v.z, v.w, h1, l1);
    hi[i] = make_uint2(h0, h1);
    lo[i] = make_uint2(l0, l1);
}
__global__ void cvt_h(const float4* __restrict__ x, uint2* __restrict__ o, int n4) {
    int i = blockIdx.x * blockDim.x + threadIdx.x;
    if (i >= n4) return;
    float4 v = x[i];
    o[i] = make_uint2(pack2h(v.x, v.y), pack2h(v.z, v.w));
}

// ---------------------------------------------------------------------------
// fp16 GEMM via mma.sync: out[M,N] = (Ahi[+Alo])[M,K] @ B[N,K]^T + bias
// MODE 0: fp32 out + bias, always 2 products.
// MODE 1: QKV. Q columns (blockIdx.x < 8): 2 products -> Q hi/lo.
//         K,V columns: single hi product -> K,V fp16 (their output is
//         rounded to fp16 anyway; error adds in quadrature).
// ---------------------------------------------------------------------------
#define GSTRIDE 40
#define MAT_BYTES (128 * GSTRIDE * 2)
#define STAGE_BYTES (3 * MAT_BYTES)     // Ahi, Alo, B
#define GK_SMEM (2 * STAGE_BYTES)       // 61440 B

template <int MODE>
__global__ __launch_bounds__(256, 2) void gemm_mma(
    const __half* __restrict__ Ahi, const __half* __restrict__ Alo,
    const __half* __restrict__ Bf,
    const float* __restrict__ bias, float* __restrict__ out,
    int M, int N, int K)
{
    extern __shared__ __align__(128) char dsm[];
    const uint32_t smb = smem_u32(dsm);

    const int tid  = threadIdx.x;
    const int wid  = tid >> 5;
    const int lane = tid & 31;
    const int wm = wid >> 2;
    const int wn = wid & 3;

    const size_t m0 = (size_t)blockIdx.y * 128;
    const size_t n0 = (size_t)blockIdx.x * 128;

    // lo-product needed? MODE 0 always; MODE 1 only for the Q section.
    const bool lo_prod = (MODE == 0) || (blockIdx.x < 8);

    const __half* srcs[3] = {Ahi + m0 * K, Alo + m0 * K, Bf + n0 * K};

    float acc[4][4][4];
#pragma unroll
    for (int i = 0; i < 4; i++)
#pragma unroll
        for (int j = 0; j < 4; j++)
#pragma unroll
            for (int k = 0; k < 4; k++) acc[i][j][k] = 0.f;

    auto load_stage = [&](int kt, int s) {
        const int k0 = kt * 32;
        const uint32_t sb = smb + s * STAGE_BYTES;
#pragma unroll
        for (int m = 0; m < 3; m++) {
            const __half* src = srcs[m];
#pragma unroll
            for (int i = 0; i < 2; i++) {
                int idx = tid + i * 256;
                int row = idx >> 2;
                int q   = idx & 3;
                cp16(sb + m * MAT_BYTES + (row * GSTRIDE + q * 8) * 2,
                     src + (size_t)row * K + k0 + q * 8);
            }
        }
        cp_commit();
    };

    const uint32_t a_row = (uint32_t)(wm * 64 + (lane & 15));
    const uint32_t a_kof = (uint32_t)(((lane >> 4) & 1) * 8);
    const uint32_t b_row = (uint32_t)(wn * 32 + (lane & 7) + ((lane >> 4) & 1) * 8);
    const uint32_t b_kof = (uint32_t)(((lane >> 3) & 1) * 8);

    const int NT = K >> 5;
    load_stage(0, 0);

    for (int kt = 0; kt < NT; kt++) {
        cp_wait0();
        __syncthreads();           // all warps done reading buffer (kt+1)&1
        if (kt + 1 < NT) load_stage(kt + 1, (kt + 1) & 1);

        const uint32_t sb = smb + (kt & 1) * STAGE_BYTES;
        const uint32_t sAhi = sb;
        const uint32_t sAlo = sb + MAT_BYTES;
        const uint32_t sB   = sb + 2 * MAT_BYTES;

#pragma unroll
        for (int ks = 0; ks < 2; ks++) {
            uint32_t bf[2][4];
#pragma unroll
            for (int nf2 = 0; nf2 < 2; nf2++) {
                uint32_t off = ((b_row + nf2 * 16) * GSTRIDE + ks * 16 + b_kof) * 2;
                ldsm4(bf[nf2], sB + off);
            }
            uint32_t ah[2][4], al[2][4];
            {
                uint32_t off0 = (a_row * GSTRIDE + ks * 16 + a_kof) * 2;
                ldsm4(ah[0], sAhi + off0);
                if (lo_prod) ldsm4(al[0], sAlo + off0);
            }
#pragma unroll
            for (int mf = 0; mf < 4; mf++) {
                const int cur = mf & 1, nxt = cur ^ 1;
                if (mf < 3) {
                    uint32_t offn = ((a_row + (mf + 1) * 16) * GSTRIDE + ks * 16 + a_kof) * 2;
                    ldsm4(ah[nxt], sAhi + offn);
                    if (lo_prod) ldsm4(al[nxt], sAlo + offn);
                }
#pragma unroll
                for (int nf = 0; nf < 4; nf++)
                    mma_f16(acc[mf][nf], ah[cur], &bf[nf >> 1][(nf & 1) * 2]);
                if (lo_prod) {
#pragma unroll
                    for (int nf = 0; nf < 4; nf++)
                        mma_f16(acc[mf][nf], al[cur], &bf[nf >> 1][(nf & 1) * 2]);
                }
            }
        }
    }

    const int r_in = lane >> 2;
    const int c_in = (lane & 3) * 2;

    if (MODE == 0) {
#pragma unroll
        for (int mf = 0; mf < 4; mf++) {
#pragma unroll
            for (int nf = 0; nf < 4; nf++) {
                size_t row = m0 + wm * 64 + mf * 16 + r_in;
                size_t col = n0 + wn * 32 + nf * 8 + c_in;
                float bx = bias[col], by = bias[col + 1];
                float2 o0 = make_float2(acc[mf][nf][0] + bx, acc[mf][nf][1] + by);
                float2 o1 = make_float2(acc[mf][nf][2] + bx, acc[mf][nf][3] + by);
                *(float2*)(out + row * N + col) = o0;
                *(float2*)(out + (row + 8) * N + col) = o1;
            }
        }
    } else {
#pragma unroll
        for (int mf = 0; mf < 4; mf++) {
#pragma unroll
            for (int nf = 0; nf < 4; nf++) {
                size_t col = n0 + wn * 32 + nf * 8 + c_in;
                int sec = (int)(col >> 10);      // 0=Q, 1=K, 2=V
                int h   = (int)((col >> 6) & 15);
                int d   = (int)(col & 63);
                float bx = bias[col], by = bias[col + 1];
#pragma unroll
                for (int half = 0; half < 2; half++) {
                    size_t row = m0 + wm * 64 + mf * 16 + r_in + half * 8;
                    int b = (int)(row >> 11);
                    int t = (int)(row & 2047);
                    size_t idx = (((size_t)(b * H_ + h) * T_ + t) * D_ + d);
                    float v0 = acc[mf][nf][half * 2 + 0] + bx;
                    float v1 = acc[mf][nf][half * 2 + 1] + by;
                    if (sec == 0) {
                        uint32_t hi, lo;
                        split2h(v0, v1, hi, lo);
                        *(uint32_t*)(g_qh + idx) = hi;
                        *(uint32_t*)(g_ql + idx) = lo;
                    } else if (sec == 1) {
                        *(uint32_t*)(g_k + idx) = pack2h(v0, v1);
                    } else {
                        *(uint32_t*)(g_v + idx) = pack2h(v0, v1);
                    }
                }
            }
        }
    }
}

// ---------------------------------------------------------------------------
// fp16 causal flash attention. S: Q hi/lo x K (2 products).
// PV: single-product fp16 P x V (P in [0,1]; rounding error ~2.4e-4,
// incoherent with the rest of the stack). Base-2 softmax, balanced q-pairs.
// ---------------------------------------------------------------------------
#define AST 72
#define QSZ (128 * AST)
#define KVSZ (128 * AST)
#define KVSTAGE (2 * KVSZ)             // K, V
#define A_SMEM ((2 * QSZ + 2 * KVSTAGE) * 2)   // 110592 B

__global__ __launch_bounds__(256) void attn_tc() {
    extern __shared__ __align__(128) __half sm[];
    const uint32_t smb = smem_u32(sm);
    const uint32_t sQhi = smb;
    const uint32_t sQlo = smb + QSZ * 2;
    const uint32_t sKV0 = smb + 2 * QSZ * 2;

    const int pair = blockIdx.x;
    const int h  = blockIdx.y;
    const int b  = blockIdx.z;
    const int tid  = threadIdx.x;
    const int wid  = tid >> 5;
    const int lane = tid & 31;
    const int bh = b * H_ + h;

    const __half* gk = g_k + (size_t)bh * T_ * D_;
    const __half* gv = g_v + (size_t)bh * T_ * D_;

    auto load_kv = [&](int kt, int s) {
        const uint32_t sb = sKV0 + s * KVSTAGE * 2;
        const __half* bases[2] = {gk + (size_t)kt * 128 * D_,
                                  gv + (size_t)kt * 128 * D_};
#pragma unroll
        for (int i = 0; i < 8; i++) {
            int idx = tid + i * 256;
            int arr = idx >> 10;
            int rem = idx & 1023;
            int row = rem >> 3;
            int ch  = rem & 7;
            cp16(sb + (arr * KVSZ + row * AST + ch * 8) * 2,
                 bases[arr] + (size_t)row * D_ + ch * 8);
        }
        cp_commit();
    };

    const uint32_t k_row = (uint32_t)((lane & 7) + ((lane >> 4) & 1) * 8);
    const uint32_t k_kof = ((lane >> 3) & 1) * 8;
    const uint32_t v_rof = (uint32_t)(lane & 15);
    const uint32_t v_cof = ((lane >> 4) & 1) * 8;

    const float SC2 = 0.125f * 1.44269504f;   // D^-0.5 * log2(e)

    auto process_qblock = [&](int qb) {
        const __half* gqh = g_qh + ((size_t)bh * T_ + qb * 128) * D_;
        const __half* gql = g_ql + ((size_t)bh * T_ + qb * 128) * D_;
#pragma unroll
        for (int i = 0; i < 8; i++) {
            int idx = tid + i * 256;
            int arr = idx >> 10;
            int rem = idx & 1023;
            int row = rem >> 3;
            int ch  = rem & 7;
            const __half* src = (arr ? gql : gqh) + (size_t)row * D_ + ch * 8;
            cp16((arr ? sQlo : sQhi) + (row * AST + ch * 8) * 2, src);
        }
        cp_commit();
        load_kv(0, 0);
        cp_wait0();
        __syncthreads();

        uint32_t qhF[4][4], qlF[4][4];
        {
            uint32_t rbase = (uint32_t)(wid * 16 + (lane & 15));
            uint32_t kof = ((lane >> 4) & 1) * 8;
#pragma unroll
            for (int ks = 0; ks < 4; ks++) {
                uint32_t off = (rbase * AST + ks * 16 + kof) * 2;
                ldsm4(qhF[ks], sQhi + off);
                ldsm4(qlF[ks], sQlo + off);
            }
        }

        float O[8][4];
#pragma unroll
        for (int i = 0; i < 8; i++)
#pragma unroll
            for (int j = 0; j < 4; j++) O[i][j] = 0.f;
        float mrow[2] = {-1e30f, -1e30f};
        float lrow[2] = {0.f, 0.f};

        for (int kt = 0; kt <= qb; kt++) {
            const bool more = (kt + 1 <= qb);
            if (more) load_kv(kt + 1, (kt + 1) & 1);
            if (more) cp_wait1(); else cp_wait0();
            __syncthreads();

            const uint32_t sb = sKV0 + (kt & 1) * KVSTAGE * 2;
            const uint32_t sK = sb;
            const uint32_t sV = sb + KVSZ * 2;

            // ---- S = Q K^T (Q hi/lo, 2 products) ---------------------------
            float S[16][4];
#pragma unroll
            for (int i = 0; i < 16; i++)
#pragma unroll
                for (int j = 0; j < 4; j++) S[i][j] = 0.f;

#pragma unroll
            for (int ks = 0; ks < 4; ks++) {
#pragma unroll
                for (int i2 = 0; i2 < 4; i2++) {
                    uint32_t kh4[2][4];
#pragma unroll
                    for (int ii = 0; ii < 2; ii++) {
                        uint32_t off = (((i2 * 2 + ii) * 16 + k_row) * AST
                                        + ks * 16 + k_kof) * 2;
                        ldsm4(kh4[ii], sK + off);
                    }
#pragma unroll
                    for (int ii = 0; ii < 2; ii++)
#pragma unroll
                        for (int half = 0; half < 2; half++)
                            mma_f16(S[(i2 * 2 + ii) * 2 + half], qhF[ks],
                                    &kh4[ii][half * 2]);
#pragma unroll
                    for (int ii = 0; ii < 2; ii++)
#pragma unroll
                        for (int half = 0; half < 2; half++)
                            mma_f16(S[(i2 * 2 + ii) * 2 + half], qlF[ks],
                                    &kh4[ii][half * 2]);
                }
            }

            // ---- scale (base-2) + causal mask ------------------------------
#pragma unroll
            for (int i = 0; i < 16; i++)
#pragma unroll
                for (int j = 0; j < 4; j++) S[i][j] *= SC2;

            if (kt == qb) {
                const int r0 = wid * 16 + (lane >> 2);
#pragma unroll
                for (int nf = 0; nf < 16; nf++) {
                    int col = nf * 8 + (lane & 3) * 2;
                    if (col > r0)      S[nf][0] = -1e30f;
                    if (col + 1 > r0)  S[nf][1] = -1e30f;
                    if (col > r0 + 8)     S[nf][2] = -1e30f;
                    if (col + 1 > r0 + 8) S[nf][3] = -1e30f;
                }
            }

            // ---- online softmax (base-2, in-warp) --------------------------
            float rm0 = -1e30f, rm1 = -1e30f;
#pragma unroll
            for (int nf = 0; nf < 16; nf++) {
                rm0 = fmaxf(rm0, fmaxf(S[nf][0], S[nf][1]));
                rm1 = fmaxf(rm1, fmaxf(S[nf][2], S[nf][3]));
            }
            rm0 = fmaxf(rm0, __shfl_xor_sync(0xffffffffu, rm0, 1));
            rm0 = fmaxf(rm0, __shfl_xor_sync(0xffffffffu, rm0, 2));
            rm1 = fmaxf(rm1, __shfl_xor_sync(0xffffffffu, rm1, 1));
            rm1 = fmaxf(rm1, __shfl_xor_sync(0xffffffffu, rm1, 2));

            float mn0 = fmaxf(mrow[0], rm0);
            float mn1 = fmaxf(mrow[1], rm1);
            float a0 = exp2f(mrow[0] - mn0);
            float a1 = exp2f(mrow[1] - mn1);
            mrow[0] = mn0; mrow[1] = mn1;

            float rs0 = 0.f, rs1 = 0.f;
#pragma unroll
            for (int nf = 0; nf < 16; nf++) {
                S[nf][0] = exp2f(S[nf][0] - mn0);
                S[nf][1] = exp2f(S[nf][1] - mn0);
                S[nf][2] = exp2f(S[nf][2] - mn1);
                S[nf][3] = exp2f(S[nf][3] - mn1);
                rs0 += S[nf][0] + S[nf][1];
                rs1 += S[nf][2] + S[nf][3];
            }
            rs0 += __shfl_xor_sync(0xffffffffu, rs0, 1);
            rs0 += __shfl_xor_sync(0xffffffffu, rs0, 2);
            rs1 += __shfl_xor_sync(0xffffffffu, rs1, 1);
            rs1 += __shfl_xor_sync(0xffffffffu, rs1, 2);
            lrow[0] = lrow[0] * a0 + rs0;
            lrow[1] = lrow[1] * a1 + rs1;

#pragma unroll
            for (int nf = 0; nf < 8; nf++) {
                O[nf][0] *= a0; O[nf][1] *= a0;
                O[nf][2] *= a1; O[nf][3] *= a1;
            }

            // ---- O += P V (single-product fp16 P; preload V frags) ---------
#pragma unroll
            for (int ks2 = 0; ks2 < 8; ks2++) {
                uint32_t pf[4];
                pf[0] = pack2h(S[2 * ks2][0],     S[2 * ks2][1]);
                pf[1] = pack2h(S[2 * ks2][2],     S[2 * ks2][3]);
                pf[2] = pack2h(S[2 * ks2 + 1][0], S[2 * ks2 + 1][1]);
                pf[3] = pack2h(S[2 * ks2 + 1][2], S[2 * ks2 + 1][3]);

                uint32_t vf[4][4];
#pragma unroll
                for (int i = 0; i < 4; i++) {
                    uint32_t off = ((ks2 * 16 + v_rof) * AST + i * 16 + v_cof) * 2;
                    ldsm4t(vf[i], sV + off);
                }
#pragma unroll
                for (int i = 0; i < 4; i++)
#pragma unroll
                    for (int half = 0; half < 2; half++)
                        mma_f16(O[i * 2 + half], pf, &vf[i][half * 2]);
            }
            __syncthreads();
        }

        const float inv0 = 1.f / lrow[0];
        const float inv1 = 1.f / lrow[1];
        const size_t row0 = (size_t)b * T_ + qb * 128 + wid * 16 + (lane >> 2);
#pragma unroll
        for (int nf = 0; nf < 8; nf++) {
            int col = h * 64 + nf * 8 + (lane & 3) * 2;
            uint32_t hi, lo;
            split2h(O[nf][0] * inv0, O[nf][1] * inv0, hi, lo);
            *(uint32_t*)(g_oh + row0 * C_ + col) = hi;
            *(uint32_t*)(g_ol + row0 * C_ + col) = lo;
            split2h(O[nf][2] * inv1, O[nf][3] * inv1, hi, lo);
            *(uint32_t*)(g_oh + (row0 + 8) * C_ + col) = hi;
            *(uint32_t*)(g_ol + (row0 + 8) * C_ + col) = lo;
        }
    };

    process_qblock(pair);
    __syncthreads();
    process_qblock(NQB - 1 - pair);
}

// ---------------------------------------------------------------------------
extern "C" void kernel_launch(void* const* d_in, const int* in_sizes, int n_in,
                              void* d_out, int out_size) {
    const float* hidden = (const float*)d_in[0];
    const float* W_qkv  = (const float*)d_in[2];
    const float* b_qkv  = (const float*)d_in[3];
    const float* W_o    = (const float*)d_in[4];
    const float* b_o    = (const float*)d_in[5];
    float* out = (float*)d_out;

    __half *xhi, *xlo, *wq, *wo, *oh, *ol;
    cudaGetSymbolAddress((void**)&xhi, g_xhi);
    cudaGetSymbolAddress((void**)&xlo, g_xlo);
    cudaGetSymbolAddress((void**)&wq, g_wq);
    cudaGetSymbolAddress((void**)&wo, g_wo);
    cudaGetSymbolAddress((void**)&oh, g_oh);
    cudaGetSymbolAddress((void**)&ol, g_ol);

    cudaFuncSetAttribute(gemm_mma<0>, cudaFuncAttributeMaxDynamicSharedMemorySize, GK_SMEM);
    cudaFuncSetAttribute(gemm_mma<1>, cudaFuncAttributeMaxDynamicSharedMemorySize, GK_SMEM);
    cudaFuncSetAttribute(attn_tc, cudaFuncAttributeMaxDynamicSharedMemorySize, A_SMEM);

    {
        int n4 = (M_ * C_) / 4;
        cvt_hilo_h<<<(n4 + 255) / 256, 256>>>((const float4*)hidden,
                                              (uint2*)xhi, (uint2*)xlo, n4);
        n4 = (C3_ * C_) / 4;
        cvt_h<<<(n4 + 255) / 256, 256>>>((const float4*)W_qkv, (uint2*)wq, n4);
        n4 = (C_ * C_) / 4;
        cvt_h<<<(n4 + 255) / 256, 256>>>((const float4*)W_o, (uint2*)wo, n4);
    }

    // 1) QKV projection (Q: 2-product; K,V: 1-product)
    {
        dim3 grid(C3_ / 128, M_ / 128);
        gemm_mma<1><<<grid, 256, GK_SMEM>>>(xhi, xlo, wq, b_qkv, nullptr, M_, C3_, C_);
    }
    // 2) flash attention
    {
        dim3 grid(NQB / 2, H_, B_);
        attn_tc<<<grid, 256, A_SMEM>>>();
    }
    // 3) out = O @ W_o^T + b_o (2-product)
    {
        dim3 grid(C_ / 128, M_ / 128);
        gemm_mma<0><<<grid, 256, GK_SMEM>>>(oh, ol, wo, b_o, out, M_, C_, C_);
    }
}

// round 13
// speedup vs baseline: 1.5842x; 1.0486x over previous
#include <cuda_runtime.h>
#include <cuda_fp16.h>
#include <cstdint>

#define B_ 4
#define T_ 2048
#define C_ 1024
#define H_ 16
#define D_ 64
#define C3_ (3 * C_)
#define M_ (B_ * T_)   // 8192
#define NQB (T_ / 128) // 16 q-blocks per (b,h)

// ---------------- scratch (device globals; no runtime alloc) ----------------
__device__ __half g_xhi[(size_t)M_ * C_],  g_xlo[(size_t)M_ * C_];
__device__ __half g_wq[(size_t)C3_ * C_];            // W_qkv fp16
__device__ __half g_wo[(size_t)C_ * C_];             // W_o   fp16
__device__ __half g_qh[(size_t)M_ * C_], g_ql[(size_t)M_ * C_];  // Q hi/lo [B,H,T,D]
__device__ __half g_k[(size_t)M_ * C_];              // K fp16 [B,H,T,D]
__device__ __half g_v[(size_t)M_ * C_];              // V fp16 [B,H,T,D]
__device__ __half g_oh[(size_t)M_ * C_], g_ol[(size_t)M_ * C_];  // attn out hi/lo

// ---------------------------- helpers ---------------------------------------
__device__ __forceinline__ uint32_t smem_u32(const void* p) {
    uint32_t a;
    asm("{ .reg .u64 t; cvta.to.shared.u64 t, %1; cvt.u32.u64 %0, t; }"
        : "=r"(a) : "l"(p));
    return a;
}
__device__ __forceinline__ void cp16(uint32_t dst, const void* src) {
    asm volatile("cp.async.cg.shared.global [%0], [%1], 16;" :: "r"(dst), "l"(src));
}
__device__ __forceinline__ void cp_commit() {
    asm volatile("cp.async.commit_group;" ::: "memory");
}
__device__ __forceinline__ void cp_wait0() {
    asm volatile("cp.async.wait_group 0;" ::: "memory");
}
__device__ __forceinline__ void cp_wait1() {
    asm volatile("cp.async.wait_group 1;" ::: "memory");
}
__device__ __forceinline__ void ldsm4(uint32_t* r, uint32_t addr) {
    asm volatile("ldmatrix.sync.aligned.m8n8.x4.shared.b16 {%0,%1,%2,%3}, [%4];"
                 : "=r"(r[0]), "=r"(r[1]), "=r"(r[2]), "=r"(r[3]) : "r"(addr));
}
__device__ __forceinline__ void ldsm4t(uint32_t* r, uint32_t addr) {
    asm volatile("ldmatrix.sync.aligned.m8n8.x4.trans.shared.b16 {%0,%1,%2,%3}, [%4];"
                 : "=r"(r[0]), "=r"(r[1]), "=r"(r[2]), "=r"(r[3]) : "r"(addr));
}
__device__ __forceinline__ void mma_f16(float* c, const uint32_t* a, const uint32_t* b) {
    asm volatile(
        "mma.sync.aligned.m16n8k16.row.col.f32.f16.f16.f32 "
        "{%0,%1,%2,%3}, {%4,%5,%6,%7}, {%8,%9}, {%0,%1,%2,%3};"
        : "+f"(c[0]), "+f"(c[1]), "+f"(c[2]), "+f"(c[3])
        : "r"(a[0]), "r"(a[1]), "r"(a[2]), "r"(a[3]), "r"(b[0]), "r"(b[1]));
}
__device__ __forceinline__ void split2h(float a, float b, uint32_t& hi, uint32_t& lo) {
    __half2 h = __floats2half2_rn(a, b);
    float2 f = __half22float2(h);
    __half2 l = __floats2half2_rn(a - f.x, b - f.y);
    hi = *reinterpret_cast<uint32_t*>(&h);
    lo = *reinterpret_cast<uint32_t*>(&l);
}
__device__ __forceinline__ uint32_t pack2h(float a, float b) {
    __half2 h = __floats2half2_rn(a, b);
    return *reinterpret_cast<uint32_t*>(&h);
}

// ---------------------------------------------------------------------------
__global__ void cvt_hilo_h(const float4* __restrict__ x, uint2* __restrict__ hi,
                           uint2* __restrict__ lo, int n4) {
    int i = blockIdx.x * blockDim.x + threadIdx.x;
    if (i >= n4) return;
    float4 v = x[i];
    uint32_t h0, l0, h1, l1;
    split2h(v.x, v.y, h0, l0);
    split2h(v.z, v.w, h1, l1);
    hi[i] = make_uint2(h0, h1);
    lo[i] = make_uint2(l0, l1);
}
__global__ void cvt_h(const float4* __restrict__ x, uint2* __restrict__ o, int n4) {
    int i = blockIdx.x * blockDim.x + threadIdx.x;
    if (i >= n4) return;
    float4 v = x[i];
    o[i] = make_uint2(pack2h(v.x, v.y), pack2h(v.z, v.w));
}

// ---------------------------------------------------------------------------
// fp16 GEMM via mma.sync, 3-STAGE cp.async pipeline (two loads always in
// flight -> hides L2 latency that bound the 2-stage version).
// MODE 0: fp32 out + bias, 2 products. MODE 1: QKV; Q blocks 2-product,
// K/V blocks 1-product AND skip the Alo smem loads entirely.
// ---------------------------------------------------------------------------
#define GSTRIDE 40
#define MAT_BYTES (128 * GSTRIDE * 2)
#define STAGE_BYTES (3 * MAT_BYTES)     // Ahi, Alo, B
#define NSTAGE 3
#define GK_SMEM (NSTAGE * STAGE_BYTES)  // 92160 B -> 2 CTAs/SM

template <int MODE>
__global__ __launch_bounds__(256, 2) void gemm_mma(
    const __half* __restrict__ Ahi, const __half* __restrict__ Alo,
    const __half* __restrict__ Bf,
    const float* __restrict__ bias, float* __restrict__ out,
    int M, int N, int K)
{
    extern __shared__ __align__(128) char dsm[];
    const uint32_t smb = smem_u32(dsm);

    const int tid  = threadIdx.x;
    const int wid  = tid >> 5;
    const int lane = tid & 31;
    const int wm = wid >> 2;
    const int wn = wid & 3;

    const size_t m0 = (size_t)blockIdx.y * 128;
    const size_t n0 = (size_t)blockIdx.x * 128;

    // lo-product needed? MODE 0 always; MODE 1 only for the Q section.
    const bool lo_prod = (MODE == 0) || (blockIdx.x < 8);

    const __half* srcs[3] = {Ahi + m0 * K, Alo + m0 * K, Bf + n0 * K};

    float acc[4][4][4];
#pragma unroll
    for (int i = 0; i < 4; i++)
#pragma unroll
        for (int j = 0; j < 4; j++)
#pragma unroll
            for (int k = 0; k < 4; k++) acc[i][j][k] = 0.f;

    auto load_stage = [&](int kt, int s) {
        const int k0 = kt * 32;
        const uint32_t sb = smb + s * STAGE_BYTES;
#pragma unroll
        for (int m = 0; m < 3; m++) {
            if (m == 1 && !lo_prod) continue;   // K/V blocks never read Alo
            const __half* src = srcs[m];
#pragma unroll
            for (int i = 0; i < 2; i++) {
                int idx = tid + i * 256;
                int row = idx >> 2;
                int q   = idx & 3;
                cp16(sb + m * MAT_BYTES + (row * GSTRIDE + q * 8) * 2,
                     src + (size_t)row * K + k0 + q * 8);
            }
        }
        cp_commit();
    };

    const uint32_t a_row = (uint32_t)(wm * 64 + (lane & 15));
    const uint32_t a_kof = (uint32_t)(((lane >> 4) & 1) * 8);
    const uint32_t b_row = (uint32_t)(wn * 32 + (lane & 7) + ((lane >> 4) & 1) * 8);
    const uint32_t b_kof = (uint32_t)(((lane >> 3) & 1) * 8);

    const int NT = K >> 5;                 // 32 chunks
    load_stage(0, 0);
    load_stage(1, 1);

    for (int kt = 0; kt < NT; kt++) {
        // stage kt ready when at most (committed-after-kt) groups outstanding
        if (kt + 1 < NT) cp_wait1(); else cp_wait0();
        __syncthreads();     // all warps done reading buffer (kt+2)%NSTAGE (chunk kt-1)
        if (kt + 2 < NT) load_stage(kt + 2, (kt + 2) % NSTAGE);

        const uint32_t sb = smb + (kt % NSTAGE) * STAGE_BYTES;
        const uint32_t sAhi = sb;
        const uint32_t sAlo = sb + MAT_BYTES;
        const uint32_t sB   = sb + 2 * MAT_BYTES;

#pragma unroll
        for (int ks = 0; ks < 2; ks++) {
            uint32_t bf[2][4];
#pragma unroll
            for (int nf2 = 0; nf2 < 2; nf2++) {
                uint32_t off = ((b_row + nf2 * 16) * GSTRIDE + ks * 16 + b_kof) * 2;
                ldsm4(bf[nf2], sB + off);
            }
            uint32_t ah[2][4], al[2][4];
            {
                uint32_t off0 = (a_row * GSTRIDE + ks * 16 + a_kof) * 2;
                ldsm4(ah[0], sAhi + off0);
                if (lo_prod) ldsm4(al[0], sAlo + off0);
            }
#pragma unroll
            for (int mf = 0; mf < 4; mf++) {
                const int cur = mf & 1, nxt = cur ^ 1;
                if (mf < 3) {
                    uint32_t offn = ((a_row + (mf + 1) * 16) * GSTRIDE + ks * 16 + a_kof) * 2;
                    ldsm4(ah[nxt], sAhi + offn);
                    if (lo_prod) ldsm4(al[nxt], sAlo + offn);
                }
#pragma unroll
                for (int nf = 0; nf < 4; nf++)
                    mma_f16(acc[mf][nf], ah[cur], &bf[nf >> 1][(nf & 1) * 2]);
                if (lo_prod) {
#pragma unroll
                    for (int nf = 0; nf < 4; nf++)
                        mma_f16(acc[mf][nf], al[cur], &bf[nf >> 1][(nf & 1) * 2]);
                }
            }
        }
    }

    const int r_in = lane >> 2;
    const int c_in = (lane & 3) * 2;

    if (MODE == 0) {
#pragma unroll
        for (int mf = 0; mf < 4; mf++) {
#pragma unroll
            for (int nf = 0; nf < 4; nf++) {
                size_t row = m0 + wm * 64 + mf * 16 + r_in;
                size_t col = n0 + wn * 32 + nf * 8 + c_in;
                float bx = bias[col], by = bias[col + 1];
                float2 o0 = make_float2(acc[mf][nf][0] + bx, acc[mf][nf][1] + by);
                float2 o1 = make_float2(acc[mf][nf][2] + bx, acc[mf][nf][3] + by);
                *(float2*)(out + row * N + col) = o0;
                *(float2*)(out + (row + 8) * N + col) = o1;
            }
        }
    } else {
#pragma unroll
        for (int mf = 0; mf < 4; mf++) {
#pragma unroll
            for (int nf = 0; nf < 4; nf++) {
                size_t col = n0 + wn * 32 + nf * 8 + c_in;
                int sec = (int)(col >> 10);      // 0=Q, 1=K, 2=V
                int h   = (int)((col >> 6) & 15);
                int d   = (int)(col & 63);
                float bx = bias[col], by = bias[col + 1];
#pragma unroll
                for (int half = 0; half < 2; half++) {
                    size_t row = m0 + wm * 64 + mf * 16 + r_in + half * 8;
                    int b = (int)(row >> 11);
                    int t = (int)(row & 2047);
                    size_t idx = (((size_t)(b * H_ + h) * T_ + t) * D_ + d);
                    float v0 = acc[mf][nf][half * 2 + 0] + bx;
                    float v1 = acc[mf][nf][half * 2 + 1] + by;
                    if (sec == 0) {
                        uint32_t hi, lo;
                        split2h(v0, v1, hi, lo);
                        *(uint32_t*)(g_qh + idx) = hi;
                        *(uint32_t*)(g_ql + idx) = lo;
                    } else if (sec == 1) {
                        *(uint32_t*)(g_k + idx) = pack2h(v0, v1);
                    } else {
                        *(uint32_t*)(g_v + idx) = pack2h(v0, v1);
                    }
                }
            }
        }
    }
}

// ---------------------------------------------------------------------------
// fp16 causal flash attention (unchanged from R12 — proven).
// S: Q hi/lo x K (2 products). PV: single-product fp16 P x V.
// Base-2 softmax, balanced q-pairs.
// ---------------------------------------------------------------------------
#define AST 72
#define QSZ (128 * AST)
#define KVSZ (128 * AST)
#define KVSTAGE (2 * KVSZ)             // K, V
#define A_SMEM ((2 * QSZ + 2 * KVSTAGE) * 2)   // 110592 B

__global__ __launch_bounds__(256) void attn_tc() {
    extern __shared__ __align__(128) __half sm[];
    const uint32_t smb = smem_u32(sm);
    const uint32_t sQhi = smb;
    const uint32_t sQlo = smb + QSZ * 2;
    const uint32_t sKV0 = smb + 2 * QSZ * 2;

    const int pair = blockIdx.x;
    const int h  = blockIdx.y;
    const int b  = blockIdx.z;
    const int tid  = threadIdx.x;
    const int wid  = tid >> 5;
    const int lane = tid & 31;
    const int bh = b * H_ + h;

    const __half* gk = g_k + (size_t)bh * T_ * D_;
    const __half* gv = g_v + (size_t)bh * T_ * D_;

    auto load_kv = [&](int kt, int s) {
        const uint32_t sb = sKV0 + s * KVSTAGE * 2;
        const __half* bases[2] = {gk + (size_t)kt * 128 * D_,
                                  gv + (size_t)kt * 128 * D_};
#pragma unroll
        for (int i = 0; i < 8; i++) {
            int idx = tid + i * 256;
            int arr = idx >> 10;
            int rem = idx & 1023;
            int row = rem >> 3;
            int ch  = rem & 7;
            cp16(sb + (arr * KVSZ + row * AST + ch * 8) * 2,
                 bases[arr] + (size_t)row * D_ + ch * 8);
        }
        cp_commit();
    };

    const uint32_t k_row = (uint32_t)((lane & 7) + ((lane >> 4) & 1) * 8);
    const uint32_t k_kof = ((lane >> 3) & 1) * 8;
    const uint32_t v_rof = (uint32_t)(lane & 15);
    const uint32_t v_cof = ((lane >> 4) & 1) * 8;

    const float SC2 = 0.125f * 1.44269504f;   // D^-0.5 * log2(e)

    auto process_qblock = [&](int qb) {
        const __half* gqh = g_qh + ((size_t)bh * T_ + qb * 128) * D_;
        const __half* gql = g_ql + ((size_t)bh * T_ + qb * 128) * D_;
#pragma unroll
        for (int i = 0; i < 8; i++) {
            int idx = tid + i * 256;
            int arr = idx >> 10;
            int rem = idx & 1023;
            int row = rem >> 3;
            int ch  = rem & 7;
            const __half* src = (arr ? gql : gqh) + (size_t)row * D_ + ch * 8;
            cp16((arr ? sQlo : sQhi) + (row * AST + ch * 8) * 2, src);
        }
        cp_commit();
        load_kv(0, 0);
        cp_wait0();
        __syncthreads();

        uint32_t qhF[4][4], qlF[4][4];
        {
            uint32_t rbase = (uint32_t)(wid * 16 + (lane & 15));
            uint32_t kof = ((lane >> 4) & 1) * 8;
#pragma unroll
            for (int ks = 0; ks < 4; ks++) {
                uint32_t off = (rbase * AST + ks * 16 + kof) * 2;
                ldsm4(qhF[ks], sQhi + off);
                ldsm4(qlF[ks], sQlo + off);
            }
        }

        float O[8][4];
#pragma unroll
        for (int i = 0; i < 8; i++)
#pragma unroll
            for (int j = 0; j < 4; j++) O[i][j] = 0.f;
        float mrow[2] = {-1e30f, -1e30f};
        float lrow[2] = {0.f, 0.f};

        for (int kt = 0; kt <= qb; kt++) {
            const bool more = (kt + 1 <= qb);
            if (more) load_kv(kt + 1, (kt + 1) & 1);
            if (more) cp_wait1(); else cp_wait0();
            __syncthreads();

            const uint32_t sb = sKV0 + (kt & 1) * KVSTAGE * 2;
            const uint32_t sK = sb;
            const uint32_t sV = sb + KVSZ * 2;

            // ---- S = Q K^T (Q hi/lo, 2 products) ---------------------------
            float S[16][4];
#pragma unroll
            for (int i = 0; i < 16; i++)
#pragma unroll
                for (int j = 0; j < 4; j++) S[i][j] = 0.f;

#pragma unroll
            for (int ks = 0; ks < 4; ks++) {
#pragma unroll
                for (int i2 = 0; i2 < 4; i2++) {
                    uint32_t kh4[2][4];
#pragma unroll
                    for (int ii = 0; ii < 2; ii++) {
                        uint32_t off = (((i2 * 2 + ii) * 16 + k_row) * AST
                                        + ks * 16 + k_kof) * 2;
                        ldsm4(kh4[ii], sK + off);
                    }
#pragma unroll
                    for (int ii = 0; ii < 2; ii++)
#pragma unroll
                        for (int half = 0; half < 2; half++)
                            mma_f16(S[(i2 * 2 + ii) * 2 + half], qhF[ks],
                                    &kh4[ii][half * 2]);
#pragma unroll
                    for (int ii = 0; ii < 2; ii++)
#pragma unroll
                        for (int half = 0; half < 2; half++)
                            mma_f16(S[(i2 * 2 + ii) * 2 + half], qlF[ks],
                                    &kh4[ii][half * 2]);
                }
            }

            // ---- scale (base-2) + causal mask ------------------------------
#pragma unroll
            for (int i = 0; i < 16; i++)
#pragma unroll
                for (int j = 0; j < 4; j++) S[i][j] *= SC2;

            if (kt == qb) {
                const int r0 = wid * 16 + (lane >> 2);
#pragma unroll
                for (int nf = 0; nf < 16; nf++) {
                    int col = nf * 8 + (lane & 3) * 2;
                    if (col > r0)      S[nf][0] = -1e30f;
                    if (col + 1 > r0)  S[nf][1] = -1e30f;
                    if (col > r0 + 8)     S[nf][2] = -1e30f;
                    if (col + 1 > r0 + 8) S[nf][3] = -1e30f;
                }
            }

            // ---- online softmax (base-2, in-warp) --------------------------
            float rm0 = -1e30f, rm1 = -1e30f;
#pragma unroll
            for (int nf = 0; nf < 16; nf++) {
                rm0 = fmaxf(rm0, fmaxf(S[nf][0], S[nf][1]));
                rm1 = fmaxf(rm1, fmaxf(S[nf][2], S[nf][3]));
            }
            rm0 = fmaxf(rm0, __shfl_xor_sync(0xffffffffu, rm0, 1));
            rm0 = fmaxf(rm0, __shfl_xor_sync(0xffffffffu, rm0, 2));
            rm1 = fmaxf(rm1, __shfl_xor_sync(0xffffffffu, rm1, 1));
            rm1 = fmaxf(rm1, __shfl_xor_sync(0xffffffffu, rm1, 2));

            float mn0 = fmaxf(mrow[0], rm0);
            float mn1 = fmaxf(mrow[1], rm1);
            float a0 = exp2f(mrow[0] - mn0);
            float a1 = exp2f(mrow[1] - mn1);
            mrow[0] = mn0; mrow[1] = mn1;

            float rs0 = 0.f, rs1 = 0.f;
#pragma unroll
            for (int nf = 0; nf < 16; nf++) {
                S[nf][0] = exp2f(S[nf][0] - mn0);
                S[nf][1] = exp2f(S[nf][1] - mn0);
                S[nf][2] = exp2f(S[nf][2] - mn1);
                S[nf][3] = exp2f(S[nf][3] - mn1);
                rs0 += S[nf][0] + S[nf][1];
                rs1 += S[nf][2] + S[nf][3];
            }
            rs0 += __shfl_xor_sync(0xffffffffu, rs0, 1);
            rs0 += __shfl_xor_sync(0xffffffffu, rs0, 2);
            rs1 += __shfl_xor_sync(0xffffffffu, rs1, 1);
            rs1 += __shfl_xor_sync(0xffffffffu, rs1, 2);
            lrow[0] = lrow[0] * a0 + rs0;
            lrow[1] = lrow[1] * a1 + rs1;

#pragma unroll
            for (int nf = 0; nf < 8; nf++) {
                O[nf][0] *= a0; O[nf][1] *= a0;
                O[nf][2] *= a1; O[nf][3] *= a1;
            }

            // ---- O += P V (single-product fp16 P; preload V frags) ---------
#pragma unroll
            for (int ks2 = 0; ks2 < 8; ks2++) {
                uint32_t pf[4];
                pf[0] = pack2h(S[2 * ks2][0],     S[2 * ks2][1]);
                pf[1] = pack2h(S[2 * ks2][2],     S[2 * ks2][3]);
                pf[2] = pack2h(S[2 * ks2 + 1][0], S[2 * ks2 + 1][1]);
                pf[3] = pack2h(S[2 * ks2 + 1][2], S[2 * ks2 + 1][3]);

                uint32_t vf[4][4];
#pragma unroll
                for (int i = 0; i < 4; i++) {
                    uint32_t off = ((ks2 * 16 + v_rof) * AST + i * 16 + v_cof) * 2;
                    ldsm4t(vf[i], sV + off);
                }
#pragma unroll
                for (int i = 0; i < 4; i++)
#pragma unroll
                    for (int half = 0; half < 2; half++)
                        mma_f16(O[i * 2 + half], pf, &vf[i][half * 2]);
            }
            __syncthreads();
        }

        const float inv0 = 1.f / lrow[0];
        const float inv1 = 1.f / lrow[1];
        const size_t row0 = (size_t)b * T_ + qb * 128 + wid * 16 + (lane >> 2);
#pragma unroll
        for (int nf = 0; nf < 8; nf++) {
            int col = h * 64 + nf * 8 + (lane & 3) * 2;
            uint32_t hi, lo;
            split2h(O[nf][0] * inv0, O[nf][1] * inv0, hi, lo);
            *(uint32_t*)(g_oh + row0 * C_ + col) = hi;
            *(uint32_t*)(g_ol + row0 * C_ + col) = lo;
            split2h(O[nf][2] * inv1, O[nf][3] * inv1, hi, lo);
            *(uint32_t*)(g_oh + (row0 + 8) * C_ + col) = hi;
            *(uint32_t*)(g_ol + (row0 + 8) * C_ + col) = lo;
        }
    };

    process_qblock(pair);
    __syncthreads();
    process_qblock(NQB - 1 - pair);
}

// ---------------------------------------------------------------------------
extern "C" void kernel_launch(void* const* d_in, const int* in_sizes, int n_in,
                              void* d_out, int out_size) {
    const float* hidden = (const float*)d_in[0];
    const float* W_qkv  = (const float*)d_in[2];
    const float* b_qkv  = (const float*)d_in[3];
    const float* W_o    = (const float*)d_in[4];
    const float* b_o    = (const float*)d_in[5];
    float* out = (float*)d_out;

    __half *xhi, *xlo, *wq, *wo, *oh, *ol;
    cudaGetSymbolAddress((void**)&xhi, g_xhi);
    cudaGetSymbolAddress((void**)&xlo, g_xlo);
    cudaGetSymbolAddress((void**)&wq, g_wq);
    cudaGetSymbolAddress((void**)&wo, g_wo);
    cudaGetSymbolAddress((void**)&oh, g_oh);
    cudaGetSymbolAddress((void**)&ol, g_ol);

    cudaFuncSetAttribute(gemm_mma<0>, cudaFuncAttributeMaxDynamicSharedMemorySize, GK_SMEM);
    cudaFuncSetAttribute(gemm_mma<1>, cudaFuncAttributeMaxDynamicSharedMemorySize, GK_SMEM);
    cudaFuncSetAttribute(attn_tc, cudaFuncAttributeMaxDynamicSharedMemorySize, A_SMEM);

    {
        int n4 = (M_ * C_) / 4;
        cvt_hilo_h<<<(n4 + 255) / 256, 256>>>((const float4*)hidden,
                                              (uint2*)xhi, (uint2*)xlo, n4);
        n4 = (C3_ * C_) / 4;
        cvt_h<<<(n4 + 255) / 256, 256>>>((const float4*)W_qkv, (uint2*)wq, n4);
        n4 = (C_ * C_) / 4;
        cvt_h<<<(n4 + 255) / 256, 256>>>((const float4*)W_o, (uint2*)wo, n4);
    }

    // 1) QKV projection (Q: 2-product; K,V: 1-product)
    {
        dim3 grid(C3_ / 128, M_ / 128);
        gemm_mma<1><<<grid, 256, GK_SMEM>>>(xhi, xlo, wq, b_qkv, nullptr, M_, C3_, C_);
    }
    // 2) flash attention
    {
        dim3 grid(NQB / 2, H_, B_);
        attn_tc<<<grid, 256, A_SMEM>>>();
    }
    // 3) out = O @ W_o^T + b_o (2-product)
    {
        dim3 grid(C_ / 128, M_ / 128);
        gemm_mma<0><<<grid, 256, GK_SMEM>>>(oh, ol, wo, b_o, out, M_, C_, C_);
    }
}

// round 14
// speedup vs baseline: 2.2092x; 1.3945x over previous
#include <cuda_runtime.h>
#include <cuda_fp16.h>
#include <cstdint>

#define B_ 4
#define T_ 2048
#define C_ 1024
#define H_ 16
#define D_ 64
#define C3_ (3 * C_)
#define M_ (B_ * T_)   // 8192
#define NQB (T_ / 128) // 16 q-blocks per (b,h)

// ---------------- scratch (device globals; no runtime alloc) ----------------
__device__ __half g_x[(size_t)M_ * C_];              // hidden fp16
__device__ __half g_wq[(size_t)C3_ * C_];            // W_qkv fp16
__device__ __half g_wo[(size_t)C_ * C_];             // W_o   fp16
__device__ __half g_q[(size_t)M_ * C_];              // Q fp16 [B,H,T,D]
__device__ __half g_k[(size_t)M_ * C_];              // K fp16 [B,H,T,D]
__device__ __half g_v[(size_t)M_ * C_];              // V fp16 [B,H,T,D]
__device__ __half g_o[(size_t)M_ * C_];              // attn out fp16 [M,C]

// ---------------------------- helpers ---------------------------------------
__device__ __forceinline__ uint32_t smem_u32(const void* p) {
    uint32_t a;
    asm("{ .reg .u64 t; cvta.to.shared.u64 t, %1; cvt.u32.u64 %0, t; }"
        : "=r"(a) : "l"(p));
    return a;
}
__device__ __forceinline__ void cp16(uint32_t dst, const void* src) {
    asm volatile("cp.async.cg.shared.global [%0], [%1], 16;" :: "r"(dst), "l"(src));
}
__device__ __forceinline__ void cp_commit() {
    asm volatile("cp.async.commit_group;" ::: "memory");
}
__device__ __forceinline__ void cp_wait0() {
    asm volatile("cp.async.wait_group 0;" ::: "memory");
}
__device__ __forceinline__ void cp_wait1() {
    asm volatile("cp.async.wait_group 1;" ::: "memory");
}
__device__ __forceinline__ void cp_wait2() {
    asm volatile("cp.async.wait_group 2;" ::: "memory");
}
__device__ __forceinline__ void ldsm4(uint32_t* r, uint32_t addr) {
    asm volatile("ldmatrix.sync.aligned.m8n8.x4.shared.b16 {%0,%1,%2,%3}, [%4];"
                 : "=r"(r[0]), "=r"(r[1]), "=r"(r[2]), "=r"(r[3]) : "r"(addr));
}
__device__ __forceinline__ void ldsm4t(uint32_t* r, uint32_t addr) {
    asm volatile("ldmatrix.sync.aligned.m8n8.x4.trans.shared.b16 {%0,%1,%2,%3}, [%4];"
                 : "=r"(r[0]), "=r"(r[1]), "=r"(r[2]), "=r"(r[3]) : "r"(addr));
}
__device__ __forceinline__ void mma_f16(float* c, const uint32_t* a, const uint32_t* b) {
    asm volatile(
        "mma.sync.aligned.m16n8k16.row.col.f32.f16.f16.f32 "
        "{%0,%1,%2,%3}, {%4,%5,%6,%7}, {%8,%9}, {%0,%1,%2,%3};"
        : "+f"(c[0]), "+f"(c[1]), "+f"(c[2]), "+f"(c[3])
        : "r"(a[0]), "r"(a[1]), "r"(a[2]), "r"(a[3]), "r"(b[0]), "r"(b[1]));
}
__device__ __forceinline__ uint32_t pack2h(float a, float b) {
    __half2 h = __floats2half2_rn(a, b);
    return *reinterpret_cast<uint32_t*>(&h);
}

// ---------------------------------------------------------------------------
__global__ void cvt_h(const float4* __restrict__ x, uint2* __restrict__ o, int n4) {
    int i = blockIdx.x * blockDim.x + threadIdx.x;
    if (i >= n4) return;
    float4 v = x[i];
    o[i] = make_uint2(pack2h(v.x, v.y), pack2h(v.z, v.w));
}

// ---------------------------------------------------------------------------
// Plain fp16 GEMM via mma.sync, 4-stage cp.async pipeline.
// 128x128 CTA tile, 8 warps (64x32 warp tile), 2 CTAs/SM, BK=32.
// MODE 0: fp32 out + bias. MODE 1: QKV -> Q,K,V fp16 [B,H,T,D].
// ---------------------------------------------------------------------------
#define GSTRIDE 40
#define MAT_BYTES (128 * GSTRIDE * 2)
#define STAGE_BYTES (2 * MAT_BYTES)     // A, B
#define NSTAGE 4
#define GK_SMEM (NSTAGE * STAGE_BYTES)  // 81920 B -> 2 CTAs/SM

template <int MODE>
__global__ __launch_bounds__(256, 2) void gemm_mma(
    const __half* __restrict__ Af, const __half* __restrict__ Bf,
    const float* __restrict__ bias, float* __restrict__ out,
    int M, int N, int K)
{
    extern __shared__ __align__(128) char dsm[];
    const uint32_t smb = smem_u32(dsm);

    const int tid  = threadIdx.x;
    const int wid  = tid >> 5;
    const int lane = tid & 31;
    const int wm = wid >> 2;
    const int wn = wid & 3;

    const size_t m0 = (size_t)blockIdx.y * 128;
    const size_t n0 = (size_t)blockIdx.x * 128;

    const __half* srcA = Af + m0 * K;
    const __half* srcB = Bf + n0 * K;

    float acc[4][4][4];
#pragma unroll
    for (int i = 0; i < 4; i++)
#pragma unroll
        for (int j = 0; j < 4; j++)
#pragma unroll
            for (int k = 0; k < 4; k++) acc[i][j][k] = 0.f;

    auto load_stage = [&](int kt, int s) {
        const int k0 = kt * 32;
        const uint32_t sb = smb + s * STAGE_BYTES;
#pragma unroll
        for (int i = 0; i < 2; i++) {
            int idx = tid + i * 256;
            int row = idx >> 2;
            int q   = idx & 3;
            cp16(sb + (row * GSTRIDE + q * 8) * 2,
                 srcA + (size_t)row * K + k0 + q * 8);
            cp16(sb + MAT_BYTES + (row * GSTRIDE + q * 8) * 2,
                 srcB + (size_t)row * K + k0 + q * 8);
        }
        cp_commit();
    };

    const uint32_t a_row = (uint32_t)(wm * 64 + (lane & 15));
    const uint32_t a_kof = (uint32_t)(((lane >> 4) & 1) * 8);
    const uint32_t b_row = (uint32_t)(wn * 32 + (lane & 7) + ((lane >> 4) & 1) * 8);
    const uint32_t b_kof = (uint32_t)(((lane >> 3) & 1) * 8);

    const int NT = K >> 5;                 // 32 chunks
    load_stage(0, 0);
    load_stage(1, 1);
    load_stage(2, 2);

    for (int kt = 0; kt < NT; kt++) {
        // groups issued so far: up to kt+2. Allow 2 newest outstanding ->
        // stage kt is complete.
        if (kt + 2 < NT) cp_wait2();
        else if (kt + 1 < NT) cp_wait1();
        else cp_wait0();
        __syncthreads();   // everyone done reading buffer (kt+3)%NSTAGE (chunk kt-1)
        if (kt + 3 < NT) load_stage(kt + 3, (kt + 3) % NSTAGE);

        const uint32_t sb = smb + (kt % NSTAGE) * STAGE_BYTES;
        const uint32_t sA = sb;
        const uint32_t sB = sb + MAT_BYTES;

#pragma unroll
        for (int ks = 0; ks < 2; ks++) {
            uint32_t bf[2][4];
#pragma unroll
            for (int nf2 = 0; nf2 < 2; nf2++) {
                uint32_t off = ((b_row + nf2 * 16) * GSTRIDE + ks * 16 + b_kof) * 2;
                ldsm4(bf[nf2], sB + off);
            }
            uint32_t af[2][4];
            {
                uint32_t off0 = (a_row * GSTRIDE + ks * 16 + a_kof) * 2;
                ldsm4(af[0], sA + off0);
            }
#pragma unroll
            for (int mf = 0; mf < 4; mf++) {
                const int cur = mf & 1, nxt = cur ^ 1;
                if (mf < 3) {
                    uint32_t offn = ((a_row + (mf + 1) * 16) * GSTRIDE + ks * 16 + a_kof) * 2;
                    ldsm4(af[nxt], sA + offn);
                }
#pragma unroll
                for (int nf = 0; nf < 4; nf++)
                    mma_f16(acc[mf][nf], af[cur], &bf[nf >> 1][(nf & 1) * 2]);
            }
        }
    }

    const int r_in = lane >> 2;
    const int c_in = (lane & 3) * 2;

    if (MODE == 0) {
#pragma unroll
        for (int mf = 0; mf < 4; mf++) {
#pragma unroll
            for (int nf = 0; nf < 4; nf++) {
                size_t row = m0 + wm * 64 + mf * 16 + r_in;
                size_t col = n0 + wn * 32 + nf * 8 + c_in;
                float bx = bias[col], by = bias[col + 1];
                float2 o0 = make_float2(acc[mf][nf][0] + bx, acc[mf][nf][1] + by);
                float2 o1 = make_float2(acc[mf][nf][2] + bx, acc[mf][nf][3] + by);
                *(float2*)(out + row * N + col) = o0;
                *(float2*)(out + (row + 8) * N + col) = o1;
            }
        }
    } else {
        __half* dst[3] = {g_q, g_k, g_v};
#pragma unroll
        for (int mf = 0; mf < 4; mf++) {
#pragma unroll
            for (int nf = 0; nf < 4; nf++) {
                size_t col = n0 + wn * 32 + nf * 8 + c_in;
                int sec = (int)(col >> 10);      // 0=Q, 1=K, 2=V
                int h   = (int)((col >> 6) & 15);
                int d   = (int)(col & 63);
                float bx = bias[col], by = bias[col + 1];
                __half* dp = dst[sec];
#pragma unroll
                for (int half = 0; half < 2; half++) {
                    size_t row = m0 + wm * 64 + mf * 16 + r_in + half * 8;
                    int b = (int)(row >> 11);
                    int t = (int)(row & 2047);
                    size_t idx = (((size_t)(b * H_ + h) * T_ + t) * D_ + d);
                    *(uint32_t*)(dp + idx) =
                        pack2h(acc[mf][nf][half * 2 + 0] + bx,
                               acc[mf][nf][half * 2 + 1] + by);
                }
            }
        }
    }
}

// ---------------------------------------------------------------------------
// Plain fp16 causal flash attention. Single-product S and PV.
// Base-2 softmax, balanced q-pairs, double-buffered KV cp.async.
// ---------------------------------------------------------------------------
#define AST 72
#define QSZ (128 * AST)
#define KVSZ (128 * AST)
#define KVSTAGE (2 * KVSZ)             // K, V
#define A_SMEM ((QSZ + 2 * KVSTAGE) * 2)   // 92160 B

__global__ __launch_bounds__(256) void attn_tc() {
    extern __shared__ __align__(128) __half sm[];
    const uint32_t smb = smem_u32(sm);
    const uint32_t sQ   = smb;
    const uint32_t sKV0 = smb + QSZ * 2;

    const int pair = blockIdx.x;
    const int h  = blockIdx.y;
    const int b  = blockIdx.z;
    const int tid  = threadIdx.x;
    const int wid  = tid >> 5;
    const int lane = tid & 31;
    const int bh = b * H_ + h;

    const __half* gk = g_k + (size_t)bh * T_ * D_;
    const __half* gv = g_v + (size_t)bh * T_ * D_;

    auto load_kv = [&](int kt, int s) {
        const uint32_t sb = sKV0 + s * KVSTAGE * 2;
        const __half* bases[2] = {gk + (size_t)kt * 128 * D_,
                                  gv + (size_t)kt * 128 * D_};
#pragma unroll
        for (int i = 0; i < 8; i++) {
            int idx = tid + i * 256;
            int arr = idx >> 10;
            int rem = idx & 1023;
            int row = rem >> 3;
            int ch  = rem & 7;
            cp16(sb + (arr * KVSZ + row * AST + ch * 8) * 2,
                 bases[arr] + (size_t)row * D_ + ch * 8);
        }
        cp_commit();
    };

    const uint32_t k_row = (uint32_t)((lane & 7) + ((lane >> 4) & 1) * 8);
    const uint32_t k_kof = ((lane >> 3) & 1) * 8;
    const uint32_t v_rof = (uint32_t)(lane & 15);
    const uint32_t v_cof = ((lane >> 4) & 1) * 8;

    const float SC2 = 0.125f * 1.44269504f;   // D^-0.5 * log2(e)

    auto process_qblock = [&](int qb) {
        const __half* gq = g_q + ((size_t)bh * T_ + qb * 128) * D_;
        // Q tile: 128 rows x 8 chunks = 1024 cp.async / 256 thr = 4 each
#pragma unroll
        for (int i = 0; i < 4; i++) {
            int idx = tid + i * 256;
            int row = idx >> 3;
            int ch  = idx & 7;
            cp16(sQ + (row * AST + ch * 8) * 2, gq + (size_t)row * D_ + ch * 8);
        }
        cp_commit();
        load_kv(0, 0);
        cp_wait0();
        __syncthreads();

        uint32_t qF[4][4];
        {
            uint32_t rbase = (uint32_t)(wid * 16 + (lane & 15));
            uint32_t kof = ((lane >> 4) & 1) * 8;
#pragma unroll
            for (int ks = 0; ks < 4; ks++) {
                uint32_t off = (rbase * AST + ks * 16 + kof) * 2;
                ldsm4(qF[ks], sQ + off);
            }
        }

        float O[8][4];
#pragma unroll
        for (int i = 0; i < 8; i++)
#pragma unroll
            for (int j = 0; j < 4; j++) O[i][j] = 0.f;
        float mrow[2] = {-1e30f, -1e30f};
        float lrow[2] = {0.f, 0.f};

        for (int kt = 0; kt <= qb; kt++) {
            const bool more = (kt + 1 <= qb);
            if (more) load_kv(kt + 1, (kt + 1) & 1);
            if (more) cp_wait1(); else cp_wait0();
            __syncthreads();

            const uint32_t sb = sKV0 + (kt & 1) * KVSTAGE * 2;
            const uint32_t sK = sb;
            const uint32_t sV = sb + KVSZ * 2;

            // ---- S = Q K^T (single product) --------------------------------
            float S[16][4];
#pragma unroll
            for (int i = 0; i < 16; i++)
#pragma unroll
                for (int j = 0; j < 4; j++) S[i][j] = 0.f;

#pragma unroll
            for (int ks = 0; ks < 4; ks++) {
#pragma unroll
                for (int i2 = 0; i2 < 4; i2++) {
                    uint32_t kh4[2][4];
#pragma unroll
                    for (int ii = 0; ii < 2; ii++) {
                        uint32_t off = (((i2 * 2 + ii) * 16 + k_row) * AST
                                        + ks * 16 + k_kof) * 2;
                        ldsm4(kh4[ii], sK + off);
                    }
#pragma unroll
                    for (int ii = 0; ii < 2; ii++)
#pragma unroll
                        for (int half = 0; half < 2; half++)
                            mma_f16(S[(i2 * 2 + ii) * 2 + half], qF[ks],
                                    &kh4[ii][half * 2]);
                }
            }

            // ---- scale (base-2) + causal mask ------------------------------
#pragma unroll
            for (int i = 0; i < 16; i++)
#pragma unroll
                for (int j = 0; j < 4; j++) S[i][j] *= SC2;

            if (kt == qb) {
                const int r0 = wid * 16 + (lane >> 2);
#pragma unroll
                for (int nf = 0; nf < 16; nf++) {
                    int col = nf * 8 + (lane & 3) * 2;
                    if (col > r0)      S[nf][0] = -1e30f;
                    if (col + 1 > r0)  S[nf][1] = -1e30f;
                    if (col > r0 + 8)     S[nf][2] = -1e30f;
                    if (col + 1 > r0 + 8) S[nf][3] = -1e30f;
                }
            }

            // ---- online softmax (base-2, in-warp) --------------------------
            float rm0 = -1e30f, rm1 = -1e30f;
#pragma unroll
            for (int nf = 0; nf < 16; nf++) {
                rm0 = fmaxf(rm0, fmaxf(S[nf][0], S[nf][1]));
                rm1 = fmaxf(rm1, fmaxf(S[nf][2], S[nf][3]));
            }
            rm0 = fmaxf(rm0, __shfl_xor_sync(0xffffffffu, rm0, 1));
            rm0 = fmaxf(rm0, __shfl_xor_sync(0xffffffffu, rm0, 2));
            rm1 = fmaxf(rm1, __shfl_xor_sync(0xffffffffu, rm1, 1));
            rm1 = fmaxf(rm1, __shfl_xor_sync(0xffffffffu, rm1, 2));

            float mn0 = fmaxf(mrow[0], rm0);
            float mn1 = fmaxf(mrow[1], rm1);
            float a0 = exp2f(mrow[0] - mn0);
            float a1 = exp2f(mrow[1] - mn1);
            mrow[0] = mn0; mrow[1] = mn1;

            float rs0 = 0.f, rs1 = 0.f;
#pragma unroll
            for (int nf = 0; nf < 16; nf++) {
                S[nf][0] = exp2f(S[nf][0] - mn0);
                S[nf][1] = exp2f(S[nf][1] - mn0);
                S[nf][2] = exp2f(S[nf][2] - mn1);
                S[nf][3] = exp2f(S[nf][3] - mn1);
                rs0 += S[nf][0] + S[nf][1];
                rs1 += S[nf][2] + S[nf][3];
            }
            rs0 += __shfl_xor_sync(0xffffffffu, rs0, 1);
            rs0 += __shfl_xor_sync(0xffffffffu, rs0, 2);
            rs1 += __shfl_xor_sync(0xffffffffu, rs1, 1);
            rs1 += __shfl_xor_sync(0xffffffffu, rs1, 2);
            lrow[0] = lrow[0] * a0 + rs0;
            lrow[1] = lrow[1] * a1 + rs1;

#pragma unroll
            for (int nf = 0; nf < 8; nf++) {
                O[nf][0] *= a0; O[nf][1] *= a0;
                O[nf][2] *= a1; O[nf][3] *= a1;
            }

            // ---- O += P V (single product; preload V frags) ----------------
#pragma unroll
            for (int ks2 = 0; ks2 < 8; ks2++) {
                uint32_t pf[4];
                pf[0] = pack2h(S[2 * ks2][0],     S[2 * ks2][1]);
                pf[1] = pack2h(S[2 * ks2][2],     S[2 * ks2][3]);
                pf[2] = pack2h(S[2 * ks2 + 1][0], S[2 * ks2 + 1][1]);
                pf[3] = pack2h(S[2 * ks2 + 1][2], S[2 * ks2 + 1][3]);

                uint32_t vf[4][4];
#pragma unroll
                for (int i = 0; i < 4; i++) {
                    uint32_t off = ((ks2 * 16 + v_rof) * AST + i * 16 + v_cof) * 2;
                    ldsm4t(vf[i], sV + off);
                }
#pragma unroll
                for (int i = 0; i < 4; i++)
#pragma unroll
                    for (int half = 0; half < 2; half++)
                        mma_f16(O[i * 2 + half], pf, &vf[i][half * 2]);
            }
            __syncthreads();
        }

        const float inv0 = 1.f / lrow[0];
        const float inv1 = 1.f / lrow[1];
        const size_t row0 = (size_t)b * T_ + qb * 128 + wid * 16 + (lane >> 2);
#pragma unroll
        for (int nf = 0; nf < 8; nf++) {
            int col = h * 64 + nf * 8 + (lane & 3) * 2;
            *(uint32_t*)(g_o + row0 * C_ + col) =
                pack2h(O[nf][0] * inv0, O[nf][1] * inv0);
            *(uint32_t*)(g_o + (row0 + 8) * C_ + col) =
                pack2h(O[nf][2] * inv1, O[nf][3] * inv1);
        }
    };

    process_qblock(pair);
    __syncthreads();
    process_qblock(NQB - 1 - pair);
}

// ---------------------------------------------------------------------------
extern "C" void kernel_launch(void* const* d_in, const int* in_sizes, int n_in,
                              void* d_out, int out_size) {
    const float* hidden = (const float*)d_in[0];
    const float* W_qkv  = (const float*)d_in[2];
    const float* b_qkv  = (const float*)d_in[3];
    const float* W_o    = (const float*)d_in[4];
    const float* b_o    = (const float*)d_in[5];
    float* out = (float*)d_out;

    __half *x, *wq, *wo, *o;
    cudaGetSymbolAddress((void**)&x, g_x);
    cudaGetSymbolAddress((void**)&wq, g_wq);
    cudaGetSymbolAddress((void**)&wo, g_wo);
    cudaGetSymbolAddress((void**)&o, g_o);

    cudaFuncSetAttribute(gemm_mma<0>, cudaFuncAttributeMaxDynamicSharedMemorySize, GK_SMEM);
    cudaFuncSetAttribute(gemm_mma<1>, cudaFuncAttributeMaxDynamicSharedMemorySize, GK_SMEM);
    cudaFuncSetAttribute(attn_tc, cudaFuncAttributeMaxDynamicSharedMemorySize, A_SMEM);

    {
        int n4 = (M_ * C_) / 4;
        cvt_h<<<(n4 + 255) / 256, 256>>>((const float4*)hidden, (uint2*)x, n4);
        n4 = (C3_ * C_) / 4;
        cvt_h<<<(n4 + 255) / 256, 256>>>((const float4*)W_qkv, (uint2*)wq, n4);
        n4 = (C_ * C_) / 4;
        cvt_h<<<(n4 + 255) / 256, 256>>>((const float4*)W_o, (uint2*)wo, n4);
    }

    // 1) QKV projection -> Q,K,V fp16 [B,H,T,D]
    {
        dim3 grid(C3_ / 128, M_ / 128);
        gemm_mma<1><<<grid, 256, GK_SMEM>>>(x, wq, b_qkv, nullptr, M_, C3_, C_);
    }
    // 2) flash attention -> g_o
    {
        dim3 grid(NQB / 2, H_, B_);
        attn_tc<<<grid, 256, A_SMEM>>>();
    }
    // 3) out = O @ W_o^T + b_o
    {
        dim3 grid(C_ / 128, M_ / 128);
        gemm_mma<0><<<grid, 256, GK_SMEM>>>(o, wo, b_o, out, M_, C_, C_);
    }
}

// round 15
// speedup vs baseline: 2.4410x; 1.1049x over previous
#include <cuda_runtime.h>
#include <cuda_fp16.h>
#include <cstdint>

#define B_ 4
#define T_ 2048
#define C_ 1024
#define H_ 16
#define D_ 64
#define C3_ (3 * C_)
#define M_ (B_ * T_)   // 8192
#define NQB (T_ / 128) // 16 q-blocks per (b,h)

// ---------------- scratch (device globals; no runtime alloc) ----------------
__device__ __half g_x[(size_t)M_ * C_];              // hidden fp16
__device__ __half g_wq[(size_t)C3_ * C_];            // W_qkv fp16
__device__ __half g_wo[(size_t)C_ * C_];             // W_o   fp16
__device__ __half g_q[(size_t)M_ * C_];              // Q fp16 [B,H,T,D]
__device__ __half g_k[(size_t)M_ * C_];              // K fp16 [B,H,T,D]
__device__ __half g_v[(size_t)M_ * C_];              // V fp16 [B,H,T,D]
__device__ __half g_o[(size_t)M_ * C_];              // attn out fp16 [M,C]

// ---------------------------- helpers ---------------------------------------
__device__ __forceinline__ uint32_t smem_u32(const void* p) {
    uint32_t a;
    asm("{ .reg .u64 t; cvta.to.shared.u64 t, %1; cvt.u32.u64 %0, t; }"
        : "=r"(a) : "l"(p));
    return a;
}
__device__ __forceinline__ void cp16(uint32_t dst, const void* src) {
    asm volatile("cp.async.cg.shared.global [%0], [%1], 16;" :: "r"(dst), "l"(src));
}
__device__ __forceinline__ void cp_commit() {
    asm volatile("cp.async.commit_group;" ::: "memory");
}
__device__ __forceinline__ void cp_wait0() {
    asm volatile("cp.async.wait_group 0;" ::: "memory");
}
__device__ __forceinline__ void cp_wait1() {
    asm volatile("cp.async.wait_group 1;" ::: "memory");
}
__device__ __forceinline__ void ldsm4(uint32_t* r, uint32_t addr) {
    asm volatile("ldmatrix.sync.aligned.m8n8.x4.shared.b16 {%0,%1,%2,%3}, [%4];"
                 : "=r"(r[0]), "=r"(r[1]), "=r"(r[2]), "=r"(r[3]) : "r"(addr));
}
__device__ __forceinline__ void ldsm4t(uint32_t* r, uint32_t addr) {
    asm volatile("ldmatrix.sync.aligned.m8n8.x4.trans.shared.b16 {%0,%1,%2,%3}, [%4];"
                 : "=r"(r[0]), "=r"(r[1]), "=r"(r[2]), "=r"(r[3]) : "r"(addr));
}
__device__ __forceinline__ void mma_f16(float* c, const uint32_t* a, const uint32_t* b) {
    asm volatile(
        "mma.sync.aligned.m16n8k16.row.col.f32.f16.f16.f32 "
        "{%0,%1,%2,%3}, {%4,%5,%6,%7}, {%8,%9}, {%0,%1,%2,%3};"
        : "+f"(c[0]), "+f"(c[1]), "+f"(c[2]), "+f"(c[3])
        : "r"(a[0]), "r"(a[1]), "r"(a[2]), "r"(a[3]), "r"(b[0]), "r"(b[1]));
}
__device__ __forceinline__ uint32_t pack2h(float a, float b) {
    __half2 h = __floats2half2_rn(a, b);
    return *reinterpret_cast<uint32_t*>(&h);
}

// ---------------------------------------------------------------------------
__global__ void cvt_h(const float4* __restrict__ x, uint2* __restrict__ o, int n4) {
    int i = blockIdx.x * blockDim.x + threadIdx.x;
    if (i >= n4) return;
    float4 v = x[i];
    o[i] = make_uint2(pack2h(v.x, v.y), pack2h(v.z, v.w));
}

// ---------------------------------------------------------------------------
// Plain fp16 GEMM via mma.sync, BK=64 chunks (half the barriers of BK=32),
// double-buffered cp.async. 128x128 CTA tile, 8 warps (64x32 warp tile),
// 2 CTAs/SM. MODE 0: fp32 out + bias. MODE 1: QKV -> Q,K,V fp16 [B,H,T,D].
// ---------------------------------------------------------------------------
#define GSTRIDE 72                       // 64 halfs + 8 pad (conflict-free ldsm)
#define MAT_BYTES (128 * GSTRIDE * 2)    // 18432 B
#define STAGE_BYTES (2 * MAT_BYTES)      // A, B: 36864 B
#define NSTAGE 2
#define GK_SMEM (NSTAGE * STAGE_BYTES)   // 73728 B -> 2 CTAs/SM

template <int MODE>
__global__ __launch_bounds__(256, 2) void gemm_mma(
    const __half* __restrict__ Af, const __half* __restrict__ Bf,
    const float* __restrict__ bias, float* __restrict__ out,
    int M, int N, int K)
{
    extern __shared__ __align__(128) char dsm[];
    const uint32_t smb = smem_u32(dsm);

    const int tid  = threadIdx.x;
    const int wid  = tid >> 5;
    const int lane = tid & 31;
    const int wm = wid >> 2;
    const int wn = wid & 3;

    const size_t m0 = (size_t)blockIdx.y * 128;
    const size_t n0 = (size_t)blockIdx.x * 128;

    const __half* srcA = Af + m0 * K;
    const __half* srcB = Bf + n0 * K;

    float acc[4][4][4];
#pragma unroll
    for (int i = 0; i < 4; i++)
#pragma unroll
        for (int j = 0; j < 4; j++)
#pragma unroll
            for (int k = 0; k < 4; k++) acc[i][j][k] = 0.f;

    // stage: 128 rows x 8 16B-chunks per matrix = 1024 cp16 x2 / 256 thr
    auto load_stage = [&](int kt, int s) {
        const int k0 = kt * 64;
        const uint32_t sb = smb + s * STAGE_BYTES;
#pragma unroll
        for (int i = 0; i < 4; i++) {
            int idx = tid + i * 256;          // 0..1023
            int row = idx >> 3;               // 0..127
            int q   = idx & 7;                // 16B chunk in 128B row
            cp16(sb + (row * GSTRIDE + q * 8) * 2,
                 srcA + (size_t)row * K + k0 + q * 8);
            cp16(sb + MAT_BYTES + (row * GSTRIDE + q * 8) * 2,
                 srcB + (size_t)row * K + k0 + q * 8);
        }
        cp_commit();
    };

    const uint32_t a_row = (uint32_t)(wm * 64 + (lane & 15));
    const uint32_t a_kof = (uint32_t)(((lane >> 4) & 1) * 8);
    const uint32_t b_row = (uint32_t)(wn * 32 + (lane & 7) + ((lane >> 4) & 1) * 8);
    const uint32_t b_kof = (uint32_t)(((lane >> 3) & 1) * 8);

    const int NT = K >> 6;                 // 16 chunks of 64
    load_stage(0, 0);

    for (int kt = 0; kt < NT; kt++) {
        cp_wait0();
        __syncthreads();   // all warps done reading buffer (kt+1)&1 (chunk kt-1)
        if (kt + 1 < NT) load_stage(kt + 1, (kt + 1) & 1);

        const uint32_t sb = smb + (kt & 1) * STAGE_BYTES;
        const uint32_t sA = sb;
        const uint32_t sB = sb + MAT_BYTES;

#pragma unroll
        for (int ks = 0; ks < 4; ks++) {
            uint32_t bf[2][4];
#pragma unroll
            for (int nf2 = 0; nf2 < 2; nf2++) {
                uint32_t off = ((b_row + nf2 * 16) * GSTRIDE + ks * 16 + b_kof) * 2;
                ldsm4(bf[nf2], sB + off);
            }
            uint32_t af[2][4];
            {
                uint32_t off0 = (a_row * GSTRIDE + ks * 16 + a_kof) * 2;
                ldsm4(af[0], sA + off0);
            }
#pragma unroll
            for (int mf = 0; mf < 4; mf++) {
                const int cur = mf & 1, nxt = cur ^ 1;
                if (mf < 3) {
                    uint32_t offn = ((a_row + (mf + 1) * 16) * GSTRIDE + ks * 16 + a_kof) * 2;
                    ldsm4(af[nxt], sA + offn);
                }
#pragma unroll
                for (int nf = 0; nf < 4; nf++)
                    mma_f16(acc[mf][nf], af[cur], &bf[nf >> 1][(nf & 1) * 2]);
            }
        }
    }

    const int r_in = lane >> 2;
    const int c_in = (lane & 3) * 2;

    if (MODE == 0) {
#pragma unroll
        for (int mf = 0; mf < 4; mf++) {
#pragma unroll
            for (int nf = 0; nf < 4; nf++) {
                size_t row = m0 + wm * 64 + mf * 16 + r_in;
                size_t col = n0 + wn * 32 + nf * 8 + c_in;
                float bx = bias[col], by = bias[col + 1];
                float2 o0 = make_float2(acc[mf][nf][0] + bx, acc[mf][nf][1] + by);
                float2 o1 = make_float2(acc[mf][nf][2] + bx, acc[mf][nf][3] + by);
                *(float2*)(out + row * N + col) = o0;
                *(float2*)(out + (row + 8) * N + col) = o1;
            }
        }
    } else {
        __half* dst[3] = {g_q, g_k, g_v};
#pragma unroll
        for (int mf = 0; mf < 4; mf++) {
#pragma unroll
            for (int nf = 0; nf < 4; nf++) {
                size_t col = n0 + wn * 32 + nf * 8 + c_in;
                int sec = (int)(col >> 10);      // 0=Q, 1=K, 2=V
                int h   = (int)((col >> 6) & 15);
                int d   = (int)(col & 63);
                float bx = bias[col], by = bias[col + 1];
                __half* dp = dst[sec];
#pragma unroll
                for (int half = 0; half < 2; half++) {
                    size_t row = m0 + wm * 64 + mf * 16 + r_in + half * 8;
                    int b = (int)(row >> 11);
                    int t = (int)(row & 2047);
                    size_t idx = (((size_t)(b * H_ + h) * T_ + t) * D_ + d);
                    *(uint32_t*)(dp + idx) =
                        pack2h(acc[mf][nf][half * 2 + 0] + bx,
                               acc[mf][nf][half * 2 + 1] + by);
                }
            }
        }
    }
}

// ---------------------------------------------------------------------------
// Plain fp16 causal flash attention, now 2 CTAs/SM so one CTA's MMAs overlap
// the other's softmax (MUFU) phase. Single-product S and PV, base-2 softmax,
// balanced q-pairs, double-buffered KV cp.async.
// ---------------------------------------------------------------------------
#define AST 72
#define QSZ (128 * AST)
#define KVSZ (128 * AST)
#define KVSTAGE (2 * KVSZ)             // K, V
#define A_SMEM ((QSZ + 2 * KVSTAGE) * 2)   // 92160 B -> 2 CTAs/SM

__global__ __launch_bounds__(256, 2) void attn_tc() {
    extern __shared__ __align__(128) __half sm[];
    const uint32_t smb = smem_u32(sm);
    const uint32_t sQ   = smb;
    const uint32_t sKV0 = smb + QSZ * 2;

    const int pair = blockIdx.x;
    const int h  = blockIdx.y;
    const int b  = blockIdx.z;
    const int tid  = threadIdx.x;
    const int wid  = tid >> 5;
    const int lane = tid & 31;
    const int bh = b * H_ + h;

    const __half* gk = g_k + (size_t)bh * T_ * D_;
    const __half* gv = g_v + (size_t)bh * T_ * D_;

    auto load_kv = [&](int kt, int s) {
        const uint32_t sb = sKV0 + s * KVSTAGE * 2;
        const __half* bases[2] = {gk + (size_t)kt * 128 * D_,
                                  gv + (size_t)kt * 128 * D_};
#pragma unroll
        for (int i = 0; i < 8; i++) {
            int idx = tid + i * 256;
            int arr = idx >> 10;
            int rem = idx & 1023;
            int row = rem >> 3;
            int ch  = rem & 7;
            cp16(sb + (arr * KVSZ + row * AST + ch * 8) * 2,
                 bases[arr] + (size_t)row * D_ + ch * 8);
        }
        cp_commit();
    };

    const uint32_t k_row = (uint32_t)((lane & 7) + ((lane >> 4) & 1) * 8);
    const uint32_t k_kof = ((lane >> 3) & 1) * 8;
    const uint32_t v_rof = (uint32_t)(lane & 15);
    const uint32_t v_cof = ((lane >> 4) & 1) * 8;

    const float SC2 = 0.125f * 1.44269504f;   // D^-0.5 * log2(e)

    auto process_qblock = [&](int qb) {
        const __half* gq = g_q + ((size_t)bh * T_ + qb * 128) * D_;
#pragma unroll
        for (int i = 0; i < 4; i++) {
            int idx = tid + i * 256;
            int row = idx >> 3;
            int ch  = idx & 7;
            cp16(sQ + (row * AST + ch * 8) * 2, gq + (size_t)row * D_ + ch * 8);
        }
        cp_commit();
        load_kv(0, 0);
        cp_wait0();
        __syncthreads();

        uint32_t qF[4][4];
        {
            uint32_t rbase = (uint32_t)(wid * 16 + (lane & 15));
            uint32_t kof = ((lane >> 4) & 1) * 8;
#pragma unroll
            for (int ks = 0; ks < 4; ks++) {
                uint32_t off = (rbase * AST + ks * 16 + kof) * 2;
                ldsm4(qF[ks], sQ + off);
            }
        }

        float O[8][4];
#pragma unroll
        for (int i = 0; i < 8; i++)
#pragma unroll
            for (int j = 0; j < 4; j++) O[i][j] = 0.f;
        float mrow[2] = {-1e30f, -1e30f};
        float lrow[2] = {0.f, 0.f};

        for (int kt = 0; kt <= qb; kt++) {
            const bool more = (kt + 1 <= qb);
            if (more) load_kv(kt + 1, (kt + 1) & 1);
            if (more) cp_wait1(); else cp_wait0();
            __syncthreads();

            const uint32_t sb = sKV0 + (kt & 1) * KVSTAGE * 2;
            const uint32_t sK = sb;
            const uint32_t sV = sb + KVSZ * 2;

            // ---- S = Q K^T (single product) --------------------------------
            float S[16][4];
#pragma unroll
            for (int i = 0; i < 16; i++)
#pragma unroll
                for (int j = 0; j < 4; j++) S[i][j] = 0.f;

#pragma unroll
            for (int ks = 0; ks < 4; ks++) {
#pragma unroll
                for (int i2 = 0; i2 < 4; i2++) {
                    uint32_t kh4[2][4];
#pragma unroll
                    for (int ii = 0; ii < 2; ii++) {
                        uint32_t off = (((i2 * 2 + ii) * 16 + k_row) * AST
                                        + ks * 16 + k_kof) * 2;
                        ldsm4(kh4[ii], sK + off);
                    }
#pragma unroll
                    for (int ii = 0; ii < 2; ii++)
#pragma unroll
                        for (int half = 0; half < 2; half++)
                            mma_f16(S[(i2 * 2 + ii) * 2 + half], qF[ks],
                                    &kh4[ii][half * 2]);
                }
            }

            // ---- scale (base-2) + causal mask ------------------------------
#pragma unroll
            for (int i = 0; i < 16; i++)
#pragma unroll
                for (int j = 0; j < 4; j++) S[i][j] *= SC2;

            if (kt == qb) {
                const int r0 = wid * 16 + (lane >> 2);
#pragma unroll
                for (int nf = 0; nf < 16; nf++) {
                    int col = nf * 8 + (lane & 3) * 2;
                    if (col > r0)      S[nf][0] = -1e30f;
                    if (col + 1 > r0)  S[nf][1] = -1e30f;
                    if (col > r0 + 8)     S[nf][2] = -1e30f;
                    if (col + 1 > r0 + 8) S[nf][3] = -1e30f;
                }
            }

            // ---- online softmax (base-2, in-warp) --------------------------
            float rm0 = -1e30f, rm1 = -1e30f;
#pragma unroll
            for (int nf = 0; nf < 16; nf++) {
                rm0 = fmaxf(rm0, fmaxf(S[nf][0], S[nf][1]));
                rm1 = fmaxf(rm1, fmaxf(S[nf][2], S[nf][3]));
            }
            rm0 = fmaxf(rm0, __shfl_xor_sync(0xffffffffu, rm0, 1));
            rm0 = fmaxf(rm0, __shfl_xor_sync(0xffffffffu, rm0, 2));
            rm1 = fmaxf(rm1, __shfl_xor_sync(0xffffffffu, rm1, 1));
            rm1 = fmaxf(rm1, __shfl_xor_sync(0xffffffffu, rm1, 2));

            float mn0 = fmaxf(mrow[0], rm0);
            float mn1 = fmaxf(mrow[1], rm1);
            float a0 = exp2f(mrow[0] - mn0);
            float a1 = exp2f(mrow[1] - mn1);
            mrow[0] = mn0; mrow[1] = mn1;

            float rs0 = 0.f, rs1 = 0.f;
#pragma unroll
            for (int nf = 0; nf < 16; nf++) {
                S[nf][0] = exp2f(S[nf][0] - mn0);
                S[nf][1] = exp2f(S[nf][1] - mn0);
                S[nf][2] = exp2f(S[nf][2] - mn1);
                S[nf][3] = exp2f(S[nf][3] - mn1);
                rs0 += S[nf][0] + S[nf][1];
                rs1 += S[nf][2] + S[nf][3];
            }
            rs0 += __shfl_xor_sync(0xffffffffu, rs0, 1);
            rs0 += __shfl_xor_sync(0xffffffffu, rs0, 2);
            rs1 += __shfl_xor_sync(0xffffffffu, rs1, 1);
            rs1 += __shfl_xor_sync(0xffffffffu, rs1, 2);
            lrow[0] = lrow[0] * a0 + rs0;
            lrow[1] = lrow[1] * a1 + rs1;

#pragma unroll
            for (int nf = 0; nf < 8; nf++) {
                O[nf][0] *= a0; O[nf][1] *= a0;
                O[nf][2] *= a1; O[nf][3] *= a1;
            }

            // ---- O += P V (single product; preload V frags) ----------------
#pragma unroll
            for (int ks2 = 0; ks2 < 8; ks2++) {
                uint32_t pf[4];
                pf[0] = pack2h(S[2 * ks2][0],     S[2 * ks2][1]);
                pf[1] = pack2h(S[2 * ks2][2],     S[2 * ks2][3]);
                pf[2] = pack2h(S[2 * ks2 + 1][0], S[2 * ks2 + 1][1]);
                pf[3] = pack2h(S[2 * ks2 + 1][2], S[2 * ks2 + 1][3]);

                uint32_t vf[4][4];
#pragma unroll
                for (int i = 0; i < 4; i++) {
                    uint32_t off = ((ks2 * 16 + v_rof) * AST + i * 16 + v_cof) * 2;
                    ldsm4t(vf[i], sV + off);
                }
#pragma unroll
                for (int i = 0; i < 4; i++)
#pragma unroll
                    for (int half = 0; half < 2; half++)
                        mma_f16(O[i * 2 + half], pf, &vf[i][half * 2]);
            }
            __syncthreads();
        }

        const float inv0 = 1.f / lrow[0];
        const float inv1 = 1.f / lrow[1];
        const size_t row0 = (size_t)b * T_ + qb * 128 + wid * 16 + (lane >> 2);
#pragma unroll
        for (int nf = 0; nf < 8; nf++) {
            int col = h * 64 + nf * 8 + (lane & 3) * 2;
            *(uint32_t*)(g_o + row0 * C_ + col) =
                pack2h(O[nf][0] * inv0, O[nf][1] * inv0);
            *(uint32_t*)(g_o + (row0 + 8) * C_ + col) =
                pack2h(O[nf][2] * inv1, O[nf][3] * inv1);
        }
    };

    process_qblock(pair);
    __syncthreads();
    process_qblock(NQB - 1 - pair);
}

// ---------------------------------------------------------------------------
extern "C" void kernel_launch(void* const* d_in, const int* in_sizes, int n_in,
                              void* d_out, int out_size) {
    const float* hidden = (const float*)d_in[0];
    const float* W_qkv  = (const float*)d_in[2];
    const float* b_qkv  = (const float*)d_in[3];
    const float* W_o    = (const float*)d_in[4];
    const float* b_o    = (const float*)d_in[5];
    float* out = (float*)d_out;

    __half *x, *wq, *wo, *o;
    cudaGetSymbolAddress((void**)&x, g_x);
    cudaGetSymbolAddress((void**)&wq, g_wq);
    cudaGetSymbolAddress((void**)&wo, g_wo);
    cudaGetSymbolAddress((void**)&o, g_o);

    cudaFuncSetAttribute(gemm_mma<0>, cudaFuncAttributeMaxDynamicSharedMemorySize, GK_SMEM);
    cudaFuncSetAttribute(gemm_mma<1>, cudaFuncAttributeMaxDynamicSharedMemorySize, GK_SMEM);
    cudaFuncSetAttribute(attn_tc, cudaFuncAttributeMaxDynamicSharedMemorySize, A_SMEM);

    {
        int n4 = (M_ * C_) / 4;
        cvt_h<<<(n4 + 255) / 256, 256>>>((const float4*)hidden, (uint2*)x, n4);
        n4 = (C3_ * C_) / 4;
        cvt_h<<<(n4 + 255) / 256, 256>>>((const float4*)W_qkv, (uint2*)wq, n4);
        n4 = (C_ * C_) / 4;
        cvt_h<<<(n4 + 255) / 256, 256>>>((const float4*)W_o, (uint2*)wo, n4);
    }

    // 1) QKV projection -> Q,K,V fp16 [B,H,T,D]
    {
        dim3 grid(C3_ / 128, M_ / 128);
        gemm_mma<1><<<grid, 256, GK_SMEM>>>(x, wq, b_qkv, nullptr, M_, C3_, C_);
    }
    // 2) flash attention -> g_o
    {
        dim3 grid(NQB / 2, H_, B_);
        attn_tc<<<grid, 256, A_SMEM>>>();
    }
    // 3) out = O @ W_o^T + b_o
    {
        dim3 grid(C_ / 128, M_ / 128);
        gemm_mma<0><<<grid, 256, GK_SMEM>>>(o, wo, b_o, out, M_, C_, C_);
    }
}

// round 16
// speedup vs baseline: 2.5535x; 1.0461x over previous
#include <cuda_runtime.h>
#include <cuda_fp16.h>
#include <cstdint>

#define B_ 4
#define T_ 2048
#define C_ 1024
#define H_ 16
#define D_ 64
#define C3_ (3 * C_)
#define M_ (B_ * T_)   // 8192
#define NQB (T_ / 128) // 16 q-blocks per (b,h)

// ---------------- scratch (device globals; no runtime alloc) ----------------
__device__ __half g_x[(size_t)M_ * C_];              // hidden fp16
__device__ __half g_wq[(size_t)C3_ * C_];            // W_qkv fp16
__device__ __half g_wo[(size_t)C_ * C_];             // W_o   fp16
__device__ __half g_q[(size_t)M_ * C_];              // Q*scale fp16 [B,H,T,D]
__device__ __half g_k[(size_t)M_ * C_];              // K fp16 [B,H,T,D]
__device__ __half g_v[(size_t)M_ * C_];              // V fp16 [B,H,T,D]
__device__ __half g_o[(size_t)M_ * C_];              // attn out fp16 [M,C]

// ---------------------------- helpers ---------------------------------------
__device__ __forceinline__ uint32_t smem_u32(const void* p) {
    uint32_t a;
    asm("{ .reg .u64 t; cvta.to.shared.u64 t, %1; cvt.u32.u64 %0, t; }"
        : "=r"(a) : "l"(p));
    return a;
}
__device__ __forceinline__ void cp16(uint32_t dst, const void* src) {
    asm volatile("cp.async.cg.shared.global [%0], [%1], 16;" :: "r"(dst), "l"(src));
}
__device__ __forceinline__ void cp_commit() {
    asm volatile("cp.async.commit_group;" ::: "memory");
}
__device__ __forceinline__ void cp_wait0() {
    asm volatile("cp.async.wait_group 0;" ::: "memory");
}
__device__ __forceinline__ void cp_wait1() {
    asm volatile("cp.async.wait_group 1;" ::: "memory");
}
__device__ __forceinline__ void ldsm4(uint32_t* r, uint32_t addr) {
    asm volatile("ldmatrix.sync.aligned.m8n8.x4.shared.b16 {%0,%1,%2,%3}, [%4];"
                 : "=r"(r[0]), "=r"(r[1]), "=r"(r[2]), "=r"(r[3]) : "r"(addr));
}
__device__ __forceinline__ void ldsm4t(uint32_t* r, uint32_t addr) {
    asm volatile("ldmatrix.sync.aligned.m8n8.x4.trans.shared.b16 {%0,%1,%2,%3}, [%4];"
                 : "=r"(r[0]), "=r"(r[1]), "=r"(r[2]), "=r"(r[3]) : "r"(addr));
}
__device__ __forceinline__ void mma_f16(float* c, const uint32_t* a, const uint32_t* b) {
    asm volatile(
        "mma.sync.aligned.m16n8k16.row.col.f32.f16.f16.f32 "
        "{%0,%1,%2,%3}, {%4,%5,%6,%7}, {%8,%9}, {%0,%1,%2,%3};"
        : "+f"(c[0]), "+f"(c[1]), "+f"(c[2]), "+f"(c[3])
        : "r"(a[0]), "r"(a[1]), "r"(a[2]), "r"(a[3]), "r"(b[0]), "r"(b[1]));
}
__device__ __forceinline__ uint32_t pack2h(float a, float b) {
    __half2 h = __floats2half2_rn(a, b);
    return *reinterpret_cast<uint32_t*>(&h);
}
__device__ __forceinline__ uint32_t ex2_h2(uint32_t x) {
    uint32_t r;
    asm("ex2.approx.f16x2 %0, %1;" : "=r"(r) : "r"(x));
    return r;
}

// ---------------------------------------------------------------------------
__global__ void cvt_h(const float4* __restrict__ x, uint2* __restrict__ o, int n4) {
    int i = blockIdx.x * blockDim.x + threadIdx.x;
    if (i >= n4) return;
    float4 v = x[i];
    o[i] = make_uint2(pack2h(v.x, v.y), pack2h(v.z, v.w));
}

// ---------------------------------------------------------------------------
// Plain fp16 GEMM via mma.sync, BK=64 chunks, 3-stage cp.async pipeline.
// 128x128 CTA tile, 8 warps (64x32 warp tile), 2 CTAs/SM.
// MODE 0: fp32 out + bias. MODE 1: QKV -> Q(*scale),K,V fp16 [B,H,T,D].
// ---------------------------------------------------------------------------
#define GSTRIDE 72                       // 64 halfs + 8 pad
#define MAT_BYTES (128 * GSTRIDE * 2)    // 18432 B
#define STAGE_BYTES (2 * MAT_BYTES)      // A, B: 36864 B
#define NSTAGE 3
#define GK_SMEM (NSTAGE * STAGE_BYTES)   // 110592 B -> 2 CTAs/SM (221 KB)

template <int MODE>
__global__ __launch_bounds__(256, 2) void gemm_mma(
    const __half* __restrict__ Af, const __half* __restrict__ Bf,
    const float* __restrict__ bias, float* __restrict__ out,
    int M, int N, int K)
{
    extern __shared__ __align__(128) char dsm[];
    const uint32_t smb = smem_u32(dsm);

    const int tid  = threadIdx.x;
    const int wid  = tid >> 5;
    const int lane = tid & 31;
    const int wm = wid >> 2;
    const int wn = wid & 3;

    const size_t m0 = (size_t)blockIdx.y * 128;
    const size_t n0 = (size_t)blockIdx.x * 128;

    const __half* srcA = Af + m0 * K;
    const __half* srcB = Bf + n0 * K;

    float acc[4][4][4];
#pragma unroll
    for (int i = 0; i < 4; i++)
#pragma unroll
        for (int j = 0; j < 4; j++)
#pragma unroll
            for (int k = 0; k < 4; k++) acc[i][j][k] = 0.f;

    auto load_stage = [&](int kt, int s) {
        const int k0 = kt * 64;
        const uint32_t sb = smb + s * STAGE_BYTES;
#pragma unroll
        for (int i = 0; i < 4; i++) {
            int idx = tid + i * 256;          // 0..1023
            int row = idx >> 3;               // 0..127
            int q   = idx & 7;                // 16B chunk in 128B row
            cp16(sb + (row * GSTRIDE + q * 8) * 2,
                 srcA + (size_t)row * K + k0 + q * 8);
            cp16(sb + MAT_BYTES + (row * GSTRIDE + q * 8) * 2,
                 srcB + (size_t)row * K + k0 + q * 8);
        }
        cp_commit();
    };

    const uint32_t a_row = (uint32_t)(wm * 64 + (lane & 15));
    const uint32_t a_kof = (uint32_t)(((lane >> 4) & 1) * 8);
    const uint32_t b_row = (uint32_t)(wn * 32 + (lane & 7) + ((lane >> 4) & 1) * 8);
    const uint32_t b_kof = (uint32_t)(((lane >> 3) & 1) * 8);

    const int NT = K >> 6;                 // 16 chunks of 64
    load_stage(0, 0);
    load_stage(1, 1);

    for (int kt = 0; kt < NT; kt++) {
        if (kt + 1 < NT) cp_wait1(); else cp_wait0();
        __syncthreads();   // all warps done reading buffer (kt+2)%3 (chunk kt-1)
        if (kt + 2 < NT) load_stage(kt + 2, (kt + 2) % NSTAGE);

        const uint32_t sb = smb + (kt % NSTAGE) * STAGE_BYTES;
        const uint32_t sA = sb;
        const uint32_t sB = sb + MAT_BYTES;

#pragma unroll
        for (int ks = 0; ks < 4; ks++) {
            uint32_t bf[2][4];
#pragma unroll
            for (int nf2 = 0; nf2 < 2; nf2++) {
                uint32_t off = ((b_row + nf2 * 16) * GSTRIDE + ks * 16 + b_kof) * 2;
                ldsm4(bf[nf2], sB + off);
            }
            uint32_t af[2][4];
            {
                uint32_t off0 = (a_row * GSTRIDE + ks * 16 + a_kof) * 2;
                ldsm4(af[0], sA + off0);
            }
#pragma unroll
            for (int mf = 0; mf < 4; mf++) {
                const int cur = mf & 1, nxt = cur ^ 1;
                if (mf < 3) {
                    uint32_t offn = ((a_row + (mf + 1) * 16) * GSTRIDE + ks * 16 + a_kof) * 2;
                    ldsm4(af[nxt], sA + offn);
                }
#pragma unroll
                for (int nf = 0; nf < 4; nf++)
                    mma_f16(acc[mf][nf], af[cur], &bf[nf >> 1][(nf & 1) * 2]);
            }
        }
    }

    const int r_in = lane >> 2;
    const int c_in = (lane & 3) * 2;

    if (MODE == 0) {
#pragma unroll
        for (int mf = 0; mf < 4; mf++) {
#pragma unroll
            for (int nf = 0; nf < 4; nf++) {
                size_t row = m0 + wm * 64 + mf * 16 + r_in;
                size_t col = n0 + wn * 32 + nf * 8 + c_in;
                float bx = bias[col], by = bias[col + 1];
                float2 o0 = make_float2(acc[mf][nf][0] + bx, acc[mf][nf][1] + by);
                float2 o1 = make_float2(acc[mf][nf][2] + bx, acc[mf][nf][3] + by);
                *(float2*)(out + row * N + col) = o0;
                *(float2*)(out + (row + 8) * N + col) = o1;
            }
        }
    } else {
        const float QS = 0.125f * 1.44269504f;   // D^-0.5 * log2(e) folded into Q
        __half* dst[3] = {g_q, g_k, g_v};
#pragma unroll
        for (int mf = 0; mf < 4; mf++) {
#pragma unroll
            for (int nf = 0; nf < 4; nf++) {
                size_t col = n0 + wn * 32 + nf * 8 + c_in;
                int sec = (int)(col >> 10);      // 0=Q, 1=K, 2=V
                int h   = (int)((col >> 6) & 15);
                int d   = (int)(col & 63);
                float bx = bias[col], by = bias[col + 1];
                float sc = (sec == 0) ? QS : 1.f;
                __half* dp = dst[sec];
#pragma unroll
                for (int half = 0; half < 2; half++) {
                    size_t row = m0 + wm * 64 + mf * 16 + r_in + half * 8;
                    int b = (int)(row >> 11);
                    int t = (int)(row & 2047);
                    size_t idx = (((size_t)(b * H_ + h) * T_ + t) * D_ + d);
                    *(uint32_t*)(dp + idx) =
                        pack2h((acc[mf][nf][half * 2 + 0] + bx) * sc,
                               (acc[mf][nf][half * 2 + 1] + by) * sc);
                }
            }
        }
    }
}

// ---------------------------------------------------------------------------
// fp16 causal flash attention, 2 CTAs/SM. Q pre-scaled by D^-0.5*log2e.
// Softmax: fp32 max, then ex2.approx.f16x2 straight into P fragments;
// row-sum accumulated by an extra ones-MMA (RS rescaled by alpha like O).
// ---------------------------------------------------------------------------
#define AST 72
#define QSZ (128 * AST)
#define KVSZ (128 * AST)
#define KVSTAGE (2 * KVSZ)             // K, V
#define A_SMEM ((QSZ + 2 * KVSTAGE) * 2)   // 92160 B -> 2 CTAs/SM

__global__ __launch_bounds__(256, 2) void attn_tc() {
    extern __shared__ __align__(128) __half sm[];
    const uint32_t smb = smem_u32(sm);
    const uint32_t sQ   = smb;
    const uint32_t sKV0 = smb + QSZ * 2;

    const int pair = blockIdx.x;
    const int h  = blockIdx.y;
    const int b  = blockIdx.z;
    const int tid  = threadIdx.x;
    const int wid  = tid >> 5;
    const int lane = tid & 31;
    const int bh = b * H_ + h;

    const __half* gk = g_k + (size_t)bh * T_ * D_;
    const __half* gv = g_v + (size_t)bh * T_ * D_;

    auto load_kv = [&](int kt, int s) {
        const uint32_t sb = sKV0 + s * KVSTAGE * 2;
        const __half* bases[2] = {gk + (size_t)kt * 128 * D_,
                                  gv + (size_t)kt * 128 * D_};
#pragma unroll
        for (int i = 0; i < 8; i++) {
            int idx = tid + i * 256;
            int arr = idx >> 10;
            int rem = idx & 1023;
            int row = rem >> 3;
            int ch  = rem & 7;
            cp16(sb + (arr * KVSZ + row * AST + ch * 8) * 2,
                 bases[arr] + (size_t)row * D_ + ch * 8);
        }
        cp_commit();
    };

    const uint32_t k_row = (uint32_t)((lane & 7) + ((lane >> 4) & 1) * 8);
    const uint32_t k_kof = ((lane >> 3) & 1) * 8;
    const uint32_t v_rof = (uint32_t)(lane & 15);
    const uint32_t v_cof = ((lane >> 4) & 1) * 8;
    const uint32_t ONESB[2] = {0x3C003C00u, 0x3C003C00u};   // half2(1,1)

    auto process_qblock = [&](int qb) {
        const __half* gq = g_q + ((size_t)bh * T_ + qb * 128) * D_;
#pragma unroll
        for (int i = 0; i < 4; i++) {
            int idx = tid + i * 256;
            int row = idx >> 3;
            int ch  = idx & 7;
            cp16(sQ + (row * AST + ch * 8) * 2, gq + (size_t)row * D_ + ch * 8);
        }
        cp_commit();
        load_kv(0, 0);
        cp_wait0();
        __syncthreads();

        uint32_t qF[4][4];
        {
            uint32_t rbase = (uint32_t)(wid * 16 + (lane & 15));
            uint32_t kof = ((lane >> 4) & 1) * 8;
#pragma unroll
            for (int ks = 0; ks < 4; ks++) {
                uint32_t off = (rbase * AST + ks * 16 + kof) * 2;
                ldsm4(qF[ks], sQ + off);
            }
        }

        float O[8][4];
#pragma unroll
        for (int i = 0; i < 8; i++)
#pragma unroll
            for (int j = 0; j < 4; j++) O[i][j] = 0.f;
        float RS[4] = {0.f, 0.f, 0.f, 0.f};   // row-sum accumulator (ones-MMA)
        float mrow[2] = {-1e30f, -1e30f};

        for (int kt = 0; kt <= qb; kt++) {
            const bool more = (kt + 1 <= qb);
            if (more) load_kv(kt + 1, (kt + 1) & 1);
            if (more) cp_wait1(); else cp_wait0();
            __syncthreads();

            const uint32_t sb = sKV0 + (kt & 1) * KVSTAGE * 2;
            const uint32_t sK = sb;
            const uint32_t sV = sb + KVSZ * 2;

            // ---- S = Q K^T (Q pre-scaled) ----------------------------------
            float S[16][4];
#pragma unroll
            for (int i = 0; i < 16; i++)
#pragma unroll
                for (int j = 0; j < 4; j++) S[i][j] = 0.f;

#pragma unroll
            for (int ks = 0; ks < 4; ks++) {
#pragma unroll
                for (int i2 = 0; i2 < 4; i2++) {
                    uint32_t kh4[2][4];
#pragma unroll
                    for (int ii = 0; ii < 2; ii++) {
                        uint32_t off = (((i2 * 2 + ii) * 16 + k_row) * AST
                                        + ks * 16 + k_kof) * 2;
                        ldsm4(kh4[ii], sK + off);
                    }
#pragma unroll
                    for (int ii = 0; ii < 2; ii++)
#pragma unroll
                        for (int half = 0; half < 2; half++)
                            mma_f16(S[(i2 * 2 + ii) * 2 + half], qF[ks],
                                    &kh4[ii][half * 2]);
                }
            }

            // ---- causal mask ------------------------------------------------
            if (kt == qb) {
                const int r0 = wid * 16 + (lane >> 2);
#pragma unroll
                for (int nf = 0; nf < 16; nf++) {
                    int col = nf * 8 + (lane & 3) * 2;
                    if (col > r0)      S[nf][0] = -1e30f;
                    if (col + 1 > r0)  S[nf][1] = -1e30f;
                    if (col > r0 + 8)     S[nf][2] = -1e30f;
                    if (col + 1 > r0 + 8) S[nf][3] = -1e30f;
                }
            }

            // ---- running max + alpha ---------------------------------------
            float rm0 = -1e30f, rm1 = -1e30f;
#pragma unroll
            for (int nf = 0; nf < 16; nf++) {
                rm0 = fmaxf(rm0, fmaxf(S[nf][0], S[nf][1]));
                rm1 = fmaxf(rm1, fmaxf(S[nf][2], S[nf][3]));
            }
            rm0 = fmaxf(rm0, __shfl_xor_sync(0xffffffffu, rm0, 1));
            rm0 = fmaxf(rm0, __shfl_xor_sync(0xffffffffu, rm0, 2));
            rm1 = fmaxf(rm1, __shfl_xor_sync(0xffffffffu, rm1, 1));
            rm1 = fmaxf(rm1, __shfl_xor_sync(0xffffffffu, rm1, 2));

            float mn0 = fmaxf(mrow[0], rm0);
            float mn1 = fmaxf(mrow[1], rm1);
            float a0 = exp2f(mrow[0] - mn0);
            float a1 = exp2f(mrow[1] - mn1);
            mrow[0] = mn0; mrow[1] = mn1;

#pragma unroll
            for (int nf = 0; nf < 8; nf++) {
                O[nf][0] *= a0; O[nf][1] *= a0;
                O[nf][2] *= a1; O[nf][3] *= a1;
            }
            RS[0] *= a0; RS[1] *= a0; RS[2] *= a1; RS[3] *= a1;

            // ---- P = ex2(S - mn) in f16x2; O += P V; RS += P @ ones --------
#pragma unroll
            for (int ks2 = 0; ks2 < 8; ks2++) {
                uint32_t pf[4];
                pf[0] = ex2_h2(pack2h(S[2 * ks2][0] - mn0,     S[2 * ks2][1] - mn0));
                pf[1] = ex2_h2(pack2h(S[2 * ks2][2] - mn1,     S[2 * ks2][3] - mn1));
                pf[2] = ex2_h2(pack2h(S[2 * ks2 + 1][0] - mn0, S[2 * ks2 + 1][1] - mn0));
                pf[3] = ex2_h2(pack2h(S[2 * ks2 + 1][2] - mn1, S[2 * ks2 + 1][3] - mn1));

                mma_f16(RS, pf, ONESB);   // row-sum (every column holds it)

                uint32_t vf[4][4];
#pragma unroll
                for (int i = 0; i < 4; i++) {
                    uint32_t off = ((ks2 * 16 + v_rof) * AST + i * 16 + v_cof) * 2;
                    ldsm4t(vf[i], sV + off);
                }
#pragma unroll
                for (int i = 0; i < 4; i++)
#pragma unroll
                    for (int half = 0; half < 2; half++)
                        mma_f16(O[i * 2 + half], pf, &vf[i][half * 2]);
            }
            __syncthreads();
        }

        const float inv0 = 1.f / RS[0];
        const float inv1 = 1.f / RS[2];
        const size_t row0 = (size_t)b * T_ + qb * 128 + wid * 16 + (lane >> 2);
#pragma unroll
        for (int nf = 0; nf < 8; nf++) {
            int col = h * 64 + nf * 8 + (lane & 3) * 2;
            *(uint32_t*)(g_o + row0 * C_ + col) =
                pack2h(O[nf][0] * inv0, O[nf][1] * inv0);
            *(uint32_t*)(g_o + (row0 + 8) * C_ + col) =
                pack2h(O[nf][2] * inv1, O[nf][3] * inv1);
        }
    };

    process_qblock(pair);
    __syncthreads();
    process_qblock(NQB - 1 - pair);
}

// ---------------------------------------------------------------------------
extern "C" void kernel_launch(void* const* d_in, const int* in_sizes, int n_in,
                              void* d_out, int out_size) {
    const float* hidden = (const float*)d_in[0];
    const float* W_qkv  = (const float*)d_in[2];
    const float* b_qkv  = (const float*)d_in[3];
    const float* W_o    = (const float*)d_in[4];
    const float* b_o    = (const float*)d_in[5];
    float* out = (float*)d_out;

    __half *x, *wq, *wo, *o;
    cudaGetSymbolAddress((void**)&x, g_x);
    cudaGetSymbolAddress((void**)&wq, g_wq);
    cudaGetSymbolAddress((void**)&wo, g_wo);
    cudaGetSymbolAddress((void**)&o, g_o);

    cudaFuncSetAttribute(gemm_mma<0>, cudaFuncAttributeMaxDynamicSharedMemorySize, GK_SMEM);
    cudaFuncSetAttribute(gemm_mma<1>, cudaFuncAttributeMaxDynamicSharedMemorySize, GK_SMEM);
    cudaFuncSetAttribute(attn_tc, cudaFuncAttributeMaxDynamicSharedMemorySize, A_SMEM);

    {
        int n4 = (M_ * C_) / 4;
        cvt_h<<<(n4 + 255) / 256, 256>>>((const float4*)hidden, (uint2*)x, n4);
        n4 = (C3_ * C_) / 4;
        cvt_h<<<(n4 + 255) / 256, 256>>>((const float4*)W_qkv, (uint2*)wq, n4);
        n4 = (C_ * C_) / 4;
        cvt_h<<<(n4 + 255) / 256, 256>>>((const float4*)W_o, (uint2*)wo, n4);
    }

    // 1) QKV projection -> Q(*scale),K,V fp16 [B,H,T,D]
    {
        dim3 grid(C3_ / 128, M_ / 128);
        gemm_mma<1><<<grid, 256, GK_SMEM>>>(x, wq, b_qkv, nullptr, M_, C3_, C_);
    }
    // 2) flash attention -> g_o
    {
        dim3 grid(NQB / 2, H_, B_);
        attn_tc<<<grid, 256, A_SMEM>>>();
    }
    // 3) out = O @ W_o^T + b_o
    {
        dim3 grid(C_ / 128, M_ / 128);
        gemm_mma<0><<<grid, 256, GK_SMEM>>>(o, wo, b_o, out, M_, C_, C_);
    }
}

// round 17
// speedup vs baseline: 2.6546x; 1.0396x over previous
#include <cuda_runtime.h>
#include <cuda_fp16.h>
#include <cstdint>

#define B_ 4
#define T_ 2048
#define C_ 1024
#define H_ 16
#define D_ 64
#define C3_ (3 * C_)
#define M_ (B_ * T_)   // 8192
#define NQB (T_ / 128) // 16 q-blocks per (b,h)
#define PGRID 304      // persistent grid (~2 CTAs/SM)

// ---------------- scratch (device globals; no runtime alloc) ----------------
__device__ __half g_x[(size_t)M_ * C_];
__device__ __half g_wq[(size_t)C3_ * C_];
__device__ __half g_wo[(size_t)C_ * C_];
__device__ __half g_q[(size_t)M_ * C_];              // Q*scale fp16 [B,H,T,D]
__device__ __half g_k[(size_t)M_ * C_];
__device__ __half g_v[(size_t)M_ * C_];
__device__ __half g_o[(size_t)M_ * C_];
__device__ unsigned g_ctr[4];                        // work counters

// ---------------------------- helpers ---------------------------------------
__device__ __forceinline__ uint32_t smem_u32(const void* p) {
    uint32_t a;
    asm("{ .reg .u64 t; cvta.to.shared.u64 t, %1; cvt.u32.u64 %0, t; }"
        : "=r"(a) : "l"(p));
    return a;
}
__device__ __forceinline__ void cp16(uint32_t dst, const void* src) {
    asm volatile("cp.async.cg.shared.global [%0], [%1], 16;" :: "r"(dst), "l"(src));
}
__device__ __forceinline__ void cp_commit() {
    asm volatile("cp.async.commit_group;" ::: "memory");
}
__device__ __forceinline__ void cp_wait0() {
    asm volatile("cp.async.wait_group 0;" ::: "memory");
}
__device__ __forceinline__ void cp_wait1() {
    asm volatile("cp.async.wait_group 1;" ::: "memory");
}
__device__ __forceinline__ void ldsm4(uint32_t* r, uint32_t addr) {
    asm volatile("ldmatrix.sync.aligned.m8n8.x4.shared.b16 {%0,%1,%2,%3}, [%4];"
                 : "=r"(r[0]), "=r"(r[1]), "=r"(r[2]), "=r"(r[3]) : "r"(addr));
}
__device__ __forceinline__ void ldsm4t(uint32_t* r, uint32_t addr) {
    asm volatile("ldmatrix.sync.aligned.m8n8.x4.trans.shared.b16 {%0,%1,%2,%3}, [%4];"
                 : "=r"(r[0]), "=r"(r[1]), "=r"(r[2]), "=r"(r[3]) : "r"(addr));
}
__device__ __forceinline__ void mma_f16(float* c, const uint32_t* a, const uint32_t* b) {
    asm volatile(
        "mma.sync.aligned.m16n8k16.row.col.f32.f16.f16.f32 "
        "{%0,%1,%2,%3}, {%4,%5,%6,%7}, {%8,%9}, {%0,%1,%2,%3};"
        : "+f"(c[0]), "+f"(c[1]), "+f"(c[2]), "+f"(c[3])
        : "r"(a[0]), "r"(a[1]), "r"(a[2]), "r"(a[3]), "r"(b[0]), "r"(b[1]));
}
__device__ __forceinline__ uint32_t pack2h(float a, float b) {
    __half2 h = __floats2half2_rn(a, b);
    return *reinterpret_cast<uint32_t*>(&h);
}
__device__ __forceinline__ uint32_t ex2_h2(uint32_t x) {
    uint32_t r;
    asm("ex2.approx.f16x2 %0, %1;" : "=r"(r) : "r"(x));
    return r;
}

// ---------------------------------------------------------------------------
__global__ void reset_ctr() {
    if (threadIdx.x < 4) g_ctr[threadIdx.x] = 0u;
}
__global__ void cvt_h(const float4* __restrict__ x, uint2* __restrict__ o, int n4) {
    int i = blockIdx.x * blockDim.x + threadIdx.x;
    if (i >= n4) return;
    float4 v = x[i];
    o[i] = make_uint2(pack2h(v.x, v.y), pack2h(v.z, v.w));
}

// ---------------------------------------------------------------------------
// Persistent fp16 GEMM via mma.sync, BK=64, 2-stage cp.async pipeline.
// Tiles dispensed by atomic counter (kills wave quantization).
// MODE 0: fp32 out + bias (counter 1). MODE 1: QKV -> Q*scale,K,V (counter 0).
// ---------------------------------------------------------------------------
#define GSTRIDE 72
#define MAT_BYTES (128 * GSTRIDE * 2)    // 18432 B
#define STAGE_BYTES (2 * MAT_BYTES)      // 36864 B
#define GK_SMEM (2 * STAGE_BYTES)        // 73728 B -> 2 CTAs/SM

template <int MODE>
__global__ __launch_bounds__(256, 2) void gemm_mma(
    const __half* __restrict__ Af, const __half* __restrict__ Bf,
    const float* __restrict__ bias, float* __restrict__ out,
    int M, int N, int K)
{
    extern __shared__ __align__(128) char dsm[];
    __shared__ unsigned s_tile;
    const uint32_t smb = smem_u32(dsm);

    const int tid  = threadIdx.x;
    const int wid  = tid >> 5;
    const int lane = tid & 31;
    const int wm = wid >> 2;
    const int wn = wid & 3;

    const int nbx = N >> 7;
    const unsigned ntiles = (unsigned)((M >> 7) * nbx);

    const uint32_t a_row = (uint32_t)(wm * 64 + (lane & 15));
    const uint32_t a_kof = (uint32_t)(((lane >> 4) & 1) * 8);
    const uint32_t b_row = (uint32_t)(wn * 32 + (lane & 7) + ((lane >> 4) & 1) * 8);
    const uint32_t b_kof = (uint32_t)(((lane >> 3) & 1) * 8);
    const int r_in = lane >> 2;
    const int c_in = (lane & 3) * 2;
    const int NT = K >> 6;

    for (;;) {
        if (tid == 0) s_tile = atomicAdd(&g_ctr[MODE == 1 ? 0 : 1], 1u);
        __syncthreads();
        const unsigned t = s_tile;
        if (t >= ntiles) break;

        const size_t m0 = (size_t)(t / nbx) * 128;
        const size_t n0 = (size_t)(t % nbx) * 128;
        const __half* srcA = Af + m0 * K;
        const __half* srcB = Bf + n0 * K;

        float acc[4][4][4];
#pragma unroll
        for (int i = 0; i < 4; i++)
#pragma unroll
            for (int j = 0; j < 4; j++)
#pragma unroll
                for (int k = 0; k < 4; k++) acc[i][j][k] = 0.f;

        auto load_stage = [&](int kt, int s) {
            const int k0 = kt * 64;
            const uint32_t sb = smb + s * STAGE_BYTES;
#pragma unroll
            for (int i = 0; i < 4; i++) {
                int idx = tid + i * 256;
                int row = idx >> 3;
                int q   = idx & 7;
                cp16(sb + (row * GSTRIDE + q * 8) * 2,
                     srcA + (size_t)row * K + k0 + q * 8);
                cp16(sb + MAT_BYTES + (row * GSTRIDE + q * 8) * 2,
                     srcB + (size_t)row * K + k0 + q * 8);
            }
            cp_commit();
        };

        load_stage(0, 0);

        for (int kt = 0; kt < NT; kt++) {
            cp_wait0();
            __syncthreads();
            if (kt + 1 < NT) load_stage(kt + 1, (kt + 1) & 1);

            const uint32_t sb = smb + (kt & 1) * STAGE_BYTES;
            const uint32_t sA = sb;
            const uint32_t sB = sb + MAT_BYTES;

#pragma unroll
            for (int ks = 0; ks < 4; ks++) {
                uint32_t bf[2][4];
#pragma unroll
                for (int nf2 = 0; nf2 < 2; nf2++) {
                    uint32_t off = ((b_row + nf2 * 16) * GSTRIDE + ks * 16 + b_kof) * 2;
                    ldsm4(bf[nf2], sB + off);
                }
                uint32_t af[2][4];
                {
                    uint32_t off0 = (a_row * GSTRIDE + ks * 16 + a_kof) * 2;
                    ldsm4(af[0], sA + off0);
                }
#pragma unroll
                for (int mf = 0; mf < 4; mf++) {
                    const int cur = mf & 1, nxt = cur ^ 1;
                    if (mf < 3) {
                        uint32_t offn = ((a_row + (mf + 1) * 16) * GSTRIDE + ks * 16 + a_kof) * 2;
                        ldsm4(af[nxt], sA + offn);
                    }
#pragma unroll
                    for (int nf = 0; nf < 4; nf++)
                        mma_f16(acc[mf][nf], af[cur], &bf[nf >> 1][(nf & 1) * 2]);
                }
            }
        }

        if (MODE == 0) {
#pragma unroll
            for (int mf = 0; mf < 4; mf++) {
#pragma unroll
                for (int nf = 0; nf < 4; nf++) {
                    size_t row = m0 + wm * 64 + mf * 16 + r_in;
                    size_t col = n0 + wn * 32 + nf * 8 + c_in;
                    float bx = bias[col], by = bias[col + 1];
                    float2 o0 = make_float2(acc[mf][nf][0] + bx, acc[mf][nf][1] + by);
                    float2 o1 = make_float2(acc[mf][nf][2] + bx, acc[mf][nf][3] + by);
                    *(float2*)(out + row * N + col) = o0;
                    *(float2*)(out + (row + 8) * N + col) = o1;
                }
            }
        } else {
            const float QS = 0.125f * 1.44269504f;
            __half* dst[3] = {g_q, g_k, g_v};
#pragma unroll
            for (int mf = 0; mf < 4; mf++) {
#pragma unroll
                for (int nf = 0; nf < 4; nf++) {
                    size_t col = n0 + wn * 32 + nf * 8 + c_in;
                    int sec = (int)(col >> 10);
                    int h   = (int)((col >> 6) & 15);
                    int d   = (int)(col & 63);
                    float bx = bias[col], by = bias[col + 1];
                    float sc = (sec == 0) ? QS : 1.f;
                    __half* dp = dst[sec];
#pragma unroll
                    for (int half = 0; half < 2; half++) {
                        size_t row = m0 + wm * 64 + mf * 16 + r_in + half * 8;
                        int b = (int)(row >> 11);
                        int tt = (int)(row & 2047);
                        size_t idx = (((size_t)(b * H_ + h) * T_ + tt) * D_ + d);
                        *(uint32_t*)(dp + idx) =
                            pack2h((acc[mf][nf][half * 2 + 0] + bx) * sc,
                                   (acc[mf][nf][half * 2 + 1] + by) * sc);
                    }
                }
            }
        }
    }
}

// ---------------------------------------------------------------------------
// Persistent fp16 causal flash attention, 2 CTAs/SM. Work items dispensed
// largest-qb-first (LPT) by atomic counter. Q pre-scaled; ex2.f16x2 softmax;
// row-sum via ones-MMA.
// ---------------------------------------------------------------------------
#define AST 72
#define QSZ (128 * AST)
#define KVSZ (128 * AST)
#define KVSTAGE (2 * KVSZ)
#define A_SMEM ((QSZ + 2 * KVSTAGE) * 2)   // 92160 B -> 2 CTAs/SM

__global__ __launch_bounds__(256, 2) void attn_tc() {
    extern __shared__ __align__(128) __half sm[];
    __shared__ unsigned s_item;
    const uint32_t smb = smem_u32(sm);
    const uint32_t sQ   = smb;
    const uint32_t sKV0 = smb + QSZ * 2;

    const int tid  = threadIdx.x;
    const int wid  = tid >> 5;
    const int lane = tid & 31;

    const uint32_t k_row = (uint32_t)((lane & 7) + ((lane >> 4) & 1) * 8);
    const uint32_t k_kof = ((lane >> 3) & 1) * 8;
    const uint32_t v_rof = (uint32_t)(lane & 15);
    const uint32_t v_cof = ((lane >> 4) & 1) * 8;
    const uint32_t ONESB[2] = {0x3C003C00u, 0x3C003C00u};

    const unsigned NITEMS = NQB * H_ * B_;   // 1024

    for (;;) {
        if (tid == 0) s_item = atomicAdd(&g_ctr[2], 1u);
        __syncthreads();
        const unsigned t = s_item;
        if (t >= NITEMS) break;

        // largest-first: qb descends as t grows
        const int qb  = NQB - 1 - (int)(t >> 6);
        const int rem = (int)(t & 63);
        const int h = rem & 15;
        const int b = rem >> 4;
        const int bh = b * H_ + h;

        const __half* gk = g_k + (size_t)bh * T_ * D_;
        const __half* gv = g_v + (size_t)bh * T_ * D_;
        const __half* gq = g_q + ((size_t)bh * T_ + qb * 128) * D_;

        auto load_kv = [&](int kt, int s) {
            const uint32_t sb = sKV0 + s * KVSTAGE * 2;
            const __half* bases[2] = {gk + (size_t)kt * 128 * D_,
                                      gv + (size_t)kt * 128 * D_};
#pragma unroll
            for (int i = 0; i < 8; i++) {
                int idx = tid + i * 256;
                int arr = idx >> 10;
                int r2  = idx & 1023;
                int row = r2 >> 3;
                int ch  = r2 & 7;
                cp16(sb + (arr * KVSZ + row * AST + ch * 8) * 2,
                     bases[arr] + (size_t)row * D_ + ch * 8);
            }
            cp_commit();
        };

#pragma unroll
        for (int i = 0; i < 4; i++) {
            int idx = tid + i * 256;
            int row = idx >> 3;
            int ch  = idx & 7;
            cp16(sQ + (row * AST + ch * 8) * 2, gq + (size_t)row * D_ + ch * 8);
        }
        cp_commit();
        load_kv(0, 0);
        cp_wait0();
        __syncthreads();

        uint32_t qF[4][4];
        {
            uint32_t rbase = (uint32_t)(wid * 16 + (lane & 15));
            uint32_t kof = ((lane >> 4) & 1) * 8;
#pragma unroll
            for (int ks = 0; ks < 4; ks++) {
                uint32_t off = (rbase * AST + ks * 16 + kof) * 2;
                ldsm4(qF[ks], sQ + off);
            }
        }

        float O[8][4];
#pragma unroll
        for (int i = 0; i < 8; i++)
#pragma unroll
            for (int j = 0; j < 4; j++) O[i][j] = 0.f;
        float RS[4] = {0.f, 0.f, 0.f, 0.f};
        float mrow[2] = {-1e30f, -1e30f};

        for (int kt = 0; kt <= qb; kt++) {
            const bool more = (kt + 1 <= qb);
            if (more) load_kv(kt + 1, (kt + 1) & 1);
            if (more) cp_wait1(); else cp_wait0();
            __syncthreads();

            const uint32_t sb = sKV0 + (kt & 1) * KVSTAGE * 2;
            const uint32_t sK = sb;
            const uint32_t sV = sb + KVSZ * 2;

            float S[16][4];
#pragma unroll
            for (int i = 0; i < 16; i++)
#pragma unroll
                for (int j = 0; j < 4; j++) S[i][j] = 0.f;

#pragma unroll
            for (int ks = 0; ks < 4; ks++) {
#pragma unroll
                for (int i2 = 0; i2 < 4; i2++) {
                    uint32_t kh4[2][4];
#pragma unroll
                    for (int ii = 0; ii < 2; ii++) {
                        uint32_t off = (((i2 * 2 + ii) * 16 + k_row) * AST
                                        + ks * 16 + k_kof) * 2;
                        ldsm4(kh4[ii], sK + off);
                    }
#pragma unroll
                    for (int ii = 0; ii < 2; ii++)
#pragma unroll
                        for (int half = 0; half < 2; half++)
                            mma_f16(S[(i2 * 2 + ii) * 2 + half], qF[ks],
                                    &kh4[ii][half * 2]);
                }
            }

            if (kt == qb) {
                const int r0 = wid * 16 + (lane >> 2);
#pragma unroll
                for (int nf = 0; nf < 16; nf++) {
                    int col = nf * 8 + (lane & 3) * 2;
                    if (col > r0)      S[nf][0] = -1e30f;
                    if (col + 1 > r0)  S[nf][1] = -1e30f;
                    if (col > r0 + 8)     S[nf][2] = -1e30f;
                    if (col + 1 > r0 + 8) S[nf][3] = -1e30f;
                }
            }

            float rm0 = -1e30f, rm1 = -1e30f;
#pragma unroll
            for (int nf = 0; nf < 16; nf++) {
                rm0 = fmaxf(rm0, fmaxf(S[nf][0], S[nf][1]));
                rm1 = fmaxf(rm1, fmaxf(S[nf][2], S[nf][3]));
            }
            rm0 = fmaxf(rm0, __shfl_xor_sync(0xffffffffu, rm0, 1));
            rm0 = fmaxf(rm0, __shfl_xor_sync(0xffffffffu, rm0, 2));
            rm1 = fmaxf(rm1, __shfl_xor_sync(0xffffffffu, rm1, 1));
            rm1 = fmaxf(rm1, __shfl_xor_sync(0xffffffffu, rm1, 2));

            float mn0 = fmaxf(mrow[0], rm0);
            float mn1 = fmaxf(mrow[1], rm1);
            float a0 = exp2f(mrow[0] - mn0);
            float a1 = exp2f(mrow[1] - mn1);
            mrow[0] = mn0; mrow[1] = mn1;

#pragma unroll
            for (int nf = 0; nf < 8; nf++) {
                O[nf][0] *= a0; O[nf][1] *= a0;
                O[nf][2] *= a1; O[nf][3] *= a1;
            }
            RS[0] *= a0; RS[1] *= a0; RS[2] *= a1; RS[3] *= a1;

#pragma unroll
            for (int ks2 = 0; ks2 < 8; ks2++) {
                uint32_t pf[4];
                pf[0] = ex2_h2(pack2h(S[2 * ks2][0] - mn0,     S[2 * ks2][1] - mn0));
                pf[1] = ex2_h2(pack2h(S[2 * ks2][2] - mn1,     S[2 * ks2][3] - mn1));
                pf[2] = ex2_h2(pack2h(S[2 * ks2 + 1][0] - mn0, S[2 * ks2 + 1][1] - mn0));
                pf[3] = ex2_h2(pack2h(S[2 * ks2 + 1][2] - mn1, S[2 * ks2 + 1][3] - mn1));

                mma_f16(RS, pf, ONESB);

                uint32_t vf[4][4];
#pragma unroll
                for (int i = 0; i < 4; i++) {
                    uint32_t off = ((ks2 * 16 + v_rof) * AST + i * 16 + v_cof) * 2;
                    ldsm4t(vf[i], sV + off);
                }
#pragma unroll
                for (int i = 0; i < 4; i++)
#pragma unroll
                    for (int half = 0; half < 2; half++)
                        mma_f16(O[i * 2 + half], pf, &vf[i][half * 2]);
            }
            __syncthreads();
        }

        const float inv0 = 1.f / RS[0];
        const float inv1 = 1.f / RS[2];
        const size_t row0 = (size_t)b * T_ + qb * 128 + wid * 16 + (lane >> 2);
#pragma unroll
        for (int nf = 0; nf < 8; nf++) {
            int col = h * 64 + nf * 8 + (lane & 3) * 2;
            *(uint32_t*)(g_o + row0 * C_ + col) =
                pack2h(O[nf][0] * inv0, O[nf][1] * inv0);
            *(uint32_t*)(g_o + (row0 + 8) * C_ + col) =
                pack2h(O[nf][2] * inv1, O[nf][3] * inv1);
        }
    }
}

// ---------------------------------------------------------------------------
extern "C" void kernel_launch(void* const* d_in, const int* in_sizes, int n_in,
                              void* d_out, int out_size) {
    const float* hidden = (const float*)d_in[0];
    const float* W_qkv  = (const float*)d_in[2];
    const float* b_qkv  = (const float*)d_in[3];
    const float* W_o    = (const float*)d_in[4];
    const float* b_o    = (const float*)d_in[5];
    float* out = (float*)d_out;

    __half *x, *wq, *wo, *o;
    cudaGetSymbolAddress((void**)&x, g_x);
    cudaGetSymbolAddress((void**)&wq, g_wq);
    cudaGetSymbolAddress((void**)&wo, g_wo);
    cudaGetSymbolAddress((void**)&o, g_o);

    cudaFuncSetAttribute(gemm_mma<0>, cudaFuncAttributeMaxDynamicSharedMemorySize, GK_SMEM);
    cudaFuncSetAttribute(gemm_mma<1>, cudaFuncAttributeMaxDynamicSharedMemorySize, GK_SMEM);
    cudaFuncSetAttribute(attn_tc, cudaFuncAttributeMaxDynamicSharedMemorySize, A_SMEM);

    reset_ctr<<<1, 32>>>();
    {
        int n4 = (M_ * C_) / 4;
        cvt_h<<<(n4 + 255) / 256, 256>>>((const float4*)hidden, (uint2*)x, n4);
        n4 = (C3_ * C_) / 4;
        cvt_h<<<(n4 + 255) / 256, 256>>>((const float4*)W_qkv, (uint2*)wq, n4);
        n4 = (C_ * C_) / 4;
        cvt_h<<<(n4 + 255) / 256, 256>>>((const float4*)W_o, (uint2*)wo, n4);
    }

    // 1) QKV projection -> Q*scale, K, V fp16 [B,H,T,D]   (persistent)
    gemm_mma<1><<<PGRID, 256, GK_SMEM>>>(x, wq, b_qkv, nullptr, M_, C3_, C_);
    // 2) flash attention -> g_o   (persistent, LPT order)
    attn_tc<<<PGRID, 256, A_SMEM>>>();
    // 3) out = O @ W_o^T + b_o   (persistent)
    gemm_mma<0><<<PGRID, 256, GK_SMEM>>>(o, wo, b_o, out, M_, C_, C_);
}